// round 10
// baseline (speedup 1.0000x reference)
#include <cuda_runtime.h>
#include <cuda_bf16.h>
#include <cstdint>

#define Nn 50000
#define Ee 800000
#define ET (Ee + Nn)
#define INC 256
#define HC 256
#define NH 4
#define OC 40
#define NB ((Nn + 255) / 256)

#define MT 128
#define MTILES ((Nn + MT - 1) / MT)
#define PADN (MTILES * MT)
#define HBLK 391

// ---------------- scratch ----------------------------------------------------
__device__ __align__(16) __nv_bfloat16 g_h1b[(size_t)Nn * HC];   // bf16 messages
__device__ float g_als1[Nn * NH];
__device__ float g_ald1[Nn * NH];
__device__ float g_h2[Nn * OC];
__device__ float g_als2[Nn];
__device__ float g_ald2[Nn];
__device__ int g_counts[Nn];
__device__ int g_fill[Nn];
__device__ int g_rowptr[Nn + 1];
__device__ int g_srcl[ET];
__device__ int g_bsum[NB];
__device__ __align__(16) __nv_bfloat16 g_w1h[INC * HC];
__device__ __align__(16) __nv_bfloat16 g_w1l[INC * HC];
__device__ __align__(16) __nv_bfloat16 g_w2h[64 * INC];
__device__ __align__(16) __nv_bfloat16 g_w2l[64 * INC];
__device__ __align__(16) __nv_bfloat16 g_a1h[(size_t)PADN * HC];
__device__ __align__(16) __nv_bfloat16 g_a1l[(size_t)PADN * HC];

// ---------------- helpers ----------------------------------------------------
__device__ __forceinline__ float lrelu(float v) { return (v > 0.f) ? v : 0.2f * v; }
__device__ __forceinline__ uint32_t pack2(__nv_bfloat16 a, __nv_bfloat16 b) {
    __nv_bfloat162 t; t.x = a; t.y = b;
    return *reinterpret_cast<uint32_t*>(&t);
}
__device__ __forceinline__ void split4(float4 v, uint2& hh, uint2& ll) {
    __nv_bfloat16 h0 = __float2bfloat16(v.x), h1 = __float2bfloat16(v.y);
    __nv_bfloat16 h2 = __float2bfloat16(v.z), h3 = __float2bfloat16(v.w);
    __nv_bfloat16 l0 = __float2bfloat16(v.x - __bfloat162float(h0));
    __nv_bfloat16 l1 = __float2bfloat16(v.y - __bfloat162float(h1));
    __nv_bfloat16 l2 = __float2bfloat16(v.z - __bfloat162float(h2));
    __nv_bfloat16 l3 = __float2bfloat16(v.w - __bfloat162float(h3));
    hh.x = pack2(h0, h1); hh.y = pack2(h2, h3);
    ll.x = pack2(l0, l1); ll.y = pack2(l2, l3);
}
__device__ __forceinline__ uint32_t smem_u32(const void* p) {
    uint32_t a;
    asm("{ .reg .u64 t; cvta.to.shared.u64 t, %1; cvt.u32.u64 %0, t; }" : "=r"(a) : "l"(p));
    return a;
}
__device__ __forceinline__ void cp16(uint32_t dst, const void* src) {
    asm volatile("cp.async.ca.shared.global [%0], [%1], 16;" :: "r"(dst), "l"(src));
}
#define CP_COMMIT() asm volatile("cp.async.commit_group;" ::: "memory")
#define CP_WAIT0()  asm volatile("cp.async.wait_group 0;" ::: "memory")

// ---------------- convert_w + init (fused) -------------------------------------
__global__ void convert_w(const float* __restrict__ W1, const float* __restrict__ W2) {
    int t = blockIdx.x * blockDim.x + threadIdx.x;
    if (t < INC * HC) {
        int k = t >> 8, n = t & 255;
        float v = W1[t];
        __nv_bfloat16 h = __float2bfloat16(v);
        g_w1h[n * INC + k] = h;
        g_w1l[n * INC + k] = __float2bfloat16(v - __bfloat162float(h));
    } else if (t < INC * HC + 64 * INC) {
        int u = t - INC * HC;
        int n = u >> 8, k = u & 255;
        float v = (n < OC) ? W2[k * OC + n] : 0.f;
        __nv_bfloat16 h = __float2bfloat16(v);
        g_w2h[n * INC + k] = h;
        g_w2l[n * INC + k] = __float2bfloat16(v - __bfloat162float(h));
    }
    if (t < Nn) { g_counts[t] = 1; g_fill[t] = 0; }
}

// ---------------- scan (2 kernels) ---------------------------------------------
__device__ __forceinline__ int block_incl_scan(int v, int* ws) {
    int lane = threadIdx.x & 31, warp = threadIdx.x >> 5;
    #pragma unroll
    for (int o = 1; o < 32; o <<= 1) {
        int u = __shfl_up_sync(0xffffffffu, v, o);
        if (lane >= o) v += u;
    }
    if (lane == 31) ws[warp] = v;
    __syncthreads();
    if (warp == 0 && lane < 8) {
        int w = ws[lane];
        #pragma unroll
        for (int o = 1; o < 8; o <<= 1) {
            int u = __shfl_up_sync(0xffu, w, o);
            if (lane >= o) w += u;
        }
        ws[lane] = w;
    }
    __syncthreads();
    if (warp > 0) v += ws[warp - 1];
    return v;
}
__global__ void scan_part() {
    __shared__ int ws[8];
    int idx = blockIdx.x * 256 + threadIdx.x;
    int v = (idx < Nn) ? g_counts[idx] : 0;
    int incl = block_incl_scan(v, ws);
    if (idx < Nn) g_rowptr[idx + 1] = incl;
    if (threadIdx.x == 255) g_bsum[blockIdx.x] = incl;
}
__global__ void scan_add2() {
    __shared__ int ws[8];
    int j = blockIdx.x;
    int tid = threadIdx.x;
    int lane = tid & 31, warp = tid >> 5;
    int v = (tid < j) ? g_bsum[tid] : 0;
    #pragma unroll
    for (int o = 16; o; o >>= 1) v += __shfl_down_sync(0xffffffffu, v, o);
    if (lane == 0) ws[warp] = v;
    __syncthreads();
    if (warp == 0) {
        int w = (lane < 8) ? ws[lane] : 0;
        #pragma unroll
        for (int o = 4; o; o >>= 1) w += __shfl_down_sync(0xffffffffu, w, o);
        if (lane == 0) ws[0] = w;
    }
    __syncthreads();
    int offset = ws[0];
    int idx = j * 256 + tid;
    if (idx < Nn) g_rowptr[idx + 1] += offset;
    if (j == 0 && tid == 0) g_rowptr[0] = 0;
}
__global__ void fill_kernel(const int* __restrict__ ei) {
    const int Q = Ee / 4;
    int i = blockIdx.x * blockDim.x + threadIdx.x;
    if (i < Q) {
        int4 s = ((const int4*)ei)[i];
        int4 d = ((const int4*)(ei + Ee))[i];
        int p;
        p = g_rowptr[d.x] + atomicAdd(&g_fill[d.x], 1); g_srcl[p] = s.x;
        p = g_rowptr[d.y] + atomicAdd(&g_fill[d.y], 1); g_srcl[p] = s.y;
        p = g_rowptr[d.z] + atomicAdd(&g_fill[d.z], 1); g_srcl[p] = s.z;
        p = g_rowptr[d.w] + atomicAdd(&g_fill[d.w], 1); g_srcl[p] = s.w;
    } else {
        int n = i - Q;
        if (n < Nn) {
            int p = g_rowptr[n] + atomicAdd(&g_fill[n], 1);
            g_srcl[p] = n;
        }
    }
}

// ---------------- GEMM common ---------------------------------------------------
#define LDW 36
#define LDB 144
#define ATILE (128 * LDB)

__device__ __forceinline__ void mma_bf16(float* c, const uint32_t* a, const uint32_t* b) {
    asm volatile(
        "mma.sync.aligned.m16n8k16.row.col.f32.bf16.bf16.f32 "
        "{%0,%1,%2,%3}, {%4,%5,%6,%7}, {%8,%9}, {%0,%1,%2,%3};"
        : "+f"(c[0]), "+f"(c[1]), "+f"(c[2]), "+f"(c[3])
        : "r"(a[0]), "r"(a[1]), "r"(a[2]), "r"(a[3]), "r"(b[0]), "r"(b[1]));
}

// ---------------- GEMM1 (+ hist blocks): h1b = bf16(x @ W1), fused attn coef ---
#define G1_BUF (4 * ATILE)
#define G1_SMEM (2 * G1_BUF)

__global__ void __launch_bounds__(512, 1)
gemm1_mma(const float* __restrict__ X, const int* __restrict__ ei,
          const float* __restrict__ a_src, const float* __restrict__ a_dst) {
    if (blockIdx.x >= MTILES * 2) {
        int i = (blockIdx.x - MTILES * 2) * 512 + threadIdx.x;
        if (i < Ee / 4) {
            int4 d = ((const int4*)(ei + Ee))[i];
            atomicAdd(&g_counts[d.x], 1);
            atomicAdd(&g_counts[d.y], 1);
            atomicAdd(&g_counts[d.z], 1);
            atomicAdd(&g_counts[d.w], 1);
        }
        return;
    }

    extern __shared__ char smem[];
    __shared__ float sAs[128], sAd[128];
    __shared__ float red[4][2][2][32];

    const int tid = threadIdx.x;
    const int wid = tid >> 5;
    const int lane = tid & 31;
    const int wm = wid >> 2;
    const int wn = wid & 3;
    const int g = lane >> 2;
    const int t = lane & 3;
    const int hl = wn >> 1;

    const int bm = (blockIdx.x >> 1) * MT;
    const int bn = (blockIdx.x & 1) * 128;

    const uint32_t sb = smem_u32(smem);

    if (tid < 128) { sAs[tid] = a_src[bn + tid]; sAd[tid] = a_dst[bn + tid]; }
    ((float*)red)[tid] = 0.f;

    float acc[2][4][4] = {};
    float4 aregs[4];

    auto loadA = [&](int c) {
        #pragma unroll
        for (int i = 0; i < 4; i++) {
            int idx = i * 512 + tid;
            int row = idx >> 4;
            int col4 = (idx & 15) * 4;
            int grow = bm + row;
            aregs[i] = (grow < Nn)
                ? *(const float4*)(X + (size_t)grow * INC + c * 64 + col4)
                : make_float4(0.f, 0.f, 0.f, 0.f);
        }
    };
    auto storeA = [&](int buf) {
        char* sAh = smem + buf * G1_BUF;
        char* sAl = sAh + ATILE;
        #pragma unroll
        for (int i = 0; i < 4; i++) {
            int idx = i * 512 + tid;
            int row = idx >> 4;
            int col4 = (idx & 15) * 4;
            uint2 hh, ll;
            split4(aregs[i], hh, ll);
            int so = row * LDB + col4 * 2;
            *(uint2*)(sAh + so) = hh;
            *(uint2*)(sAl + so) = ll;
        }
    };
    auto cpB = [&](int c, int buf) {
        uint32_t dBh = sb + buf * G1_BUF + 2 * ATILE;
        uint32_t dBl = dBh + ATILE;
        #pragma unroll
        for (int i = 0; i < 2; i++) {
            int idx = i * 512 + tid;
            int row = idx >> 3;
            int col8 = (idx & 7) * 8;
            size_t gb = (size_t)(bn + row) * INC + c * 64 + col8;
            uint32_t so = row * LDB + col8 * 2;
            cp16(dBh + so, g_w1h + gb);
            cp16(dBl + so, g_w1l + gb);
        }
    };
    auto compute = [&](int buf) {
        const uint32_t* Ahw = (const uint32_t*)(smem + buf * G1_BUF);
        const uint32_t* Alw = (const uint32_t*)(smem + buf * G1_BUF + ATILE);
        const uint32_t* Bhw = (const uint32_t*)(smem + buf * G1_BUF + 2 * ATILE);
        const uint32_t* Blw = (const uint32_t*)(smem + buf * G1_BUF + 3 * ATILE);
        #pragma unroll
        for (int kk = 0; kk < 4; kk++) {
            const int kw = kk * 8;
            uint32_t bh[4][2], bl[4][2];
            #pragma unroll
            for (int nt = 0; nt < 4; nt++) {
                int w0 = (wn * 32 + nt * 8 + g) * LDW + kw + t;
                bh[nt][0] = Bhw[w0]; bh[nt][1] = Bhw[w0 + 4];
                bl[nt][0] = Blw[w0]; bl[nt][1] = Blw[w0 + 4];
            }
            #pragma unroll
            for (int mt = 0; mt < 2; mt++) {
                int w0 = (wm * 32 + mt * 16 + g) * LDW + kw + t;
                uint32_t ah[4], al[4];
                ah[0] = Ahw[w0]; ah[1] = Ahw[w0 + 8 * LDW];
                ah[2] = Ahw[w0 + 4]; ah[3] = Ahw[w0 + 8 * LDW + 4];
                al[0] = Alw[w0]; al[1] = Alw[w0 + 8 * LDW];
                al[2] = Alw[w0 + 4]; al[3] = Alw[w0 + 8 * LDW + 4];
                #pragma unroll
                for (int nt = 0; nt < 4; nt++) {
                    mma_bf16(acc[mt][nt], ah, bh[nt]);
                    mma_bf16(acc[mt][nt], ah, bl[nt]);
                    mma_bf16(acc[mt][nt], al, bh[nt]);
                }
            }
        }
    };

    loadA(0); cpB(0, 0); CP_COMMIT(); storeA(0);
    CP_WAIT0(); __syncthreads();
    #pragma unroll
    for (int c = 0; c < 4; c++) {
        int buf = c & 1;
        if (c < 3) { loadA(c + 1); cpB(c + 1, buf ^ 1); CP_COMMIT(); }
        compute(buf);
        if (c < 3) { storeA(buf ^ 1); CP_WAIT0(); __syncthreads(); }
    }

    // ---- epilogue: bf16 h1 stores + attn dot-products ----
    #pragma unroll
    for (int mt = 0; mt < 2; mt++) {
        int row0 = bm + wm * 32 + mt * 16 + g;
        int row1 = row0 + 8;
        float s0 = 0.f, s1 = 0.f, d0 = 0.f, d1 = 0.f;
        #pragma unroll
        for (int nt = 0; nt < 4; nt++) {
            int lcol = wn * 32 + nt * 8 + 2 * t;
            int col = bn + lcol;
            float as0 = sAs[lcol], as1 = sAs[lcol + 1];
            float ad0 = sAd[lcol], ad1 = sAd[lcol + 1];
            s0 += acc[mt][nt][0] * as0 + acc[mt][nt][1] * as1;
            s1 += acc[mt][nt][2] * as0 + acc[mt][nt][3] * as1;
            d0 += acc[mt][nt][0] * ad0 + acc[mt][nt][1] * ad1;
            d1 += acc[mt][nt][2] * ad0 + acc[mt][nt][3] * ad1;
            if (row0 < Nn)
                *(uint32_t*)(g_h1b + (size_t)row0 * HC + col) =
                    pack2(__float2bfloat16(acc[mt][nt][0]), __float2bfloat16(acc[mt][nt][1]));
            if (row1 < Nn)
                *(uint32_t*)(g_h1b + (size_t)row1 * HC + col) =
                    pack2(__float2bfloat16(acc[mt][nt][2]), __float2bfloat16(acc[mt][nt][3]));
        }
        s0 += __shfl_down_sync(0xffffffffu, s0, 2); s0 += __shfl_down_sync(0xffffffffu, s0, 1);
        s1 += __shfl_down_sync(0xffffffffu, s1, 2); s1 += __shfl_down_sync(0xffffffffu, s1, 1);
        d0 += __shfl_down_sync(0xffffffffu, d0, 2); d0 += __shfl_down_sync(0xffffffffu, d0, 1);
        d1 += __shfl_down_sync(0xffffffffu, d1, 2); d1 += __shfl_down_sync(0xffffffffu, d1, 1);
        if (t == 0) {
            int r0 = mt * 16 + g, r1 = r0 + 8;
            atomicAdd(&red[wm][hl][0][r0], s0);
            atomicAdd(&red[wm][hl][0][r1], s1);
            atomicAdd(&red[wm][hl][1][r0], d0);
            atomicAdd(&red[wm][hl][1][r1], d1);
        }
    }
    __syncthreads();
    if (tid < 128) {
        int n = bm + tid;
        if (n < Nn) {
            int w = tid >> 5, r = tid & 31;
            #pragma unroll
            for (int h = 0; h < 2; h++) {
                int head = (bn >> 6) + h;
                g_als1[n * NH + head] = red[w][h][0][r];
                g_ald1[n * NH + head] = red[w][h][1][r];
            }
        }
    }
}

// ---------------- GEMM2: h2 = agg1 @ W2, fused attn coef epilogue -------------
#define BTILE2 (64 * LDB)
#define G2_BUF (2 * ATILE + 2 * BTILE2)
#define G2_SMEM (2 * G2_BUF)

__global__ void __launch_bounds__(512, 1)
gemm2_mma(const float* __restrict__ a_src, const float* __restrict__ a_dst) {
    extern __shared__ char smem[];
    __shared__ float sAs[64], sAd[64];
    __shared__ float red2[2][128];

    const int tid = threadIdx.x;
    const int wid = tid >> 5;
    const int lane = tid & 31;
    const int wm = wid >> 1;
    const int wn = wid & 1;
    const int g = lane >> 2;
    const int t = lane & 3;

    const int bm = blockIdx.x * MT;
    const uint32_t sb = smem_u32(smem);

    if (tid < 64) { sAs[tid] = (tid < OC) ? a_src[tid] : 0.f;
                    sAd[tid] = (tid < OC) ? a_dst[tid] : 0.f; }
    if (tid < 256) ((float*)red2)[tid] = 0.f;

    float acc[4][4] = {};

    auto stage = [&](int c, int buf) {
        uint32_t dAh = sb + buf * G2_BUF;
        uint32_t dAl = dAh + ATILE;
        uint32_t dBh = dAl + ATILE;
        uint32_t dBl = dBh + BTILE2;
        #pragma unroll
        for (int i = 0; i < 2; i++) {
            int idx = i * 512 + tid;
            int row = idx >> 3;
            int col8 = (idx & 7) * 8;
            size_t ga = (size_t)(bm + row) * HC + c * 64 + col8;
            uint32_t so = row * LDB + col8 * 2;
            cp16(dAh + so, g_a1h + ga);
            cp16(dAl + so, g_a1l + ga);
        }
        {
            int idx = tid;
            int row = idx >> 3;
            int col8 = (idx & 7) * 8;
            size_t gb = (size_t)row * INC + c * 64 + col8;
            uint32_t so = row * LDB + col8 * 2;
            cp16(dBh + so, g_w2h + gb);
            cp16(dBl + so, g_w2l + gb);
        }
    };
    auto compute = [&](int buf) {
        const uint32_t* Ahw = (const uint32_t*)(smem + buf * G2_BUF);
        const uint32_t* Alw = (const uint32_t*)(smem + buf * G2_BUF + ATILE);
        const uint32_t* Bhw = (const uint32_t*)(smem + buf * G2_BUF + 2 * ATILE);
        const uint32_t* Blw = (const uint32_t*)(smem + buf * G2_BUF + 2 * ATILE + BTILE2);
        #pragma unroll
        for (int kk = 0; kk < 4; kk++) {
            const int kw = kk * 8;
            uint32_t bh[4][2], bl[4][2];
            #pragma unroll
            for (int nt = 0; nt < 4; nt++) {
                int w0 = (wn * 32 + nt * 8 + g) * LDW + kw + t;
                bh[nt][0] = Bhw[w0]; bh[nt][1] = Bhw[w0 + 4];
                bl[nt][0] = Blw[w0]; bl[nt][1] = Blw[w0 + 4];
            }
            {
                int w0 = (wm * 16 + g) * LDW + kw + t;
                uint32_t ah[4], al[4];
                ah[0] = Ahw[w0]; ah[1] = Ahw[w0 + 8 * LDW];
                ah[2] = Ahw[w0 + 4]; ah[3] = Ahw[w0 + 8 * LDW + 4];
                al[0] = Alw[w0]; al[1] = Alw[w0 + 8 * LDW];
                al[2] = Alw[w0 + 4]; al[3] = Alw[w0 + 8 * LDW + 4];
                #pragma unroll
                for (int nt = 0; nt < 4; nt++) {
                    mma_bf16(acc[nt], ah, bh[nt]);
                    mma_bf16(acc[nt], ah, bl[nt]);
                    mma_bf16(acc[nt], al, bh[nt]);
                }
            }
        }
    };

    stage(0, 0); CP_COMMIT();
    CP_WAIT0(); __syncthreads();
    #pragma unroll
    for (int c = 0; c < 4; c++) {
        int buf = c & 1;
        if (c < 3) { stage(c + 1, buf ^ 1); CP_COMMIT(); }
        compute(buf);
        if (c < 3) { CP_WAIT0(); __syncthreads(); }
    }

    {
        int row0 = bm + wm * 16 + g;
        int row1 = row0 + 8;
        float s0 = 0.f, s1 = 0.f, d0 = 0.f, d1 = 0.f;
        #pragma unroll
        for (int nt = 0; nt < 4; nt++) {
            int lcol = wn * 32 + nt * 8 + 2 * t;
            float as0 = sAs[lcol], as1 = sAs[lcol + 1];
            float ad0 = sAd[lcol], ad1 = sAd[lcol + 1];
            s0 += acc[nt][0] * as0 + acc[nt][1] * as1;
            s1 += acc[nt][2] * as0 + acc[nt][3] * as1;
            d0 += acc[nt][0] * ad0 + acc[nt][1] * ad1;
            d1 += acc[nt][2] * ad0 + acc[nt][3] * ad1;
            if (lcol < OC) {
                if (row0 < Nn)
                    *(float2*)(g_h2 + (size_t)row0 * OC + lcol) = make_float2(acc[nt][0], acc[nt][1]);
                if (row1 < Nn)
                    *(float2*)(g_h2 + (size_t)row1 * OC + lcol) = make_float2(acc[nt][2], acc[nt][3]);
            }
        }
        s0 += __shfl_down_sync(0xffffffffu, s0, 2); s0 += __shfl_down_sync(0xffffffffu, s0, 1);
        s1 += __shfl_down_sync(0xffffffffu, s1, 2); s1 += __shfl_down_sync(0xffffffffu, s1, 1);
        d0 += __shfl_down_sync(0xffffffffu, d0, 2); d0 += __shfl_down_sync(0xffffffffu, d0, 1);
        d1 += __shfl_down_sync(0xffffffffu, d1, 2); d1 += __shfl_down_sync(0xffffffffu, d1, 1);
        if (t == 0) {
            int r0 = wm * 16 + g, r1 = r0 + 8;
            atomicAdd(&red2[0][r0], s0);
            atomicAdd(&red2[0][r1], s1);
            atomicAdd(&red2[1][r0], d0);
            atomicAdd(&red2[1][r1], d1);
        }
    }
    __syncthreads();
    if (tid < 128) {
        int n = bm + tid;
        if (n < Nn) {
            g_als2[n] = red2[0][tid];
            g_ald2[n] = red2[1][tid];
        }
    }
}

// ---------------- layer 1: bf16 gather softmax+agg+bias+relu+split ------------
// 256 threads: warp = edge slot (8 parallel edges), lane = uint4 of 8 channels
__global__ __launch_bounds__(256) void agg1_kernel(const float* __restrict__ b1) {
    int d = blockIdx.x;
    int start = g_rowptr[d], end = g_rowptr[d + 1];
    int tid = threadIdx.x;
    __shared__ float sden[NH];
    __shared__ int ssrc[128];
    __shared__ float salpha[128 * NH];
    __shared__ float sacc[8 * 256];

    if (tid < NH) sden[tid] = 1e-16f;
    float4 aldv = *(const float4*)&g_ald1[d * NH];

    const int ch8 = tid & 31;       // uint4 lane: channels [ch8*8, ch8*8+8)
    const int slot = tid >> 5;      // 0..7 edge slot (= warp)
    const int head = ch8 >> 3;
    float acc[8] = {};
    float p0 = 0.f, p1 = 0.f, p2 = 0.f, p3 = 0.f;

    for (int base = start; base < end; base += 128) {
        int cnt = min(128, end - base);
        __syncthreads();
        if (tid < cnt) {
            int s = g_srcl[base + tid];
            ssrc[tid] = s;
            float4 als = *(const float4*)&g_als1[s * NH];
            float e0 = __expf(lrelu(als.x + aldv.x));
            float e1 = __expf(lrelu(als.y + aldv.y));
            float e2 = __expf(lrelu(als.z + aldv.z));
            float e3 = __expf(lrelu(als.w + aldv.w));
            salpha[tid * 4 + 0] = e0; salpha[tid * 4 + 1] = e1;
            salpha[tid * 4 + 2] = e2; salpha[tid * 4 + 3] = e3;
            p0 += e0; p1 += e1; p2 += e2; p3 += e3;
        }
        __syncthreads();
        for (int j = slot; j < cnt; j += 8) {
            float a = salpha[j * 4 + head];
            int s = ssrc[j];
            uint4 hv = *(const uint4*)(g_h1b + (size_t)s * HC + ch8 * 8);
            const __nv_bfloat162* hp = (const __nv_bfloat162*)&hv;
            #pragma unroll
            for (int q = 0; q < 4; q++) {
                float2 f = __bfloat1622float2(hp[q]);
                acc[q * 2]     = fmaf(a, f.x, acc[q * 2]);
                acc[q * 2 + 1] = fmaf(a, f.y, acc[q * 2 + 1]);
            }
        }
    }
    #pragma unroll
    for (int off = 16; off; off >>= 1) {
        p0 += __shfl_down_sync(0xffffffffu, p0, off);
        p1 += __shfl_down_sync(0xffffffffu, p1, off);
        p2 += __shfl_down_sync(0xffffffffu, p2, off);
        p3 += __shfl_down_sync(0xffffffffu, p3, off);
    }
    if ((tid & 31) == 0) {
        atomicAdd(&sden[0], p0);
        atomicAdd(&sden[1], p1);
        atomicAdd(&sden[2], p2);
        atomicAdd(&sden[3], p3);
    }
    #pragma unroll
    for (int q = 0; q < 8; q++)
        sacc[slot * 256 + ch8 * 8 + q] = acc[q];
    __syncthreads();
    if (tid < 64) {
        int ch = tid * 4;
        float4 r = make_float4(0.f, 0.f, 0.f, 0.f);
        #pragma unroll
        for (int s = 0; s < 8; s++) {
            r.x += sacc[s * 256 + ch];
            r.y += sacc[s * 256 + ch + 1];
            r.z += sacc[s * 256 + ch + 2];
            r.w += sacc[s * 256 + ch + 3];
        }
        float rd = 1.f / sden[tid >> 4];
        float4 bb = *(const float4*)(b1 + ch);
        r.x = fmaxf(r.x * rd + bb.x, 0.f);
        r.y = fmaxf(r.y * rd + bb.y, 0.f);
        r.z = fmaxf(r.z * rd + bb.z, 0.f);
        r.w = fmaxf(r.w * rd + bb.w, 0.f);
        uint2 hh, ll;
        split4(r, hh, ll);
        *(uint2*)(g_a1h + (size_t)d * HC + ch) = hh;
        *(uint2*)(g_a1l + (size_t)d * HC + ch) = ll;
    }
}

// ---------------- layer 2 single-pass agg + log_softmax ----------------------
__global__ void agg2_final(const float* __restrict__ b2, float* __restrict__ out) {
    int n = blockIdx.x * 8 + (threadIdx.x >> 5);
    if (n >= Nn) return;
    int lane = threadIdx.x & 31;
    int start = g_rowptr[n], end = g_rowptr[n + 1];
    float ald = g_ald2[n];

    float den = 0.f, acc0 = 0.f, acc1 = 0.f;
    for (int base = start; base < end; base += 32) {
        int i = base + lane;
        int s = 0; float e = 0.f;
        if (i < end) {
            s = g_srcl[i];
            e = __expf(lrelu(g_als2[s] + ald));
        }
        den += e;
        int cnt = min(32, end - base);
        for (int j = 0; j < cnt; j++) {
            int   sj = __shfl_sync(0xffffffffu, s, j);
            float ej = __shfl_sync(0xffffffffu, e, j);
            acc0 = fmaf(ej, g_h2[sj * OC + lane], acc0);
            if (lane < 8) acc1 = fmaf(ej, g_h2[sj * OC + 32 + lane], acc1);
        }
    }
    #pragma unroll
    for (int off = 16; off; off >>= 1)
        den += __shfl_xor_sync(0xffffffffu, den, off);
    float rden = 1.f / (den + 1e-16f);

    float v0 = acc0 * rden + b2[lane];
    float v1 = (lane < 8) ? (acc1 * rden + b2[32 + lane]) : -3.402823466e38f;
    float mx = fmaxf(v0, v1);
    #pragma unroll
    for (int off = 16; off; off >>= 1)
        mx = fmaxf(mx, __shfl_xor_sync(0xffffffffu, mx, off));
    float se = expf(v0 - mx) + ((lane < 8) ? expf(v1 - mx) : 0.f);
    #pragma unroll
    for (int off = 16; off; off >>= 1)
        se += __shfl_xor_sync(0xffffffffu, se, off);
    float lse = mx + logf(se);
    out[n * OC + lane] = v0 - lse;
    if (lane < 8) out[n * OC + 32 + lane] = v1 - lse;
}

// ---------------- launch -----------------------------------------------------
extern "C" void kernel_launch(void* const* d_in, const int* in_sizes, int n_in,
                              void* d_out, int out_size) {
    const float* x      = (const float*)d_in[0];
    const int*   ei     = (const int*)d_in[1];
    const float* W1     = (const float*)d_in[2];
    const float* a_src1 = (const float*)d_in[3];
    const float* a_dst1 = (const float*)d_in[4];
    const float* b1     = (const float*)d_in[5];
    const float* W2     = (const float*)d_in[6];
    const float* a_src2 = (const float*)d_in[7];
    const float* a_dst2 = (const float*)d_in[8];
    const float* b2     = (const float*)d_in[9];
    float* out = (float*)d_out;

    cudaFuncSetAttribute(gemm1_mma, cudaFuncAttributeMaxDynamicSharedMemorySize, G1_SMEM);
    cudaFuncSetAttribute(gemm2_mma, cudaFuncAttributeMaxDynamicSharedMemorySize, G2_SMEM);

    convert_w<<<(INC * HC + 64 * INC + 255) / 256, 256>>>(W1, W2);
    gemm1_mma<<<MTILES * 2 + HBLK, 512, G1_SMEM>>>(x, ei, a_src1, a_dst1);
    scan_part<<<NB, 256>>>();
    scan_add2<<<NB, 256>>>();
    fill_kernel<<<(Ee / 4 + Nn + 255) / 256, 256>>>(ei);
    agg1_kernel<<<Nn, 256>>>(b1);
    gemm2_mma<<<MTILES, 512, G2_SMEM>>>(a_src2, a_dst2);
    agg2_final<<<(Nn + 7) / 8, 256>>>(b2, out);
}

// round 11
// speedup vs baseline: 1.4967x; 1.4967x over previous
#include <cuda_runtime.h>
#include <cuda_bf16.h>
#include <cstdint>

#define Nn 50000
#define Ee 800000
#define ET (Ee + Nn)
#define INC 256
#define HC 256
#define NH 4
#define OC 40
#define NB ((Nn + 255) / 256)

#define MT 128
#define MTILES ((Nn + MT - 1) / MT)
#define PADN (MTILES * MT)
#define HBLK 391

// ---------------- scratch ----------------------------------------------------
__device__ __align__(16) __nv_bfloat16 g_h1b[(size_t)Nn * HC];   // bf16 messages
__device__ float g_als1[Nn * NH];
__device__ float g_ald1[Nn * NH];
__device__ float g_h2[Nn * OC];
__device__ float g_als2[Nn];
__device__ float g_ald2[Nn];
__device__ int g_counts[Nn];
__device__ int g_fill[Nn];
__device__ int g_rowptr[Nn + 1];
__device__ int g_srcl[ET];
__device__ int g_bsum[NB];
__device__ __align__(16) __nv_bfloat16 g_w1h[INC * HC];
__device__ __align__(16) __nv_bfloat16 g_w1l[INC * HC];
__device__ __align__(16) __nv_bfloat16 g_w2h[64 * INC];
__device__ __align__(16) __nv_bfloat16 g_w2l[64 * INC];
__device__ __align__(16) __nv_bfloat16 g_a1h[(size_t)PADN * HC];
__device__ __align__(16) __nv_bfloat16 g_a1l[(size_t)PADN * HC];

// ---------------- helpers ----------------------------------------------------
__device__ __forceinline__ float lrelu(float v) { return (v > 0.f) ? v : 0.2f * v; }
__device__ __forceinline__ uint32_t pack2(__nv_bfloat16 a, __nv_bfloat16 b) {
    __nv_bfloat162 t; t.x = a; t.y = b;
    return *reinterpret_cast<uint32_t*>(&t);
}
__device__ __forceinline__ void split4(float4 v, uint2& hh, uint2& ll) {
    __nv_bfloat16 h0 = __float2bfloat16(v.x), h1 = __float2bfloat16(v.y);
    __nv_bfloat16 h2 = __float2bfloat16(v.z), h3 = __float2bfloat16(v.w);
    __nv_bfloat16 l0 = __float2bfloat16(v.x - __bfloat162float(h0));
    __nv_bfloat16 l1 = __float2bfloat16(v.y - __bfloat162float(h1));
    __nv_bfloat16 l2 = __float2bfloat16(v.z - __bfloat162float(h2));
    __nv_bfloat16 l3 = __float2bfloat16(v.w - __bfloat162float(h3));
    hh.x = pack2(h0, h1); hh.y = pack2(h2, h3);
    ll.x = pack2(l0, l1); ll.y = pack2(l2, l3);
}
__device__ __forceinline__ uint32_t smem_u32(const void* p) {
    uint32_t a;
    asm("{ .reg .u64 t; cvta.to.shared.u64 t, %1; cvt.u32.u64 %0, t; }" : "=r"(a) : "l"(p));
    return a;
}
__device__ __forceinline__ void cp16(uint32_t dst, const void* src) {
    asm volatile("cp.async.ca.shared.global [%0], [%1], 16;" :: "r"(dst), "l"(src));
}
#define CP_COMMIT() asm volatile("cp.async.commit_group;" ::: "memory")
#define CP_WAIT0()  asm volatile("cp.async.wait_group 0;" ::: "memory")

// ---------------- convert_w + init (fused) -------------------------------------
__global__ void convert_w(const float* __restrict__ W1, const float* __restrict__ W2) {
    int t = blockIdx.x * blockDim.x + threadIdx.x;
    if (t < INC * HC) {
        int k = t >> 8, n = t & 255;
        float v = W1[t];
        __nv_bfloat16 h = __float2bfloat16(v);
        g_w1h[n * INC + k] = h;
        g_w1l[n * INC + k] = __float2bfloat16(v - __bfloat162float(h));
    } else if (t < INC * HC + 64 * INC) {
        int u = t - INC * HC;
        int n = u >> 8, k = u & 255;
        float v = (n < OC) ? W2[k * OC + n] : 0.f;
        __nv_bfloat16 h = __float2bfloat16(v);
        g_w2h[n * INC + k] = h;
        g_w2l[n * INC + k] = __float2bfloat16(v - __bfloat162float(h));
    }
    if (t < Nn) { g_counts[t] = 1; g_fill[t] = 0; }
}

// ---------------- scan (2 kernels) ---------------------------------------------
__device__ __forceinline__ int block_incl_scan(int v, int* ws) {
    int lane = threadIdx.x & 31, warp = threadIdx.x >> 5;
    #pragma unroll
    for (int o = 1; o < 32; o <<= 1) {
        int u = __shfl_up_sync(0xffffffffu, v, o);
        if (lane >= o) v += u;
    }
    if (lane == 31) ws[warp] = v;
    __syncthreads();
    if (warp == 0 && lane < 8) {
        int w = ws[lane];
        #pragma unroll
        for (int o = 1; o < 8; o <<= 1) {
            int u = __shfl_up_sync(0xffu, w, o);
            if (lane >= o) w += u;
        }
        ws[lane] = w;
    }
    __syncthreads();
    if (warp > 0) v += ws[warp - 1];
    return v;
}
__global__ void scan_part() {
    __shared__ int ws[8];
    int idx = blockIdx.x * 256 + threadIdx.x;
    int v = (idx < Nn) ? g_counts[idx] : 0;
    int incl = block_incl_scan(v, ws);
    if (idx < Nn) g_rowptr[idx + 1] = incl;
    if (threadIdx.x == 255) g_bsum[blockIdx.x] = incl;
}
__global__ void scan_add2() {
    __shared__ int ws[8];
    int j = blockIdx.x;
    int tid = threadIdx.x;
    int lane = tid & 31, warp = tid >> 5;
    int v = (tid < j) ? g_bsum[tid] : 0;
    #pragma unroll
    for (int o = 16; o; o >>= 1) v += __shfl_down_sync(0xffffffffu, v, o);
    if (lane == 0) ws[warp] = v;
    __syncthreads();
    if (warp == 0) {
        int w = (lane < 8) ? ws[lane] : 0;
        #pragma unroll
        for (int o = 4; o; o >>= 1) w += __shfl_down_sync(0xffffffffu, w, o);
        if (lane == 0) ws[0] = w;
    }
    __syncthreads();
    int offset = ws[0];
    int idx = j * 256 + tid;
    if (idx < Nn) g_rowptr[idx + 1] += offset;
    if (j == 0 && tid == 0) g_rowptr[0] = 0;
}
__global__ void fill_kernel(const int* __restrict__ ei) {
    const int Q = Ee / 4;
    int i = blockIdx.x * blockDim.x + threadIdx.x;
    if (i < Q) {
        int4 s = ((const int4*)ei)[i];
        int4 d = ((const int4*)(ei + Ee))[i];
        int p;
        p = g_rowptr[d.x] + atomicAdd(&g_fill[d.x], 1); g_srcl[p] = s.x;
        p = g_rowptr[d.y] + atomicAdd(&g_fill[d.y], 1); g_srcl[p] = s.y;
        p = g_rowptr[d.z] + atomicAdd(&g_fill[d.z], 1); g_srcl[p] = s.z;
        p = g_rowptr[d.w] + atomicAdd(&g_fill[d.w], 1); g_srcl[p] = s.w;
    } else {
        int n = i - Q;
        if (n < Nn) {
            int p = g_rowptr[n] + atomicAdd(&g_fill[n], 1);
            g_srcl[p] = n;
        }
    }
}

// ---------------- GEMM common ---------------------------------------------------
#define LDW 36
#define LDB 144
#define ATILE (128 * LDB)

__device__ __forceinline__ void mma_bf16(float* c, const uint32_t* a, const uint32_t* b) {
    asm volatile(
        "mma.sync.aligned.m16n8k16.row.col.f32.bf16.bf16.f32 "
        "{%0,%1,%2,%3}, {%4,%5,%6,%7}, {%8,%9}, {%0,%1,%2,%3};"
        : "+f"(c[0]), "+f"(c[1]), "+f"(c[2]), "+f"(c[3])
        : "r"(a[0]), "r"(a[1]), "r"(a[2]), "r"(a[3]), "r"(b[0]), "r"(b[1]));
}

// ---------------- GEMM1 (+ hist blocks): h1b = bf16(x @ W1), fused attn coef ---
#define G1_BUF (4 * ATILE)
#define G1_SMEM (2 * G1_BUF)

__global__ void __launch_bounds__(512, 1)
gemm1_mma(const float* __restrict__ X, const int* __restrict__ ei,
          const float* __restrict__ a_src, const float* __restrict__ a_dst) {
    if (blockIdx.x >= MTILES * 2) {
        int i = (blockIdx.x - MTILES * 2) * 512 + threadIdx.x;
        if (i < Ee / 4) {
            int4 d = ((const int4*)(ei + Ee))[i];
            atomicAdd(&g_counts[d.x], 1);
            atomicAdd(&g_counts[d.y], 1);
            atomicAdd(&g_counts[d.z], 1);
            atomicAdd(&g_counts[d.w], 1);
        }
        return;
    }

    extern __shared__ char smem[];
    __shared__ float sAs[128], sAd[128];
    __shared__ float red[4][2][2][32];

    const int tid = threadIdx.x;
    const int wid = tid >> 5;
    const int lane = tid & 31;
    const int wm = wid >> 2;
    const int wn = wid & 3;
    const int g = lane >> 2;
    const int t = lane & 3;
    const int hl = wn >> 1;

    const int bm = (blockIdx.x >> 1) * MT;
    const int bn = (blockIdx.x & 1) * 128;

    const uint32_t sb = smem_u32(smem);

    if (tid < 128) { sAs[tid] = a_src[bn + tid]; sAd[tid] = a_dst[bn + tid]; }
    ((float*)red)[tid] = 0.f;

    float acc[2][4][4] = {};
    float4 aregs[4];

    auto loadA = [&](int c) {
        #pragma unroll
        for (int i = 0; i < 4; i++) {
            int idx = i * 512 + tid;
            int row = idx >> 4;
            int col4 = (idx & 15) * 4;
            int grow = bm + row;
            aregs[i] = (grow < Nn)
                ? *(const float4*)(X + (size_t)grow * INC + c * 64 + col4)
                : make_float4(0.f, 0.f, 0.f, 0.f);
        }
    };
    auto storeA = [&](int buf) {
        char* sAh = smem + buf * G1_BUF;
        char* sAl = sAh + ATILE;
        #pragma unroll
        for (int i = 0; i < 4; i++) {
            int idx = i * 512 + tid;
            int row = idx >> 4;
            int col4 = (idx & 15) * 4;
            uint2 hh, ll;
            split4(aregs[i], hh, ll);
            int so = row * LDB + col4 * 2;
            *(uint2*)(sAh + so) = hh;
            *(uint2*)(sAl + so) = ll;
        }
    };
    auto cpB = [&](int c, int buf) {
        uint32_t dBh = sb + buf * G1_BUF + 2 * ATILE;
        uint32_t dBl = dBh + ATILE;
        #pragma unroll
        for (int i = 0; i < 2; i++) {
            int idx = i * 512 + tid;
            int row = idx >> 3;
            int col8 = (idx & 7) * 8;
            size_t gb = (size_t)(bn + row) * INC + c * 64 + col8;
            uint32_t so = row * LDB + col8 * 2;
            cp16(dBh + so, g_w1h + gb);
            cp16(dBl + so, g_w1l + gb);
        }
    };
    auto compute = [&](int buf) {
        const uint32_t* Ahw = (const uint32_t*)(smem + buf * G1_BUF);
        const uint32_t* Alw = (const uint32_t*)(smem + buf * G1_BUF + ATILE);
        const uint32_t* Bhw = (const uint32_t*)(smem + buf * G1_BUF + 2 * ATILE);
        const uint32_t* Blw = (const uint32_t*)(smem + buf * G1_BUF + 3 * ATILE);
        #pragma unroll
        for (int kk = 0; kk < 4; kk++) {
            const int kw = kk * 8;
            uint32_t bh[4][2], bl[4][2];
            #pragma unroll
            for (int nt = 0; nt < 4; nt++) {
                int w0 = (wn * 32 + nt * 8 + g) * LDW + kw + t;
                bh[nt][0] = Bhw[w0]; bh[nt][1] = Bhw[w0 + 4];
                bl[nt][0] = Blw[w0]; bl[nt][1] = Blw[w0 + 4];
            }
            #pragma unroll
            for (int mt = 0; mt < 2; mt++) {
                int w0 = (wm * 32 + mt * 16 + g) * LDW + kw + t;
                uint32_t ah[4], al[4];
                ah[0] = Ahw[w0]; ah[1] = Ahw[w0 + 8 * LDW];
                ah[2] = Ahw[w0 + 4]; ah[3] = Ahw[w0 + 8 * LDW + 4];
                al[0] = Alw[w0]; al[1] = Alw[w0 + 8 * LDW];
                al[2] = Alw[w0 + 4]; al[3] = Alw[w0 + 8 * LDW + 4];
                #pragma unroll
                for (int nt = 0; nt < 4; nt++) {
                    mma_bf16(acc[mt][nt], ah, bh[nt]);
                    mma_bf16(acc[mt][nt], ah, bl[nt]);
                    mma_bf16(acc[mt][nt], al, bh[nt]);
                }
            }
        }
    };

    loadA(0); cpB(0, 0); CP_COMMIT(); storeA(0);
    CP_WAIT0(); __syncthreads();
    #pragma unroll
    for (int c = 0; c < 4; c++) {
        int buf = c & 1;
        if (c < 3) { loadA(c + 1); cpB(c + 1, buf ^ 1); CP_COMMIT(); }
        compute(buf);
        if (c < 3) { storeA(buf ^ 1); CP_WAIT0(); __syncthreads(); }
    }

    // ---- epilogue: bf16 h1 stores + attn dot-products ----
    #pragma unroll
    for (int mt = 0; mt < 2; mt++) {
        int row0 = bm + wm * 32 + mt * 16 + g;
        int row1 = row0 + 8;
        float s0 = 0.f, s1 = 0.f, d0 = 0.f, d1 = 0.f;
        #pragma unroll
        for (int nt = 0; nt < 4; nt++) {
            int lcol = wn * 32 + nt * 8 + 2 * t;
            int col = bn + lcol;
            float as0 = sAs[lcol], as1 = sAs[lcol + 1];
            float ad0 = sAd[lcol], ad1 = sAd[lcol + 1];
            s0 += acc[mt][nt][0] * as0 + acc[mt][nt][1] * as1;
            s1 += acc[mt][nt][2] * as0 + acc[mt][nt][3] * as1;
            d0 += acc[mt][nt][0] * ad0 + acc[mt][nt][1] * ad1;
            d1 += acc[mt][nt][2] * ad0 + acc[mt][nt][3] * ad1;
            if (row0 < Nn)
                *(uint32_t*)(g_h1b + (size_t)row0 * HC + col) =
                    pack2(__float2bfloat16(acc[mt][nt][0]), __float2bfloat16(acc[mt][nt][1]));
            if (row1 < Nn)
                *(uint32_t*)(g_h1b + (size_t)row1 * HC + col) =
                    pack2(__float2bfloat16(acc[mt][nt][2]), __float2bfloat16(acc[mt][nt][3]));
        }
        s0 += __shfl_down_sync(0xffffffffu, s0, 2); s0 += __shfl_down_sync(0xffffffffu, s0, 1);
        s1 += __shfl_down_sync(0xffffffffu, s1, 2); s1 += __shfl_down_sync(0xffffffffu, s1, 1);
        d0 += __shfl_down_sync(0xffffffffu, d0, 2); d0 += __shfl_down_sync(0xffffffffu, d0, 1);
        d1 += __shfl_down_sync(0xffffffffu, d1, 2); d1 += __shfl_down_sync(0xffffffffu, d1, 1);
        if (t == 0) {
            int r0 = mt * 16 + g, r1 = r0 + 8;
            atomicAdd(&red[wm][hl][0][r0], s0);
            atomicAdd(&red[wm][hl][0][r1], s1);
            atomicAdd(&red[wm][hl][1][r0], d0);
            atomicAdd(&red[wm][hl][1][r1], d1);
        }
    }
    __syncthreads();
    if (tid < 128) {
        int n = bm + tid;
        if (n < Nn) {
            int w = tid >> 5, r = tid & 31;
            #pragma unroll
            for (int h = 0; h < 2; h++) {
                int head = (bn >> 6) + h;
                g_als1[n * NH + head] = red[w][h][0][r];
                g_ald1[n * NH + head] = red[w][h][1][r];
            }
        }
    }
}

// ---------------- GEMM2: h2 = agg1 @ W2, fused attn coef epilogue -------------
#define BTILE2 (64 * LDB)
#define G2_BUF (2 * ATILE + 2 * BTILE2)
#define G2_SMEM (2 * G2_BUF)

__global__ void __launch_bounds__(512, 1)
gemm2_mma(const float* __restrict__ a_src, const float* __restrict__ a_dst) {
    extern __shared__ char smem[];
    __shared__ float sAs[64], sAd[64];
    __shared__ float red2[2][128];

    const int tid = threadIdx.x;
    const int wid = tid >> 5;
    const int lane = tid & 31;
    const int wm = wid >> 1;
    const int wn = wid & 1;
    const int g = lane >> 2;
    const int t = lane & 3;

    const int bm = blockIdx.x * MT;
    const uint32_t sb = smem_u32(smem);

    if (tid < 64) { sAs[tid] = (tid < OC) ? a_src[tid] : 0.f;
                    sAd[tid] = (tid < OC) ? a_dst[tid] : 0.f; }
    if (tid < 256) ((float*)red2)[tid] = 0.f;

    float acc[4][4] = {};

    auto stage = [&](int c, int buf) {
        uint32_t dAh = sb + buf * G2_BUF;
        uint32_t dAl = dAh + ATILE;
        uint32_t dBh = dAl + ATILE;
        uint32_t dBl = dBh + BTILE2;
        #pragma unroll
        for (int i = 0; i < 2; i++) {
            int idx = i * 512 + tid;
            int row = idx >> 3;
            int col8 = (idx & 7) * 8;
            size_t ga = (size_t)(bm + row) * HC + c * 64 + col8;
            uint32_t so = row * LDB + col8 * 2;
            cp16(dAh + so, g_a1h + ga);
            cp16(dAl + so, g_a1l + ga);
        }
        {
            int idx = tid;
            int row = idx >> 3;
            int col8 = (idx & 7) * 8;
            size_t gb = (size_t)row * INC + c * 64 + col8;
            uint32_t so = row * LDB + col8 * 2;
            cp16(dBh + so, g_w2h + gb);
            cp16(dBl + so, g_w2l + gb);
        }
    };
    auto compute = [&](int buf) {
        const uint32_t* Ahw = (const uint32_t*)(smem + buf * G2_BUF);
        const uint32_t* Alw = (const uint32_t*)(smem + buf * G2_BUF + ATILE);
        const uint32_t* Bhw = (const uint32_t*)(smem + buf * G2_BUF + 2 * ATILE);
        const uint32_t* Blw = (const uint32_t*)(smem + buf * G2_BUF + 2 * ATILE + BTILE2);
        #pragma unroll
        for (int kk = 0; kk < 4; kk++) {
            const int kw = kk * 8;
            uint32_t bh[4][2], bl[4][2];
            #pragma unroll
            for (int nt = 0; nt < 4; nt++) {
                int w0 = (wn * 32 + nt * 8 + g) * LDW + kw + t;
                bh[nt][0] = Bhw[w0]; bh[nt][1] = Bhw[w0 + 4];
                bl[nt][0] = Blw[w0]; bl[nt][1] = Blw[w0 + 4];
            }
            {
                int w0 = (wm * 16 + g) * LDW + kw + t;
                uint32_t ah[4], al[4];
                ah[0] = Ahw[w0]; ah[1] = Ahw[w0 + 8 * LDW];
                ah[2] = Ahw[w0 + 4]; ah[3] = Ahw[w0 + 8 * LDW + 4];
                al[0] = Alw[w0]; al[1] = Alw[w0 + 8 * LDW];
                al[2] = Alw[w0 + 4]; al[3] = Alw[w0 + 8 * LDW + 4];
                #pragma unroll
                for (int nt = 0; nt < 4; nt++) {
                    mma_bf16(acc[nt], ah, bh[nt]);
                    mma_bf16(acc[nt], ah, bl[nt]);
                    mma_bf16(acc[nt], al, bh[nt]);
                }
            }
        }
    };

    stage(0, 0); CP_COMMIT();
    CP_WAIT0(); __syncthreads();
    #pragma unroll
    for (int c = 0; c < 4; c++) {
        int buf = c & 1;
        if (c < 3) { stage(c + 1, buf ^ 1); CP_COMMIT(); }
        compute(buf);
        if (c < 3) { CP_WAIT0(); __syncthreads(); }
    }

    {
        int row0 = bm + wm * 16 + g;
        int row1 = row0 + 8;
        float s0 = 0.f, s1 = 0.f, d0 = 0.f, d1 = 0.f;
        #pragma unroll
        for (int nt = 0; nt < 4; nt++) {
            int lcol = wn * 32 + nt * 8 + 2 * t;
            float as0 = sAs[lcol], as1 = sAs[lcol + 1];
            float ad0 = sAd[lcol], ad1 = sAd[lcol + 1];
            s0 += acc[nt][0] * as0 + acc[nt][1] * as1;
            s1 += acc[nt][2] * as0 + acc[nt][3] * as1;
            d0 += acc[nt][0] * ad0 + acc[nt][1] * ad1;
            d1 += acc[nt][2] * ad0 + acc[nt][3] * ad1;
            if (lcol < OC) {
                if (row0 < Nn)
                    *(float2*)(g_h2 + (size_t)row0 * OC + lcol) = make_float2(acc[nt][0], acc[nt][1]);
                if (row1 < Nn)
                    *(float2*)(g_h2 + (size_t)row1 * OC + lcol) = make_float2(acc[nt][2], acc[nt][3]);
            }
        }
        s0 += __shfl_down_sync(0xffffffffu, s0, 2); s0 += __shfl_down_sync(0xffffffffu, s0, 1);
        s1 += __shfl_down_sync(0xffffffffu, s1, 2); s1 += __shfl_down_sync(0xffffffffu, s1, 1);
        d0 += __shfl_down_sync(0xffffffffu, d0, 2); d0 += __shfl_down_sync(0xffffffffu, d0, 1);
        d1 += __shfl_down_sync(0xffffffffu, d1, 2); d1 += __shfl_down_sync(0xffffffffu, d1, 1);
        if (t == 0) {
            int r0 = wm * 16 + g, r1 = r0 + 8;
            atomicAdd(&red2[0][r0], s0);
            atomicAdd(&red2[0][r1], s1);
            atomicAdd(&red2[1][r0], d0);
            atomicAdd(&red2[1][r1], d1);
        }
    }
    __syncthreads();
    if (tid < 128) {
        int n = bm + tid;
        if (n < Nn) {
            g_als2[n] = red2[0][tid];
            g_ald2[n] = red2[1][tid];
        }
    }
}

// ---------------- layer 1: round-9 structure, bf16 uint2 gathers ---------------
// 256 threads: slot = tid>>6 (4 parallel edges), ch4 = tid&63 (4 channels each)
__global__ __launch_bounds__(256) void agg1_kernel(const float* __restrict__ b1) {
    int d = blockIdx.x;
    int start = g_rowptr[d], end = g_rowptr[d + 1];
    int tid = threadIdx.x;
    __shared__ float sden[NH];
    __shared__ int ssrc[128];
    __shared__ float salpha[128 * NH];
    __shared__ float4 sacc[4 * 64];

    if (tid < NH) sden[tid] = 1e-16f;
    float4 aldv = *(const float4*)&g_ald1[d * NH];

    const int ch4 = tid & 63;       // channels [ch4*4, ch4*4+4)
    const int slot = tid >> 6;      // 0..3 edge slot
    const int head = ch4 >> 4;
    float4 acc = make_float4(0.f, 0.f, 0.f, 0.f);
    float p0 = 0.f, p1 = 0.f, p2 = 0.f, p3 = 0.f;

    for (int base = start; base < end; base += 128) {
        int cnt = min(128, end - base);
        __syncthreads();
        if (tid < cnt) {
            int s = g_srcl[base + tid];
            ssrc[tid] = s;
            float4 als = *(const float4*)&g_als1[s * NH];
            float e0 = __expf(lrelu(als.x + aldv.x));
            float e1 = __expf(lrelu(als.y + aldv.y));
            float e2 = __expf(lrelu(als.z + aldv.z));
            float e3 = __expf(lrelu(als.w + aldv.w));
            salpha[tid * 4 + 0] = e0; salpha[tid * 4 + 1] = e1;
            salpha[tid * 4 + 2] = e2; salpha[tid * 4 + 3] = e3;
            p0 += e0; p1 += e1; p2 += e2; p3 += e3;
        }
        __syncthreads();
        int j = slot;
        for (; j + 4 < cnt; j += 8) {
            float a0 = salpha[j * 4 + head];
            float a1 = salpha[(j + 4) * 4 + head];
            int s0 = ssrc[j], s1 = ssrc[j + 4];
            uint2 hv0 = *(const uint2*)(g_h1b + (size_t)s0 * HC + ch4 * 4);
            uint2 hv1 = *(const uint2*)(g_h1b + (size_t)s1 * HC + ch4 * 4);
            float2 f00 = __bfloat1622float2(*(const __nv_bfloat162*)&hv0.x);
            float2 f01 = __bfloat1622float2(*(const __nv_bfloat162*)&hv0.y);
            float2 f10 = __bfloat1622float2(*(const __nv_bfloat162*)&hv1.x);
            float2 f11 = __bfloat1622float2(*(const __nv_bfloat162*)&hv1.y);
            acc.x = fmaf(a0, f00.x, acc.x); acc.y = fmaf(a0, f00.y, acc.y);
            acc.z = fmaf(a0, f01.x, acc.z); acc.w = fmaf(a0, f01.y, acc.w);
            acc.x = fmaf(a1, f10.x, acc.x); acc.y = fmaf(a1, f10.y, acc.y);
            acc.z = fmaf(a1, f11.x, acc.z); acc.w = fmaf(a1, f11.y, acc.w);
        }
        for (; j < cnt; j += 4) {
            float a = salpha[j * 4 + head];
            int s = ssrc[j];
            uint2 hv = *(const uint2*)(g_h1b + (size_t)s * HC + ch4 * 4);
            float2 f0 = __bfloat1622float2(*(const __nv_bfloat162*)&hv.x);
            float2 f1 = __bfloat1622float2(*(const __nv_bfloat162*)&hv.y);
            acc.x = fmaf(a, f0.x, acc.x);
            acc.y = fmaf(a, f0.y, acc.y);
            acc.z = fmaf(a, f1.x, acc.z);
            acc.w = fmaf(a, f1.y, acc.w);
        }
    }
    #pragma unroll
    for (int off = 16; off; off >>= 1) {
        p0 += __shfl_down_sync(0xffffffffu, p0, off);
        p1 += __shfl_down_sync(0xffffffffu, p1, off);
        p2 += __shfl_down_sync(0xffffffffu, p2, off);
        p3 += __shfl_down_sync(0xffffffffu, p3, off);
    }
    if ((tid & 31) == 0) {
        atomicAdd(&sden[0], p0);
        atomicAdd(&sden[1], p1);
        atomicAdd(&sden[2], p2);
        atomicAdd(&sden[3], p3);
    }
    sacc[slot * 64 + ch4] = acc;
    __syncthreads();
    if (tid < 64) {
        float4 a0 = sacc[tid], a1 = sacc[64 + tid], a2 = sacc[128 + tid], a3 = sacc[192 + tid];
        float rd = 1.f / sden[tid >> 4];
        int ch = tid * 4;
        float4 bb = *(const float4*)(b1 + ch);
        float4 r;
        r.x = fmaxf((a0.x + a1.x + a2.x + a3.x) * rd + bb.x, 0.f);
        r.y = fmaxf((a0.y + a1.y + a2.y + a3.y) * rd + bb.y, 0.f);
        r.z = fmaxf((a0.z + a1.z + a2.z + a3.z) * rd + bb.z, 0.f);
        r.w = fmaxf((a0.w + a1.w + a2.w + a3.w) * rd + bb.w, 0.f);
        uint2 hh, ll;
        split4(r, hh, ll);
        *(uint2*)(g_a1h + (size_t)d * HC + ch) = hh;
        *(uint2*)(g_a1l + (size_t)d * HC + ch) = ll;
    }
}

// ---------------- layer 2 single-pass agg + log_softmax ----------------------
__global__ void agg2_final(const float* __restrict__ b2, float* __restrict__ out) {
    int n = blockIdx.x * 8 + (threadIdx.x >> 5);
    if (n >= Nn) return;
    int lane = threadIdx.x & 31;
    int start = g_rowptr[n], end = g_rowptr[n + 1];
    float ald = g_ald2[n];

    float den = 0.f, acc0 = 0.f, acc1 = 0.f;
    for (int base = start; base < end; base += 32) {
        int i = base + lane;
        int s = 0; float e = 0.f;
        if (i < end) {
            s = g_srcl[i];
            e = __expf(lrelu(g_als2[s] + ald));
        }
        den += e;
        int cnt = min(32, end - base);
        for (int j = 0; j < cnt; j++) {
            int   sj = __shfl_sync(0xffffffffu, s, j);
            float ej = __shfl_sync(0xffffffffu, e, j);
            acc0 = fmaf(ej, g_h2[sj * OC + lane], acc0);
            if (lane < 8) acc1 = fmaf(ej, g_h2[sj * OC + 32 + lane], acc1);
        }
    }
    #pragma unroll
    for (int off = 16; off; off >>= 1)
        den += __shfl_xor_sync(0xffffffffu, den, off);
    float rden = 1.f / (den + 1e-16f);

    float v0 = acc0 * rden + b2[lane];
    float v1 = (lane < 8) ? (acc1 * rden + b2[32 + lane]) : -3.402823466e38f;
    float mx = fmaxf(v0, v1);
    #pragma unroll
    for (int off = 16; off; off >>= 1)
        mx = fmaxf(mx, __shfl_xor_sync(0xffffffffu, mx, off));
    float se = expf(v0 - mx) + ((lane < 8) ? expf(v1 - mx) : 0.f);
    #pragma unroll
    for (int off = 16; off; off >>= 1)
        se += __shfl_xor_sync(0xffffffffu, se, off);
    float lse = mx + logf(se);
    out[n * OC + lane] = v0 - lse;
    if (lane < 8) out[n * OC + 32 + lane] = v1 - lse;
}

// ---------------- launch -----------------------------------------------------
extern "C" void kernel_launch(void* const* d_in, const int* in_sizes, int n_in,
                              void* d_out, int out_size) {
    const float* x      = (const float*)d_in[0];
    const int*   ei     = (const int*)d_in[1];
    const float* W1     = (const float*)d_in[2];
    const float* a_src1 = (const float*)d_in[3];
    const float* a_dst1 = (const float*)d_in[4];
    const float* b1     = (const float*)d_in[5];
    const float* W2     = (const float*)d_in[6];
    const float* a_src2 = (const float*)d_in[7];
    const float* a_dst2 = (const float*)d_in[8];
    const float* b2     = (const float*)d_in[9];
    float* out = (float*)d_out;

    cudaFuncSetAttribute(gemm1_mma, cudaFuncAttributeMaxDynamicSharedMemorySize, G1_SMEM);
    cudaFuncSetAttribute(gemm2_mma, cudaFuncAttributeMaxDynamicSharedMemorySize, G2_SMEM);

    convert_w<<<(INC * HC + 64 * INC + 255) / 256, 256>>>(W1, W2);
    gemm1_mma<<<MTILES * 2 + HBLK, 512, G1_SMEM>>>(x, ei, a_src1, a_dst1);
    scan_part<<<NB, 256>>>();
    scan_add2<<<NB, 256>>>();
    fill_kernel<<<(Ee / 4 + Nn + 255) / 256, 256>>>(ei);
    agg1_kernel<<<Nn, 256>>>(b1);
    gemm2_mma<<<MTILES, 512, G2_SMEM>>>(a_src2, a_dst2);
    agg2_final<<<(Nn + 7) / 8, 256>>>(b2, out);
}

// round 12
// speedup vs baseline: 1.6563x; 1.1066x over previous
#include <cuda_runtime.h>
#include <cuda_bf16.h>
#include <cstdint>

#define Nn 50000
#define Ee 800000
#define ET (Ee + Nn)
#define INC 256
#define HC 256
#define NH 4
#define OC 40
#define NB ((Nn + 255) / 256)

#define MT 128
#define MTILES ((Nn + MT - 1) / MT)
#define PADN (MTILES * MT)
#define HBLK 391

// ---------------- scratch ----------------------------------------------------
__device__ __align__(16) __nv_bfloat16 g_h1b[(size_t)Nn * HC];   // bf16 messages
__device__ float g_als1[Nn * NH];
__device__ float g_ald1[Nn * NH];
__device__ float g_h2[Nn * OC];
__device__ float g_als2[Nn];
__device__ float g_ald2[Nn];
__device__ int g_counts[Nn];
__device__ int g_fill[Nn];
__device__ int g_rowptr[Nn + 1];
__device__ int g_srcl[ET];
__device__ int g_bsum[NB];
__device__ __align__(16) __nv_bfloat16 g_w1h[INC * HC];
__device__ __align__(16) __nv_bfloat16 g_w1l[INC * HC];
__device__ __align__(16) __nv_bfloat16 g_w2h[64 * INC];
__device__ __align__(16) __nv_bfloat16 g_w2l[64 * INC];
__device__ __align__(16) __nv_bfloat16 g_a1h[(size_t)PADN * HC];

// ---------------- helpers ----------------------------------------------------
__device__ __forceinline__ float lrelu(float v) { return (v > 0.f) ? v : 0.2f * v; }
__device__ __forceinline__ uint32_t pack2(__nv_bfloat16 a, __nv_bfloat16 b) {
    __nv_bfloat162 t; t.x = a; t.y = b;
    return *reinterpret_cast<uint32_t*>(&t);
}
__device__ __forceinline__ uint2 tobf4(float4 v) {
    uint2 r;
    r.x = pack2(__float2bfloat16(v.x), __float2bfloat16(v.y));
    r.y = pack2(__float2bfloat16(v.z), __float2bfloat16(v.w));
    return r;
}
__device__ __forceinline__ uint32_t smem_u32(const void* p) {
    uint32_t a;
    asm("{ .reg .u64 t; cvta.to.shared.u64 t, %1; cvt.u32.u64 %0, t; }" : "=r"(a) : "l"(p));
    return a;
}
__device__ __forceinline__ void cp16(uint32_t dst, const void* src) {
    asm volatile("cp.async.ca.shared.global [%0], [%1], 16;" :: "r"(dst), "l"(src));
}
#define CP_COMMIT() asm volatile("cp.async.commit_group;" ::: "memory")
#define CP_WAIT0()  asm volatile("cp.async.wait_group 0;" ::: "memory")

// ---------------- convert_w + init (fused) -------------------------------------
__global__ void convert_w(const float* __restrict__ W1, const float* __restrict__ W2) {
    int t = blockIdx.x * blockDim.x + threadIdx.x;
    if (t < INC * HC) {
        int k = t >> 8, n = t & 255;
        float v = W1[t];
        __nv_bfloat16 h = __float2bfloat16(v);
        g_w1h[n * INC + k] = h;
        g_w1l[n * INC + k] = __float2bfloat16(v - __bfloat162float(h));
    } else if (t < INC * HC + 64 * INC) {
        int u = t - INC * HC;
        int n = u >> 8, k = u & 255;
        float v = (n < OC) ? W2[k * OC + n] : 0.f;
        __nv_bfloat16 h = __float2bfloat16(v);
        g_w2h[n * INC + k] = h;
        g_w2l[n * INC + k] = __float2bfloat16(v - __bfloat162float(h));
    }
    if (t < Nn) { g_counts[t] = 1; g_fill[t] = 0; }
}

// ---------------- scan (2 kernels) ---------------------------------------------
__device__ __forceinline__ int block_incl_scan(int v, int* ws) {
    int lane = threadIdx.x & 31, warp = threadIdx.x >> 5;
    #pragma unroll
    for (int o = 1; o < 32; o <<= 1) {
        int u = __shfl_up_sync(0xffffffffu, v, o);
        if (lane >= o) v += u;
    }
    if (lane == 31) ws[warp] = v;
    __syncthreads();
    if (warp == 0 && lane < 8) {
        int w = ws[lane];
        #pragma unroll
        for (int o = 1; o < 8; o <<= 1) {
            int u = __shfl_up_sync(0xffu, w, o);
            if (lane >= o) w += u;
        }
        ws[lane] = w;
    }
    __syncthreads();
    if (warp > 0) v += ws[warp - 1];
    return v;
}
__global__ void scan_part() {
    __shared__ int ws[8];
    int idx = blockIdx.x * 256 + threadIdx.x;
    int v = (idx < Nn) ? g_counts[idx] : 0;
    int incl = block_incl_scan(v, ws);
    if (idx < Nn) g_rowptr[idx + 1] = incl;
    if (threadIdx.x == 255) g_bsum[blockIdx.x] = incl;
}
__global__ void scan_add2() {
    __shared__ int ws[8];
    int j = blockIdx.x;
    int tid = threadIdx.x;
    int lane = tid & 31, warp = tid >> 5;
    int v = (tid < j) ? g_bsum[tid] : 0;
    #pragma unroll
    for (int o = 16; o; o >>= 1) v += __shfl_down_sync(0xffffffffu, v, o);
    if (lane == 0) ws[warp] = v;
    __syncthreads();
    if (warp == 0) {
        int w = (lane < 8) ? ws[lane] : 0;
        #pragma unroll
        for (int o = 4; o; o >>= 1) w += __shfl_down_sync(0xffffffffu, w, o);
        if (lane == 0) ws[0] = w;
    }
    __syncthreads();
    int offset = ws[0];
    int idx = j * 256 + tid;
    if (idx < Nn) g_rowptr[idx + 1] += offset;
    if (j == 0 && tid == 0) g_rowptr[0] = 0;
}
__global__ void fill_kernel(const int* __restrict__ ei) {
    const int Q = Ee / 4;
    int i = blockIdx.x * blockDim.x + threadIdx.x;
    if (i < Q) {
        int4 s = ((const int4*)ei)[i];
        int4 d = ((const int4*)(ei + Ee))[i];
        int p;
        p = g_rowptr[d.x] + atomicAdd(&g_fill[d.x], 1); g_srcl[p] = s.x;
        p = g_rowptr[d.y] + atomicAdd(&g_fill[d.y], 1); g_srcl[p] = s.y;
        p = g_rowptr[d.z] + atomicAdd(&g_fill[d.z], 1); g_srcl[p] = s.z;
        p = g_rowptr[d.w] + atomicAdd(&g_fill[d.w], 1); g_srcl[p] = s.w;
    } else {
        int n = i - Q;
        if (n < Nn) {
            int p = g_rowptr[n] + atomicAdd(&g_fill[n], 1);
            g_srcl[p] = n;
        }
    }
}

// ---------------- GEMM common ---------------------------------------------------
#define LDW 36
#define LDB 144
#define ATILE (128 * LDB)

__device__ __forceinline__ void mma_bf16(float* c, const uint32_t* a, const uint32_t* b) {
    asm volatile(
        "mma.sync.aligned.m16n8k16.row.col.f32.bf16.bf16.f32 "
        "{%0,%1,%2,%3}, {%4,%5,%6,%7}, {%8,%9}, {%0,%1,%2,%3};"
        : "+f"(c[0]), "+f"(c[1]), "+f"(c[2]), "+f"(c[3])
        : "r"(a[0]), "r"(a[1]), "r"(a[2]), "r"(a[3]), "r"(b[0]), "r"(b[1]));
}

// ---------------- GEMM1 (+ hist): h1b = bf16(x @ W1), 2-term split -------------
// smem per buf: [Ah][Bh][Bl]
#define G1_BUF (3 * ATILE)
#define G1_SMEM (2 * G1_BUF)     // 110592

__global__ void __launch_bounds__(512, 1)
gemm1_mma(const float* __restrict__ X, const int* __restrict__ ei,
          const float* __restrict__ a_src, const float* __restrict__ a_dst) {
    if (blockIdx.x >= MTILES * 2) {
        int i = (blockIdx.x - MTILES * 2) * 512 + threadIdx.x;
        if (i < Ee / 4) {
            int4 d = ((const int4*)(ei + Ee))[i];
            atomicAdd(&g_counts[d.x], 1);
            atomicAdd(&g_counts[d.y], 1);
            atomicAdd(&g_counts[d.z], 1);
            atomicAdd(&g_counts[d.w], 1);
        }
        return;
    }

    extern __shared__ char smem[];
    __shared__ float sAs[128], sAd[128];
    __shared__ float red[4][2][2][32];

    const int tid = threadIdx.x;
    const int wid = tid >> 5;
    const int lane = tid & 31;
    const int wm = wid >> 2;
    const int wn = wid & 3;
    const int g = lane >> 2;
    const int t = lane & 3;
    const int hl = wn >> 1;

    const int bm = (blockIdx.x >> 1) * MT;
    const int bn = (blockIdx.x & 1) * 128;

    const uint32_t sb = smem_u32(smem);

    if (tid < 128) { sAs[tid] = a_src[bn + tid]; sAd[tid] = a_dst[bn + tid]; }
    ((float*)red)[tid] = 0.f;

    float acc[2][4][4] = {};
    float4 aregs[4];

    auto loadA = [&](int c) {
        #pragma unroll
        for (int i = 0; i < 4; i++) {
            int idx = i * 512 + tid;
            int row = idx >> 4;
            int col4 = (idx & 15) * 4;
            int grow = bm + row;
            aregs[i] = (grow < Nn)
                ? *(const float4*)(X + (size_t)grow * INC + c * 64 + col4)
                : make_float4(0.f, 0.f, 0.f, 0.f);
        }
    };
    auto storeA = [&](int buf) {
        char* sAh = smem + buf * G1_BUF;
        #pragma unroll
        for (int i = 0; i < 4; i++) {
            int idx = i * 512 + tid;
            int row = idx >> 4;
            int col4 = (idx & 15) * 4;
            int so = row * LDB + col4 * 2;
            *(uint2*)(sAh + so) = tobf4(aregs[i]);
        }
    };
    auto cpB = [&](int c, int buf) {
        uint32_t dBh = sb + buf * G1_BUF + ATILE;
        uint32_t dBl = dBh + ATILE;
        #pragma unroll
        for (int i = 0; i < 2; i++) {
            int idx = i * 512 + tid;
            int row = idx >> 3;
            int col8 = (idx & 7) * 8;
            size_t gb = (size_t)(bn + row) * INC + c * 64 + col8;
            uint32_t so = row * LDB + col8 * 2;
            cp16(dBh + so, g_w1h + gb);
            cp16(dBl + so, g_w1l + gb);
        }
    };
    auto compute = [&](int buf) {
        const uint32_t* Ahw = (const uint32_t*)(smem + buf * G1_BUF);
        const uint32_t* Bhw = (const uint32_t*)(smem + buf * G1_BUF + ATILE);
        const uint32_t* Blw = (const uint32_t*)(smem + buf * G1_BUF + 2 * ATILE);
        #pragma unroll
        for (int kk = 0; kk < 4; kk++) {
            const int kw = kk * 8;
            uint32_t bh[4][2], bl[4][2];
            #pragma unroll
            for (int nt = 0; nt < 4; nt++) {
                int w0 = (wn * 32 + nt * 8 + g) * LDW + kw + t;
                bh[nt][0] = Bhw[w0]; bh[nt][1] = Bhw[w0 + 4];
                bl[nt][0] = Blw[w0]; bl[nt][1] = Blw[w0 + 4];
            }
            #pragma unroll
            for (int mt = 0; mt < 2; mt++) {
                int w0 = (wm * 32 + mt * 16 + g) * LDW + kw + t;
                uint32_t ah[4];
                ah[0] = Ahw[w0]; ah[1] = Ahw[w0 + 8 * LDW];
                ah[2] = Ahw[w0 + 4]; ah[3] = Ahw[w0 + 8 * LDW + 4];
                #pragma unroll
                for (int nt = 0; nt < 4; nt++) {
                    mma_bf16(acc[mt][nt], ah, bh[nt]);
                    mma_bf16(acc[mt][nt], ah, bl[nt]);
                }
            }
        }
    };

    loadA(0); cpB(0, 0); CP_COMMIT(); storeA(0);
    CP_WAIT0(); __syncthreads();
    #pragma unroll
    for (int c = 0; c < 4; c++) {
        int buf = c & 1;
        if (c < 3) { loadA(c + 1); cpB(c + 1, buf ^ 1); CP_COMMIT(); }
        compute(buf);
        if (c < 3) { storeA(buf ^ 1); CP_WAIT0(); __syncthreads(); }
    }

    // ---- epilogue: bf16 h1 stores + attn dot-products ----
    #pragma unroll
    for (int mt = 0; mt < 2; mt++) {
        int row0 = bm + wm * 32 + mt * 16 + g;
        int row1 = row0 + 8;
        float s0 = 0.f, s1 = 0.f, d0 = 0.f, d1 = 0.f;
        #pragma unroll
        for (int nt = 0; nt < 4; nt++) {
            int lcol = wn * 32 + nt * 8 + 2 * t;
            int col = bn + lcol;
            float as0 = sAs[lcol], as1 = sAs[lcol + 1];
            float ad0 = sAd[lcol], ad1 = sAd[lcol + 1];
            s0 += acc[mt][nt][0] * as0 + acc[mt][nt][1] * as1;
            s1 += acc[mt][nt][2] * as0 + acc[mt][nt][3] * as1;
            d0 += acc[mt][nt][0] * ad0 + acc[mt][nt][1] * ad1;
            d1 += acc[mt][nt][2] * ad0 + acc[mt][nt][3] * ad1;
            if (row0 < Nn)
                *(uint32_t*)(g_h1b + (size_t)row0 * HC + col) =
                    pack2(__float2bfloat16(acc[mt][nt][0]), __float2bfloat16(acc[mt][nt][1]));
            if (row1 < Nn)
                *(uint32_t*)(g_h1b + (size_t)row1 * HC + col) =
                    pack2(__float2bfloat16(acc[mt][nt][2]), __float2bfloat16(acc[mt][nt][3]));
        }
        s0 += __shfl_down_sync(0xffffffffu, s0, 2); s0 += __shfl_down_sync(0xffffffffu, s0, 1);
        s1 += __shfl_down_sync(0xffffffffu, s1, 2); s1 += __shfl_down_sync(0xffffffffu, s1, 1);
        d0 += __shfl_down_sync(0xffffffffu, d0, 2); d0 += __shfl_down_sync(0xffffffffu, d0, 1);
        d1 += __shfl_down_sync(0xffffffffu, d1, 2); d1 += __shfl_down_sync(0xffffffffu, d1, 1);
        if (t == 0) {
            int r0 = mt * 16 + g, r1 = r0 + 8;
            atomicAdd(&red[wm][hl][0][r0], s0);
            atomicAdd(&red[wm][hl][0][r1], s1);
            atomicAdd(&red[wm][hl][1][r0], d0);
            atomicAdd(&red[wm][hl][1][r1], d1);
        }
    }
    __syncthreads();
    if (tid < 128) {
        int n = bm + tid;
        if (n < Nn) {
            int w = tid >> 5, r = tid & 31;
            #pragma unroll
            for (int h = 0; h < 2; h++) {
                int head = (bn >> 6) + h;
                g_als1[n * NH + head] = red[w][h][0][r];
                g_ald1[n * NH + head] = red[w][h][1][r];
            }
        }
    }
}

// ---------------- GEMM2: h2 = agg1 @ W2, 2-term split ---------------------------
#define BTILE2 (64 * LDB)
#define G2_BUF (ATILE + 2 * BTILE2)   // 36864
#define G2_SMEM (2 * G2_BUF)          // 73728

__global__ void __launch_bounds__(512, 1)
gemm2_mma(const float* __restrict__ a_src, const float* __restrict__ a_dst) {
    extern __shared__ char smem[];
    __shared__ float sAs[64], sAd[64];
    __shared__ float red2[2][128];

    const int tid = threadIdx.x;
    const int wid = tid >> 5;
    const int lane = tid & 31;
    const int wm = wid >> 1;
    const int wn = wid & 1;
    const int g = lane >> 2;
    const int t = lane & 3;

    const int bm = blockIdx.x * MT;
    const uint32_t sb = smem_u32(smem);

    if (tid < 64) { sAs[tid] = (tid < OC) ? a_src[tid] : 0.f;
                    sAd[tid] = (tid < OC) ? a_dst[tid] : 0.f; }
    if (tid < 256) ((float*)red2)[tid] = 0.f;

    float acc[4][4] = {};

    auto stage = [&](int c, int buf) {
        uint32_t dAh = sb + buf * G2_BUF;
        uint32_t dBh = dAh + ATILE;
        uint32_t dBl = dBh + BTILE2;
        #pragma unroll
        for (int i = 0; i < 2; i++) {
            int idx = i * 512 + tid;
            int row = idx >> 3;
            int col8 = (idx & 7) * 8;
            size_t ga = (size_t)(bm + row) * HC + c * 64 + col8;
            uint32_t so = row * LDB + col8 * 2;
            cp16(dAh + so, g_a1h + ga);
        }
        {
            int idx = tid;
            int row = idx >> 3;
            int col8 = (idx & 7) * 8;
            size_t gb = (size_t)row * INC + c * 64 + col8;
            uint32_t so = row * LDB + col8 * 2;
            cp16(dBh + so, g_w2h + gb);
            cp16(dBl + so, g_w2l + gb);
        }
    };
    auto compute = [&](int buf) {
        const uint32_t* Ahw = (const uint32_t*)(smem + buf * G2_BUF);
        const uint32_t* Bhw = (const uint32_t*)(smem + buf * G2_BUF + ATILE);
        const uint32_t* Blw = (const uint32_t*)(smem + buf * G2_BUF + ATILE + BTILE2);
        #pragma unroll
        for (int kk = 0; kk < 4; kk++) {
            const int kw = kk * 8;
            uint32_t bh[4][2], bl[4][2];
            #pragma unroll
            for (int nt = 0; nt < 4; nt++) {
                int w0 = (wn * 32 + nt * 8 + g) * LDW + kw + t;
                bh[nt][0] = Bhw[w0]; bh[nt][1] = Bhw[w0 + 4];
                bl[nt][0] = Blw[w0]; bl[nt][1] = Blw[w0 + 4];
            }
            {
                int w0 = (wm * 16 + g) * LDW + kw + t;
                uint32_t ah[4];
                ah[0] = Ahw[w0]; ah[1] = Ahw[w0 + 8 * LDW];
                ah[2] = Ahw[w0 + 4]; ah[3] = Ahw[w0 + 8 * LDW + 4];
                #pragma unroll
                for (int nt = 0; nt < 4; nt++) {
                    mma_bf16(acc[nt], ah, bh[nt]);
                    mma_bf16(acc[nt], ah, bl[nt]);
                }
            }
        }
    };

    stage(0, 0); CP_COMMIT();
    CP_WAIT0(); __syncthreads();
    #pragma unroll
    for (int c = 0; c < 4; c++) {
        int buf = c & 1;
        if (c < 3) { stage(c + 1, buf ^ 1); CP_COMMIT(); }
        compute(buf);
        if (c < 3) { CP_WAIT0(); __syncthreads(); }
    }

    {
        int row0 = bm + wm * 16 + g;
        int row1 = row0 + 8;
        float s0 = 0.f, s1 = 0.f, d0 = 0.f, d1 = 0.f;
        #pragma unroll
        for (int nt = 0; nt < 4; nt++) {
            int lcol = wn * 32 + nt * 8 + 2 * t;
            float as0 = sAs[lcol], as1 = sAs[lcol + 1];
            float ad0 = sAd[lcol], ad1 = sAd[lcol + 1];
            s0 += acc[nt][0] * as0 + acc[nt][1] * as1;
            s1 += acc[nt][2] * as0 + acc[nt][3] * as1;
            d0 += acc[nt][0] * ad0 + acc[nt][1] * ad1;
            d1 += acc[nt][2] * ad0 + acc[nt][3] * ad1;
            if (lcol < OC) {
                if (row0 < Nn)
                    *(float2*)(g_h2 + (size_t)row0 * OC + lcol) = make_float2(acc[nt][0], acc[nt][1]);
                if (row1 < Nn)
                    *(float2*)(g_h2 + (size_t)row1 * OC + lcol) = make_float2(acc[nt][2], acc[nt][3]);
            }
        }
        s0 += __shfl_down_sync(0xffffffffu, s0, 2); s0 += __shfl_down_sync(0xffffffffu, s0, 1);
        s1 += __shfl_down_sync(0xffffffffu, s1, 2); s1 += __shfl_down_sync(0xffffffffu, s1, 1);
        d0 += __shfl_down_sync(0xffffffffu, d0, 2); d0 += __shfl_down_sync(0xffffffffu, d0, 1);
        d1 += __shfl_down_sync(0xffffffffu, d1, 2); d1 += __shfl_down_sync(0xffffffffu, d1, 1);
        if (t == 0) {
            int r0 = wm * 16 + g, r1 = r0 + 8;
            atomicAdd(&red2[0][r0], s0);
            atomicAdd(&red2[0][r1], s1);
            atomicAdd(&red2[1][r0], d0);
            atomicAdd(&red2[1][r1], d1);
        }
    }
    __syncthreads();
    if (tid < 128) {
        int n = bm + tid;
        if (n < Nn) {
            g_als2[n] = red2[0][tid];
            g_ald2[n] = red2[1][tid];
        }
    }
}

// ---------------- layer 1: round-9 structure, bf16 uint2 gathers ---------------
__global__ __launch_bounds__(256) void agg1_kernel(const float* __restrict__ b1) {
    int d = blockIdx.x;
    int start = g_rowptr[d], end = g_rowptr[d + 1];
    int tid = threadIdx.x;
    __shared__ float sden[NH];
    __shared__ int ssrc[128];
    __shared__ float salpha[128 * NH];
    __shared__ float4 sacc[4 * 64];

    if (tid < NH) sden[tid] = 1e-16f;
    float4 aldv = *(const float4*)&g_ald1[d * NH];

    const int ch4 = tid & 63;
    const int slot = tid >> 6;
    const int head = ch4 >> 4;
    float4 acc = make_float4(0.f, 0.f, 0.f, 0.f);
    float p0 = 0.f, p1 = 0.f, p2 = 0.f, p3 = 0.f;

    for (int base = start; base < end; base += 128) {
        int cnt = min(128, end - base);
        __syncthreads();
        if (tid < cnt) {
            int s = g_srcl[base + tid];
            ssrc[tid] = s;
            float4 als = *(const float4*)&g_als1[s * NH];
            float e0 = __expf(lrelu(als.x + aldv.x));
            float e1 = __expf(lrelu(als.y + aldv.y));
            float e2 = __expf(lrelu(als.z + aldv.z));
            float e3 = __expf(lrelu(als.w + aldv.w));
            salpha[tid * 4 + 0] = e0; salpha[tid * 4 + 1] = e1;
            salpha[tid * 4 + 2] = e2; salpha[tid * 4 + 3] = e3;
            p0 += e0; p1 += e1; p2 += e2; p3 += e3;
        }
        __syncthreads();
        int j = slot;
        for (; j + 4 < cnt; j += 8) {
            float a0 = salpha[j * 4 + head];
            float a1 = salpha[(j + 4) * 4 + head];
            int s0 = ssrc[j], s1 = ssrc[j + 4];
            uint2 hv0 = *(const uint2*)(g_h1b + (size_t)s0 * HC + ch4 * 4);
            uint2 hv1 = *(const uint2*)(g_h1b + (size_t)s1 * HC + ch4 * 4);
            float2 f00 = __bfloat1622float2(*(const __nv_bfloat162*)&hv0.x);
            float2 f01 = __bfloat1622float2(*(const __nv_bfloat162*)&hv0.y);
            float2 f10 = __bfloat1622float2(*(const __nv_bfloat162*)&hv1.x);
            float2 f11 = __bfloat1622float2(*(const __nv_bfloat162*)&hv1.y);
            acc.x = fmaf(a0, f00.x, acc.x); acc.y = fmaf(a0, f00.y, acc.y);
            acc.z = fmaf(a0, f01.x, acc.z); acc.w = fmaf(a0, f01.y, acc.w);
            acc.x = fmaf(a1, f10.x, acc.x); acc.y = fmaf(a1, f10.y, acc.y);
            acc.z = fmaf(a1, f11.x, acc.z); acc.w = fmaf(a1, f11.y, acc.w);
        }
        for (; j < cnt; j += 4) {
            float a = salpha[j * 4 + head];
            int s = ssrc[j];
            uint2 hv = *(const uint2*)(g_h1b + (size_t)s * HC + ch4 * 4);
            float2 f0 = __bfloat1622float2(*(const __nv_bfloat162*)&hv.x);
            float2 f1 = __bfloat1622float2(*(const __nv_bfloat162*)&hv.y);
            acc.x = fmaf(a, f0.x, acc.x);
            acc.y = fmaf(a, f0.y, acc.y);
            acc.z = fmaf(a, f1.x, acc.z);
            acc.w = fmaf(a, f1.y, acc.w);
        }
    }
    #pragma unroll
    for (int off = 16; off; off >>= 1) {
        p0 += __shfl_down_sync(0xffffffffu, p0, off);
        p1 += __shfl_down_sync(0xffffffffu, p1, off);
        p2 += __shfl_down_sync(0xffffffffu, p2, off);
        p3 += __shfl_down_sync(0xffffffffu, p3, off);
    }
    if ((tid & 31) == 0) {
        atomicAdd(&sden[0], p0);
        atomicAdd(&sden[1], p1);
        atomicAdd(&sden[2], p2);
        atomicAdd(&sden[3], p3);
    }
    sacc[slot * 64 + ch4] = acc;
    __syncthreads();
    if (tid < 64) {
        float4 a0 = sacc[tid], a1 = sacc[64 + tid], a2 = sacc[128 + tid], a3 = sacc[192 + tid];
        float rd = 1.f / sden[tid >> 4];
        int ch = tid * 4;
        float4 bb = *(const float4*)(b1 + ch);
        float4 r;
        r.x = fmaxf((a0.x + a1.x + a2.x + a3.x) * rd + bb.x, 0.f);
        r.y = fmaxf((a0.y + a1.y + a2.y + a3.y) * rd + bb.y, 0.f);
        r.z = fmaxf((a0.z + a1.z + a2.z + a3.z) * rd + bb.z, 0.f);
        r.w = fmaxf((a0.w + a1.w + a2.w + a3.w) * rd + bb.w, 0.f);
        *(uint2*)(g_a1h + (size_t)d * HC + ch) = tobf4(r);
    }
}

// ---------------- layer 2 single-pass agg + log_softmax ----------------------
__global__ void agg2_final(const float* __restrict__ b2, float* __restrict__ out) {
    int n = blockIdx.x * 8 + (threadIdx.x >> 5);
    if (n >= Nn) return;
    int lane = threadIdx.x & 31;
    int start = g_rowptr[n], end = g_rowptr[n + 1];
    float ald = g_ald2[n];

    float den = 0.f, acc0 = 0.f, acc1 = 0.f;
    for (int base = start; base < end; base += 32) {
        int i = base + lane;
        int s = 0; float e = 0.f;
        if (i < end) {
            s = g_srcl[i];
            e = __expf(lrelu(g_als2[s] + ald));
        }
        den += e;
        int cnt = min(32, end - base);
        for (int j = 0; j < cnt; j++) {
            int   sj = __shfl_sync(0xffffffffu, s, j);
            float ej = __shfl_sync(0xffffffffu, e, j);
            acc0 = fmaf(ej, g_h2[sj * OC + lane], acc0);
            if (lane < 8) acc1 = fmaf(ej, g_h2[sj * OC + 32 + lane], acc1);
        }
    }
    #pragma unroll
    for (int off = 16; off; off >>= 1)
        den += __shfl_xor_sync(0xffffffffu, den, off);
    float rden = 1.f / (den + 1e-16f);

    float v0 = acc0 * rden + b2[lane];
    float v1 = (lane < 8) ? (acc1 * rden + b2[32 + lane]) : -3.402823466e38f;
    float mx = fmaxf(v0, v1);
    #pragma unroll
    for (int off = 16; off; off >>= 1)
        mx = fmaxf(mx, __shfl_xor_sync(0xffffffffu, mx, off));
    float se = expf(v0 - mx) + ((lane < 8) ? expf(v1 - mx) : 0.f);
    #pragma unroll
    for (int off = 16; off; off >>= 1)
        se += __shfl_xor_sync(0xffffffffu, se, off);
    float lse = mx + logf(se);
    out[n * OC + lane] = v0 - lse;
    if (lane < 8) out[n * OC + 32 + lane] = v1 - lse;
}

// ---------------- launch -----------------------------------------------------
extern "C" void kernel_launch(void* const* d_in, const int* in_sizes, int n_in,
                              void* d_out, int out_size) {
    const float* x      = (const float*)d_in[0];
    const int*   ei     = (const int*)d_in[1];
    const float* W1     = (const float*)d_in[2];
    const float* a_src1 = (const float*)d_in[3];
    const float* a_dst1 = (const float*)d_in[4];
    const float* b1     = (const float*)d_in[5];
    const float* W2     = (const float*)d_in[6];
    const float* a_src2 = (const float*)d_in[7];
    const float* a_dst2 = (const float*)d_in[8];
    const float* b2     = (const float*)d_in[9];
    float* out = (float*)d_out;

    cudaFuncSetAttribute(gemm1_mma, cudaFuncAttributeMaxDynamicSharedMemorySize, G1_SMEM);
    cudaFuncSetAttribute(gemm2_mma, cudaFuncAttributeMaxDynamicSharedMemorySize, G2_SMEM);

    convert_w<<<(INC * HC + 64 * INC + 255) / 256, 256>>>(W1, W2);
    gemm1_mma<<<MTILES * 2 + HBLK, 512, G1_SMEM>>>(x, ei, a_src1, a_dst1);
    scan_part<<<NB, 256>>>();
    scan_add2<<<NB, 256>>>();
    fill_kernel<<<(Ee / 4 + Nn + 255) / 256, 256>>>(ei);
    agg1_kernel<<<Nn, 256>>>(b1);
    gemm2_mma<<<MTILES, 512, G2_SMEM>>>(a_src2, a_dst2);
    agg2_final<<<(Nn + 7) / 8, 256>>>(b2, out);
}

// round 13
// speedup vs baseline: 1.7905x; 1.0810x over previous
#include <cuda_runtime.h>
#include <cuda_bf16.h>
#include <cstdint>

#define Nn 50000
#define Ee 800000
#define ET (Ee + Nn)
#define INC 256
#define HC 256
#define NH 4
#define OC 40
#define NB ((Nn + 255) / 256)

#define MT 128
#define MTILES ((Nn + MT - 1) / MT)
#define PADN (MTILES * MT)
#define HBLK 391

// ---------------- scratch ----------------------------------------------------
__device__ __align__(16) __nv_bfloat16 g_h1b[(size_t)Nn * HC];   // bf16 messages
__device__ float g_als1[Nn * NH];
__device__ float g_ald1[Nn * NH];
__device__ float g_h2[Nn * OC];
__device__ float g_als2[Nn];
__device__ float g_ald2[Nn];
__device__ int g_counts[Nn];
__device__ int g_fill[Nn];
__device__ int g_rowptr[Nn + 1];
__device__ int g_srcl[ET];
__device__ int g_bsum[NB];
__device__ __align__(16) __nv_bfloat16 g_w1h[INC * HC];
__device__ __align__(16) __nv_bfloat16 g_w2h[64 * INC];
__device__ __align__(16) __nv_bfloat16 g_a1h[(size_t)PADN * HC];

// ---------------- helpers ----------------------------------------------------
__device__ __forceinline__ float lrelu(float v) { return (v > 0.f) ? v : 0.2f * v; }
__device__ __forceinline__ uint32_t pack2(__nv_bfloat16 a, __nv_bfloat16 b) {
    __nv_bfloat162 t; t.x = a; t.y = b;
    return *reinterpret_cast<uint32_t*>(&t);
}
__device__ __forceinline__ uint2 tobf4(float4 v) {
    uint2 r;
    r.x = pack2(__float2bfloat16(v.x), __float2bfloat16(v.y));
    r.y = pack2(__float2bfloat16(v.z), __float2bfloat16(v.w));
    return r;
}
__device__ __forceinline__ uint32_t smem_u32(const void* p) {
    uint32_t a;
    asm("{ .reg .u64 t; cvta.to.shared.u64 t, %1; cvt.u32.u64 %0, t; }" : "=r"(a) : "l"(p));
    return a;
}
__device__ __forceinline__ void cp16(uint32_t dst, const void* src) {
    asm volatile("cp.async.ca.shared.global [%0], [%1], 16;" :: "r"(dst), "l"(src));
}
#define CP_COMMIT() asm volatile("cp.async.commit_group;" ::: "memory")
#define CP_WAIT0()  asm volatile("cp.async.wait_group 0;" ::: "memory")

// ---------------- convert_w + init (fused) -------------------------------------
__global__ void convert_w(const float* __restrict__ W1, const float* __restrict__ W2) {
    int t = blockIdx.x * blockDim.x + threadIdx.x;
    if (t < INC * HC) {
        int k = t >> 8, n = t & 255;
        g_w1h[n * INC + k] = __float2bfloat16(W1[t]);
    } else if (t < INC * HC + 64 * INC) {
        int u = t - INC * HC;
        int n = u >> 8, k = u & 255;
        float v = (n < OC) ? W2[k * OC + n] : 0.f;
        g_w2h[n * INC + k] = __float2bfloat16(v);
    }
    if (t < Nn) { g_counts[t] = 1; g_fill[t] = 0; }
}

// ---------------- scan (2 kernels) ---------------------------------------------
__device__ __forceinline__ int block_incl_scan(int v, int* ws) {
    int lane = threadIdx.x & 31, warp = threadIdx.x >> 5;
    #pragma unroll
    for (int o = 1; o < 32; o <<= 1) {
        int u = __shfl_up_sync(0xffffffffu, v, o);
        if (lane >= o) v += u;
    }
    if (lane == 31) ws[warp] = v;
    __syncthreads();
    if (warp == 0 && lane < 8) {
        int w = ws[lane];
        #pragma unroll
        for (int o = 1; o < 8; o <<= 1) {
            int u = __shfl_up_sync(0xffu, w, o);
            if (lane >= o) w += u;
        }
        ws[lane] = w;
    }
    __syncthreads();
    if (warp > 0) v += ws[warp - 1];
    return v;
}
__global__ void scan_part() {
    __shared__ int ws[8];
    int idx = blockIdx.x * 256 + threadIdx.x;
    int v = (idx < Nn) ? g_counts[idx] : 0;
    int incl = block_incl_scan(v, ws);
    if (idx < Nn) g_rowptr[idx + 1] = incl;
    if (threadIdx.x == 255) g_bsum[blockIdx.x] = incl;
}
__global__ void scan_add2() {
    __shared__ int ws[8];
    int j = blockIdx.x;
    int tid = threadIdx.x;
    int lane = tid & 31, warp = tid >> 5;
    int v = (tid < j) ? g_bsum[tid] : 0;
    #pragma unroll
    for (int o = 16; o; o >>= 1) v += __shfl_down_sync(0xffffffffu, v, o);
    if (lane == 0) ws[warp] = v;
    __syncthreads();
    if (warp == 0) {
        int w = (lane < 8) ? ws[lane] : 0;
        #pragma unroll
        for (int o = 4; o; o >>= 1) w += __shfl_down_sync(0xffffffffu, w, o);
        if (lane == 0) ws[0] = w;
    }
    __syncthreads();
    int offset = ws[0];
    int idx = j * 256 + tid;
    if (idx < Nn) g_rowptr[idx + 1] += offset;
    if (j == 0 && tid == 0) g_rowptr[0] = 0;
}
__global__ void fill_kernel(const int* __restrict__ ei) {
    const int Q = Ee / 4;
    int i = blockIdx.x * blockDim.x + threadIdx.x;
    if (i < Q) {
        int4 s = ((const int4*)ei)[i];
        int4 d = ((const int4*)(ei + Ee))[i];
        int p;
        p = g_rowptr[d.x] + atomicAdd(&g_fill[d.x], 1); g_srcl[p] = s.x;
        p = g_rowptr[d.y] + atomicAdd(&g_fill[d.y], 1); g_srcl[p] = s.y;
        p = g_rowptr[d.z] + atomicAdd(&g_fill[d.z], 1); g_srcl[p] = s.z;
        p = g_rowptr[d.w] + atomicAdd(&g_fill[d.w], 1); g_srcl[p] = s.w;
    } else {
        int n = i - Q;
        if (n < Nn) {
            int p = g_rowptr[n] + atomicAdd(&g_fill[n], 1);
            g_srcl[p] = n;
        }
    }
}

// ---------------- GEMM common ---------------------------------------------------
#define LDW 36
#define LDB 144
#define ATILE (128 * LDB)

__device__ __forceinline__ void mma_bf16(float* c, const uint32_t* a, const uint32_t* b) {
    asm volatile(
        "mma.sync.aligned.m16n8k16.row.col.f32.bf16.bf16.f32 "
        "{%0,%1,%2,%3}, {%4,%5,%6,%7}, {%8,%9}, {%0,%1,%2,%3};"
        : "+f"(c[0]), "+f"(c[1]), "+f"(c[2]), "+f"(c[3])
        : "r"(a[0]), "r"(a[1]), "r"(a[2]), "r"(a[3]), "r"(b[0]), "r"(b[1]));
}

// ---------------- GEMM1 (+ hist): h1b = bf16(x @ W1), pure bf16 ----------------
// smem per buf: [Ah][Bh]
#define G1_BUF (2 * ATILE)
#define G1_SMEM (2 * G1_BUF)     // 73728

__global__ void __launch_bounds__(512, 1)
gemm1_mma(const float* __restrict__ X, const int* __restrict__ ei,
          const float* __restrict__ a_src, const float* __restrict__ a_dst) {
    if (blockIdx.x >= MTILES * 2) {
        int i = (blockIdx.x - MTILES * 2) * 512 + threadIdx.x;
        if (i < Ee / 4) {
            int4 d = ((const int4*)(ei + Ee))[i];
            atomicAdd(&g_counts[d.x], 1);
            atomicAdd(&g_counts[d.y], 1);
            atomicAdd(&g_counts[d.z], 1);
            atomicAdd(&g_counts[d.w], 1);
        }
        return;
    }

    extern __shared__ char smem[];
    __shared__ float sAs[128], sAd[128];
    __shared__ float red[4][2][2][32];

    const int tid = threadIdx.x;
    const int wid = tid >> 5;
    const int lane = tid & 31;
    const int wm = wid >> 2;
    const int wn = wid & 3;
    const int g = lane >> 2;
    const int t = lane & 3;
    const int hl = wn >> 1;

    const int bm = (blockIdx.x >> 1) * MT;
    const int bn = (blockIdx.x & 1) * 128;

    const uint32_t sb = smem_u32(smem);

    if (tid < 128) { sAs[tid] = a_src[bn + tid]; sAd[tid] = a_dst[bn + tid]; }
    ((float*)red)[tid] = 0.f;

    float acc[2][4][4] = {};
    float4 aregs[4];

    auto loadA = [&](int c) {
        #pragma unroll
        for (int i = 0; i < 4; i++) {
            int idx = i * 512 + tid;
            int row = idx >> 4;
            int col4 = (idx & 15) * 4;
            int grow = bm + row;
            aregs[i] = (grow < Nn)
                ? *(const float4*)(X + (size_t)grow * INC + c * 64 + col4)
                : make_float4(0.f, 0.f, 0.f, 0.f);
        }
    };
    auto storeA = [&](int buf) {
        char* sAh = smem + buf * G1_BUF;
        #pragma unroll
        for (int i = 0; i < 4; i++) {
            int idx = i * 512 + tid;
            int row = idx >> 4;
            int col4 = (idx & 15) * 4;
            int so = row * LDB + col4 * 2;
            *(uint2*)(sAh + so) = tobf4(aregs[i]);
        }
    };
    auto cpB = [&](int c, int buf) {
        uint32_t dBh = sb + buf * G1_BUF + ATILE;
        #pragma unroll
        for (int i = 0; i < 2; i++) {
            int idx = i * 512 + tid;
            int row = idx >> 3;
            int col8 = (idx & 7) * 8;
            size_t gb = (size_t)(bn + row) * INC + c * 64 + col8;
            uint32_t so = row * LDB + col8 * 2;
            cp16(dBh + so, g_w1h + gb);
        }
    };
    auto compute = [&](int buf) {
        const uint32_t* Ahw = (const uint32_t*)(smem + buf * G1_BUF);
        const uint32_t* Bhw = (const uint32_t*)(smem + buf * G1_BUF + ATILE);
        #pragma unroll
        for (int kk = 0; kk < 4; kk++) {
            const int kw = kk * 8;
            uint32_t bh[4][2];
            #pragma unroll
            for (int nt = 0; nt < 4; nt++) {
                int w0 = (wn * 32 + nt * 8 + g) * LDW + kw + t;
                bh[nt][0] = Bhw[w0]; bh[nt][1] = Bhw[w0 + 4];
            }
            #pragma unroll
            for (int mt = 0; mt < 2; mt++) {
                int w0 = (wm * 32 + mt * 16 + g) * LDW + kw + t;
                uint32_t ah[4];
                ah[0] = Ahw[w0]; ah[1] = Ahw[w0 + 8 * LDW];
                ah[2] = Ahw[w0 + 4]; ah[3] = Ahw[w0 + 8 * LDW + 4];
                #pragma unroll
                for (int nt = 0; nt < 4; nt++)
                    mma_bf16(acc[mt][nt], ah, bh[nt]);
            }
        }
    };

    loadA(0); cpB(0, 0); CP_COMMIT(); storeA(0);
    CP_WAIT0(); __syncthreads();
    #pragma unroll
    for (int c = 0; c < 4; c++) {
        int buf = c & 1;
        if (c < 3) { loadA(c + 1); cpB(c + 1, buf ^ 1); CP_COMMIT(); }
        compute(buf);
        if (c < 3) { storeA(buf ^ 1); CP_WAIT0(); __syncthreads(); }
    }

    // ---- epilogue: bf16 h1 stores + attn dot-products ----
    #pragma unroll
    for (int mt = 0; mt < 2; mt++) {
        int row0 = bm + wm * 32 + mt * 16 + g;
        int row1 = row0 + 8;
        float s0 = 0.f, s1 = 0.f, d0 = 0.f, d1 = 0.f;
        #pragma unroll
        for (int nt = 0; nt < 4; nt++) {
            int lcol = wn * 32 + nt * 8 + 2 * t;
            int col = bn + lcol;
            float as0 = sAs[lcol], as1 = sAs[lcol + 1];
            float ad0 = sAd[lcol], ad1 = sAd[lcol + 1];
            s0 += acc[mt][nt][0] * as0 + acc[mt][nt][1] * as1;
            s1 += acc[mt][nt][2] * as0 + acc[mt][nt][3] * as1;
            d0 += acc[mt][nt][0] * ad0 + acc[mt][nt][1] * ad1;
            d1 += acc[mt][nt][2] * ad0 + acc[mt][nt][3] * ad1;
            if (row0 < Nn)
                *(uint32_t*)(g_h1b + (size_t)row0 * HC + col) =
                    pack2(__float2bfloat16(acc[mt][nt][0]), __float2bfloat16(acc[mt][nt][1]));
            if (row1 < Nn)
                *(uint32_t*)(g_h1b + (size_t)row1 * HC + col) =
                    pack2(__float2bfloat16(acc[mt][nt][2]), __float2bfloat16(acc[mt][nt][3]));
        }
        s0 += __shfl_down_sync(0xffffffffu, s0, 2); s0 += __shfl_down_sync(0xffffffffu, s0, 1);
        s1 += __shfl_down_sync(0xffffffffu, s1, 2); s1 += __shfl_down_sync(0xffffffffu, s1, 1);
        d0 += __shfl_down_sync(0xffffffffu, d0, 2); d0 += __shfl_down_sync(0xffffffffu, d0, 1);
        d1 += __shfl_down_sync(0xffffffffu, d1, 2); d1 += __shfl_down_sync(0xffffffffu, d1, 1);
        if (t == 0) {
            int r0 = mt * 16 + g, r1 = r0 + 8;
            atomicAdd(&red[wm][hl][0][r0], s0);
            atomicAdd(&red[wm][hl][0][r1], s1);
            atomicAdd(&red[wm][hl][1][r0], d0);
            atomicAdd(&red[wm][hl][1][r1], d1);
        }
    }
    __syncthreads();
    if (tid < 128) {
        int n = bm + tid;
        if (n < Nn) {
            int w = tid >> 5, r = tid & 31;
            #pragma unroll
            for (int h = 0; h < 2; h++) {
                int head = (bn >> 6) + h;
                g_als1[n * NH + head] = red[w][h][0][r];
                g_ald1[n * NH + head] = red[w][h][1][r];
            }
        }
    }
}

// ---------------- GEMM2: h2 = agg1 @ W2, pure bf16 ------------------------------
#define BTILE2 (64 * LDB)
#define G2_BUF (ATILE + BTILE2)       // 27648
#define G2_SMEM (2 * G2_BUF)          // 55296

__global__ void __launch_bounds__(512, 1)
gemm2_mma(const float* __restrict__ a_src, const float* __restrict__ a_dst) {
    extern __shared__ char smem[];
    __shared__ float sAs[64], sAd[64];
    __shared__ float red2[2][128];

    const int tid = threadIdx.x;
    const int wid = tid >> 5;
    const int lane = tid & 31;
    const int wm = wid >> 1;
    const int wn = wid & 1;
    const int g = lane >> 2;
    const int t = lane & 3;

    const int bm = blockIdx.x * MT;
    const uint32_t sb = smem_u32(smem);

    if (tid < 64) { sAs[tid] = (tid < OC) ? a_src[tid] : 0.f;
                    sAd[tid] = (tid < OC) ? a_dst[tid] : 0.f; }
    if (tid < 256) ((float*)red2)[tid] = 0.f;

    float acc[4][4] = {};

    auto stage = [&](int c, int buf) {
        uint32_t dAh = sb + buf * G2_BUF;
        uint32_t dBh = dAh + ATILE;
        #pragma unroll
        for (int i = 0; i < 2; i++) {
            int idx = i * 512 + tid;
            int row = idx >> 3;
            int col8 = (idx & 7) * 8;
            size_t ga = (size_t)(bm + row) * HC + c * 64 + col8;
            uint32_t so = row * LDB + col8 * 2;
            cp16(dAh + so, g_a1h + ga);
        }
        {
            int idx = tid;
            int row = idx >> 3;
            int col8 = (idx & 7) * 8;
            size_t gb = (size_t)row * INC + c * 64 + col8;
            uint32_t so = row * LDB + col8 * 2;
            cp16(dBh + so, g_w2h + gb);
        }
    };
    auto compute = [&](int buf) {
        const uint32_t* Ahw = (const uint32_t*)(smem + buf * G2_BUF);
        const uint32_t* Bhw = (const uint32_t*)(smem + buf * G2_BUF + ATILE);
        #pragma unroll
        for (int kk = 0; kk < 4; kk++) {
            const int kw = kk * 8;
            uint32_t bh[4][2];
            #pragma unroll
            for (int nt = 0; nt < 4; nt++) {
                int w0 = (wn * 32 + nt * 8 + g) * LDW + kw + t;
                bh[nt][0] = Bhw[w0]; bh[nt][1] = Bhw[w0 + 4];
            }
            {
                int w0 = (wm * 16 + g) * LDW + kw + t;
                uint32_t ah[4];
                ah[0] = Ahw[w0]; ah[1] = Ahw[w0 + 8 * LDW];
                ah[2] = Ahw[w0 + 4]; ah[3] = Ahw[w0 + 8 * LDW + 4];
                #pragma unroll
                for (int nt = 0; nt < 4; nt++)
                    mma_bf16(acc[nt], ah, bh[nt]);
            }
        }
    };

    stage(0, 0); CP_COMMIT();
    CP_WAIT0(); __syncthreads();
    #pragma unroll
    for (int c = 0; c < 4; c++) {
        int buf = c & 1;
        if (c < 3) { stage(c + 1, buf ^ 1); CP_COMMIT(); }
        compute(buf);
        if (c < 3) { CP_WAIT0(); __syncthreads(); }
    }

    {
        int row0 = bm + wm * 16 + g;
        int row1 = row0 + 8;
        float s0 = 0.f, s1 = 0.f, d0 = 0.f, d1 = 0.f;
        #pragma unroll
        for (int nt = 0; nt < 4; nt++) {
            int lcol = wn * 32 + nt * 8 + 2 * t;
            float as0 = sAs[lcol], as1 = sAs[lcol + 1];
            float ad0 = sAd[lcol], ad1 = sAd[lcol + 1];
            s0 += acc[nt][0] * as0 + acc[nt][1] * as1;
            s1 += acc[nt][2] * as0 + acc[nt][3] * as1;
            d0 += acc[nt][0] * ad0 + acc[nt][1] * ad1;
            d1 += acc[nt][2] * ad0 + acc[nt][3] * ad1;
            if (lcol < OC) {
                if (row0 < Nn)
                    *(float2*)(g_h2 + (size_t)row0 * OC + lcol) = make_float2(acc[nt][0], acc[nt][1]);
                if (row1 < Nn)
                    *(float2*)(g_h2 + (size_t)row1 * OC + lcol) = make_float2(acc[nt][2], acc[nt][3]);
            }
        }
        s0 += __shfl_down_sync(0xffffffffu, s0, 2); s0 += __shfl_down_sync(0xffffffffu, s0, 1);
        s1 += __shfl_down_sync(0xffffffffu, s1, 2); s1 += __shfl_down_sync(0xffffffffu, s1, 1);
        d0 += __shfl_down_sync(0xffffffffu, d0, 2); d0 += __shfl_down_sync(0xffffffffu, d0, 1);
        d1 += __shfl_down_sync(0xffffffffu, d1, 2); d1 += __shfl_down_sync(0xffffffffu, d1, 1);
        if (t == 0) {
            int r0 = wm * 16 + g, r1 = r0 + 8;
            atomicAdd(&red2[0][r0], s0);
            atomicAdd(&red2[0][r1], s1);
            atomicAdd(&red2[1][r0], d0);
            atomicAdd(&red2[1][r1], d1);
        }
    }
    __syncthreads();
    if (tid < 128) {
        int n = bm + tid;
        if (n < Nn) {
            g_als2[n] = red2[0][tid];
            g_ald2[n] = red2[1][tid];
        }
    }
}

// ---------------- layer 1: bf16 uint2 gathers -----------------------------------
__global__ __launch_bounds__(256) void agg1_kernel(const float* __restrict__ b1) {
    int d = blockIdx.x;
    int start = g_rowptr[d], end = g_rowptr[d + 1];
    int tid = threadIdx.x;
    __shared__ float sden[NH];
    __shared__ int ssrc[128];
    __shared__ float salpha[128 * NH];
    __shared__ float4 sacc[4 * 64];

    if (tid < NH) sden[tid] = 1e-16f;
    float4 aldv = *(const float4*)&g_ald1[d * NH];

    const int ch4 = tid & 63;
    const int slot = tid >> 6;
    const int head = ch4 >> 4;
    float4 acc = make_float4(0.f, 0.f, 0.f, 0.f);
    float p0 = 0.f, p1 = 0.f, p2 = 0.f, p3 = 0.f;

    for (int base = start; base < end; base += 128) {
        int cnt = min(128, end - base);
        __syncthreads();
        if (tid < cnt) {
            int s = g_srcl[base + tid];
            ssrc[tid] = s;
            float4 als = *(const float4*)&g_als1[s * NH];
            float e0 = __expf(lrelu(als.x + aldv.x));
            float e1 = __expf(lrelu(als.y + aldv.y));
            float e2 = __expf(lrelu(als.z + aldv.z));
            float e3 = __expf(lrelu(als.w + aldv.w));
            salpha[tid * 4 + 0] = e0; salpha[tid * 4 + 1] = e1;
            salpha[tid * 4 + 2] = e2; salpha[tid * 4 + 3] = e3;
            p0 += e0; p1 += e1; p2 += e2; p3 += e3;
        }
        __syncthreads();
        int j = slot;
        for (; j + 4 < cnt; j += 8) {
            float a0 = salpha[j * 4 + head];
            float a1 = salpha[(j + 4) * 4 + head];
            int s0 = ssrc[j], s1 = ssrc[j + 4];
            uint2 hv0 = *(const uint2*)(g_h1b + (size_t)s0 * HC + ch4 * 4);
            uint2 hv1 = *(const uint2*)(g_h1b + (size_t)s1 * HC + ch4 * 4);
            float2 f00 = __bfloat1622float2(*(const __nv_bfloat162*)&hv0.x);
            float2 f01 = __bfloat1622float2(*(const __nv_bfloat162*)&hv0.y);
            float2 f10 = __bfloat1622float2(*(const __nv_bfloat162*)&hv1.x);
            float2 f11 = __bfloat1622float2(*(const __nv_bfloat162*)&hv1.y);
            acc.x = fmaf(a0, f00.x, acc.x); acc.y = fmaf(a0, f00.y, acc.y);
            acc.z = fmaf(a0, f01.x, acc.z); acc.w = fmaf(a0, f01.y, acc.w);
            acc.x = fmaf(a1, f10.x, acc.x); acc.y = fmaf(a1, f10.y, acc.y);
            acc.z = fmaf(a1, f11.x, acc.z); acc.w = fmaf(a1, f11.y, acc.w);
        }
        for (; j < cnt; j += 4) {
            float a = salpha[j * 4 + head];
            int s = ssrc[j];
            uint2 hv = *(const uint2*)(g_h1b + (size_t)s * HC + ch4 * 4);
            float2 f0 = __bfloat1622float2(*(const __nv_bfloat162*)&hv.x);
            float2 f1 = __bfloat1622float2(*(const __nv_bfloat162*)&hv.y);
            acc.x = fmaf(a, f0.x, acc.x);
            acc.y = fmaf(a, f0.y, acc.y);
            acc.z = fmaf(a, f1.x, acc.z);
            acc.w = fmaf(a, f1.y, acc.w);
        }
    }
    #pragma unroll
    for (int off = 16; off; off >>= 1) {
        p0 += __shfl_down_sync(0xffffffffu, p0, off);
        p1 += __shfl_down_sync(0xffffffffu, p1, off);
        p2 += __shfl_down_sync(0xffffffffu, p2, off);
        p3 += __shfl_down_sync(0xffffffffu, p3, off);
    }
    if ((tid & 31) == 0) {
        atomicAdd(&sden[0], p0);
        atomicAdd(&sden[1], p1);
        atomicAdd(&sden[2], p2);
        atomicAdd(&sden[3], p3);
    }
    sacc[slot * 64 + ch4] = acc;
    __syncthreads();
    if (tid < 64) {
        float4 a0 = sacc[tid], a1 = sacc[64 + tid], a2 = sacc[128 + tid], a3 = sacc[192 + tid];
        float rd = 1.f / sden[tid >> 4];
        int ch = tid * 4;
        float4 bb = *(const float4*)(b1 + ch);
        float4 r;
        r.x = fmaxf((a0.x + a1.x + a2.x + a3.x) * rd + bb.x, 0.f);
        r.y = fmaxf((a0.y + a1.y + a2.y + a3.y) * rd + bb.y, 0.f);
        r.z = fmaxf((a0.z + a1.z + a2.z + a3.z) * rd + bb.z, 0.f);
        r.w = fmaxf((a0.w + a1.w + a2.w + a3.w) * rd + bb.w, 0.f);
        *(uint2*)(g_a1h + (size_t)d * HC + ch) = tobf4(r);
    }
}

// ---------------- layer 2 single-pass agg + log_softmax ----------------------
__global__ void agg2_final(const float* __restrict__ b2, float* __restrict__ out) {
    int n = blockIdx.x * 8 + (threadIdx.x >> 5);
    if (n >= Nn) return;
    int lane = threadIdx.x & 31;
    int start = g_rowptr[n], end = g_rowptr[n + 1];
    float ald = g_ald2[n];

    float den = 0.f, acc0 = 0.f, acc1 = 0.f;
    for (int base = start; base < end; base += 32) {
        int i = base + lane;
        int s = 0; float e = 0.f;
        if (i < end) {
            s = g_srcl[i];
            e = __expf(lrelu(g_als2[s] + ald));
        }
        den += e;
        int cnt = min(32, end - base);
        for (int j = 0; j < cnt; j++) {
            int   sj = __shfl_sync(0xffffffffu, s, j);
            float ej = __shfl_sync(0xffffffffu, e, j);
            acc0 = fmaf(ej, g_h2[sj * OC + lane], acc0);
            if (lane < 8) acc1 = fmaf(ej, g_h2[sj * OC + 32 + lane], acc1);
        }
    }
    #pragma unroll
    for (int off = 16; off; off >>= 1)
        den += __shfl_xor_sync(0xffffffffu, den, off);
    float rden = 1.f / (den + 1e-16f);

    float v0 = acc0 * rden + b2[lane];
    float v1 = (lane < 8) ? (acc1 * rden + b2[32 + lane]) : -3.402823466e38f;
    float mx = fmaxf(v0, v1);
    #pragma unroll
    for (int off = 16; off; off >>= 1)
        mx = fmaxf(mx, __shfl_xor_sync(0xffffffffu, mx, off));
    float se = expf(v0 - mx) + ((lane < 8) ? expf(v1 - mx) : 0.f);
    #pragma unroll
    for (int off = 16; off; off >>= 1)
        se += __shfl_xor_sync(0xffffffffu, se, off);
    float lse = mx + logf(se);
    out[n * OC + lane] = v0 - lse;
    if (lane < 8) out[n * OC + 32 + lane] = v1 - lse;
}

// ---------------- launch -----------------------------------------------------
extern "C" void kernel_launch(void* const* d_in, const int* in_sizes, int n_in,
                              void* d_out, int out_size) {
    const float* x      = (const float*)d_in[0];
    const int*   ei     = (const int*)d_in[1];
    const float* W1     = (const float*)d_in[2];
    const float* a_src1 = (const float*)d_in[3];
    const float* a_dst1 = (const float*)d_in[4];
    const float* b1     = (const float*)d_in[5];
    const float* W2     = (const float*)d_in[6];
    const float* a_src2 = (const float*)d_in[7];
    const float* a_dst2 = (const float*)d_in[8];
    const float* b2     = (const float*)d_in[9];
    float* out = (float*)d_out;

    cudaFuncSetAttribute(gemm1_mma, cudaFuncAttributeMaxDynamicSharedMemorySize, G1_SMEM);
    cudaFuncSetAttribute(gemm2_mma, cudaFuncAttributeMaxDynamicSharedMemorySize, G2_SMEM);

    convert_w<<<(INC * HC + 64 * INC + 255) / 256, 256>>>(W1, W2);
    gemm1_mma<<<MTILES * 2 + HBLK, 512, G1_SMEM>>>(x, ei, a_src1, a_dst1);
    scan_part<<<NB, 256>>>();
    scan_add2<<<NB, 256>>>();
    fill_kernel<<<(Ee / 4 + Nn + 255) / 256, 256>>>(ei);
    agg1_kernel<<<Nn, 256>>>(b1);
    gemm2_mma<<<MTILES, 512, G2_SMEM>>>(a_src2, a_dst2);
    agg2_final<<<(Nn + 7) / 8, 256>>>(b2, out);
}

// round 14
// speedup vs baseline: 2.3010x; 1.2851x over previous
#include <cuda_runtime.h>
#include <cuda_bf16.h>
#include <cstdint>

#define Nn 50000
#define Ee 800000
#define ET (Ee + Nn)
#define INC 256
#define HC 256
#define NH 4
#define OC 40
#define NB ((Nn + 255) / 256)

#define MT 128
#define MTILES ((Nn + MT - 1) / MT)
#define PADN (MTILES * MT)
#define HBLK 391

// ---------------- scratch ----------------------------------------------------
__device__ __align__(16) __nv_bfloat16 g_h1b[(size_t)Nn * HC];
__device__ float g_als1[Nn * NH];
__device__ float g_ald1[Nn * NH];
__device__ float g_h2[Nn * OC];
__device__ float g_als2[Nn];
__device__ float g_ald2[Nn];
__device__ int g_counts[Nn];
__device__ int g_fill[Nn];
__device__ int g_rowptr[Nn + 1];
__device__ int g_srcl[ET];
__device__ __align__(16) __nv_bfloat16 g_w1h[INC * HC];
__device__ __align__(16) __nv_bfloat16 g_w2h[64 * INC];
__device__ __align__(16) __nv_bfloat16 g_a1h[(size_t)PADN * HC];

// ---------------- helpers ----------------------------------------------------
__device__ __forceinline__ float lrelu(float v) { return (v > 0.f) ? v : 0.2f * v; }
__device__ __forceinline__ uint32_t pack2(__nv_bfloat16 a, __nv_bfloat16 b) {
    __nv_bfloat162 t; t.x = a; t.y = b;
    return *reinterpret_cast<uint32_t*>(&t);
}
__device__ __forceinline__ uint2 tobf4(float4 v) {
    uint2 r;
    r.x = pack2(__float2bfloat16(v.x), __float2bfloat16(v.y));
    r.y = pack2(__float2bfloat16(v.z), __float2bfloat16(v.w));
    return r;
}
__device__ __forceinline__ uint32_t smem_u32(const void* p) {
    uint32_t a;
    asm("{ .reg .u64 t; cvta.to.shared.u64 t, %1; cvt.u32.u64 %0, t; }" : "=r"(a) : "l"(p));
    return a;
}
__device__ __forceinline__ void cp16(uint32_t dst, const void* src) {
    asm volatile("cp.async.ca.shared.global [%0], [%1], 16;" :: "r"(dst), "l"(src));
}
#define CP_COMMIT() asm volatile("cp.async.commit_group;" ::: "memory")
#define CP_WAIT0()  asm volatile("cp.async.wait_group 0;" ::: "memory")

// ---------------- convert_w + init (fused) -------------------------------------
__global__ void convert_w(const float* __restrict__ W1, const float* __restrict__ W2) {
    int t = blockIdx.x * blockDim.x + threadIdx.x;
    if (t < INC * HC) {
        int k = t >> 8, n = t & 255;
        g_w1h[n * INC + k] = __float2bfloat16(W1[t]);
    } else if (t < INC * HC + 64 * INC) {
        int u = t - INC * HC;
        int n = u >> 8, k = u & 255;
        float v = (n < OC) ? W2[k * OC + n] : 0.f;
        g_w2h[n * INC + k] = __float2bfloat16(v);
    }
    if (t < Nn) { g_counts[t] = 1; g_fill[t] = 0; }
}

// ---------------- fused single-pass scan ----------------------------------------
// block j: offset = sum(counts[0 .. j*256)) computed redundantly, then local scan
__global__ void scan_fused() {
    __shared__ int ws[8];
    int j = blockIdx.x;
    int tid = threadIdx.x;
    int lane = tid & 31, warp = tid >> 5;

    int off = 0;
    for (int i = tid; i < j * 256; i += 256) off += g_counts[i];
    #pragma unroll
    for (int o = 16; o; o >>= 1) off += __shfl_down_sync(0xffffffffu, off, o);
    if (lane == 0) ws[warp] = off;
    __syncthreads();
    if (warp == 0) {
        int w = (lane < 8) ? ws[lane] : 0;
        #pragma unroll
        for (int o = 4; o; o >>= 1) w += __shfl_down_sync(0xffffffffu, w, o);
        if (lane == 0) ws[0] = w;
    }
    __syncthreads();
    int total_off = ws[0];
    __syncthreads();

    // local inclusive scan of this chunk
    int idx = j * 256 + tid;
    int v = (idx < Nn) ? g_counts[idx] : 0;
    #pragma unroll
    for (int o = 1; o < 32; o <<= 1) {
        int u = __shfl_up_sync(0xffffffffu, v, o);
        if (lane >= o) v += u;
    }
    if (lane == 31) ws[warp] = v;
    __syncthreads();
    if (warp == 0 && lane < 8) {
        int w = ws[lane];
        #pragma unroll
        for (int o = 1; o < 8; o <<= 1) {
            int u = __shfl_up_sync(0xffu, w, o);
            if (lane >= o) w += u;
        }
        ws[lane] = w;
    }
    __syncthreads();
    if (warp > 0) v += ws[warp - 1];
    if (idx < Nn) g_rowptr[idx + 1] = v + total_off;
    if (j == 0 && tid == 0) g_rowptr[0] = 0;
}

__global__ void fill_kernel(const int* __restrict__ ei) {
    const int Q = Ee / 4;
    int i = blockIdx.x * blockDim.x + threadIdx.x;
    if (i < Q) {
        int4 s = ((const int4*)ei)[i];
        int4 d = ((const int4*)(ei + Ee))[i];
        int p;
        p = g_rowptr[d.x] + atomicAdd(&g_fill[d.x], 1); g_srcl[p] = s.x;
        p = g_rowptr[d.y] + atomicAdd(&g_fill[d.y], 1); g_srcl[p] = s.y;
        p = g_rowptr[d.z] + atomicAdd(&g_fill[d.z], 1); g_srcl[p] = s.z;
        p = g_rowptr[d.w] + atomicAdd(&g_fill[d.w], 1); g_srcl[p] = s.w;
    } else {
        int n = i - Q;
        if (n < Nn) {
            int p = g_rowptr[n] + atomicAdd(&g_fill[n], 1);
            g_srcl[p] = n;
        }
    }
}

// ---------------- GEMM common ---------------------------------------------------
#define LDW 36
#define LDB 144
#define ATILE (128 * LDB)

__device__ __forceinline__ void mma_bf16(float* c, const uint32_t* a, const uint32_t* b) {
    asm volatile(
        "mma.sync.aligned.m16n8k16.row.col.f32.bf16.bf16.f32 "
        "{%0,%1,%2,%3}, {%4,%5,%6,%7}, {%8,%9}, {%0,%1,%2,%3};"
        : "+f"(c[0]), "+f"(c[1]), "+f"(c[2]), "+f"(c[3])
        : "r"(a[0]), "r"(a[1]), "r"(a[2]), "r"(a[3]), "r"(b[0]), "r"(b[1]));
}

// ---------------- GEMM1 (+ hist): h1b = bf16(x @ W1), pure bf16 ----------------
#define G1_BUF (2 * ATILE)
#define G1_SMEM (2 * G1_BUF)

__global__ void __launch_bounds__(512, 1)
gemm1_mma(const float* __restrict__ X, const int* __restrict__ ei,
          const float* __restrict__ a_src, const float* __restrict__ a_dst) {
    if (blockIdx.x >= MTILES * 2) {
        int i = (blockIdx.x - MTILES * 2) * 512 + threadIdx.x;
        if (i < Ee / 4) {
            int4 d = ((const int4*)(ei + Ee))[i];
            atomicAdd(&g_counts[d.x], 1);
            atomicAdd(&g_counts[d.y], 1);
            atomicAdd(&g_counts[d.z], 1);
            atomicAdd(&g_counts[d.w], 1);
        }
        return;
    }

    extern __shared__ char smem[];
    __shared__ float sAs[128], sAd[128];
    __shared__ float red[4][2][2][32];

    const int tid = threadIdx.x;
    const int wid = tid >> 5;
    const int lane = tid & 31;
    const int wm = wid >> 2;
    const int wn = wid & 3;
    const int g = lane >> 2;
    const int t = lane & 3;
    const int hl = wn >> 1;

    const int bm = (blockIdx.x >> 1) * MT;
    const int bn = (blockIdx.x & 1) * 128;

    const uint32_t sb = smem_u32(smem);

    if (tid < 128) { sAs[tid] = a_src[bn + tid]; sAd[tid] = a_dst[bn + tid]; }
    ((float*)red)[tid] = 0.f;

    float acc[2][4][4] = {};
    float4 aregs[4];

    auto loadA = [&](int c) {
        #pragma unroll
        for (int i = 0; i < 4; i++) {
            int idx = i * 512 + tid;
            int row = idx >> 4;
            int col4 = (idx & 15) * 4;
            int grow = bm + row;
            aregs[i] = (grow < Nn)
                ? *(const float4*)(X + (size_t)grow * INC + c * 64 + col4)
                : make_float4(0.f, 0.f, 0.f, 0.f);
        }
    };
    auto storeA = [&](int buf) {
        char* sAh = smem + buf * G1_BUF;
        #pragma unroll
        for (int i = 0; i < 4; i++) {
            int idx = i * 512 + tid;
            int row = idx >> 4;
            int col4 = (idx & 15) * 4;
            int so = row * LDB + col4 * 2;
            *(uint2*)(sAh + so) = tobf4(aregs[i]);
        }
    };
    auto cpB = [&](int c, int buf) {
        uint32_t dBh = sb + buf * G1_BUF + ATILE;
        #pragma unroll
        for (int i = 0; i < 2; i++) {
            int idx = i * 512 + tid;
            int row = idx >> 3;
            int col8 = (idx & 7) * 8;
            size_t gb = (size_t)(bn + row) * INC + c * 64 + col8;
            uint32_t so = row * LDB + col8 * 2;
            cp16(dBh + so, g_w1h + gb);
        }
    };
    auto compute = [&](int buf) {
        const uint32_t* Ahw = (const uint32_t*)(smem + buf * G1_BUF);
        const uint32_t* Bhw = (const uint32_t*)(smem + buf * G1_BUF + ATILE);
        #pragma unroll
        for (int kk = 0; kk < 4; kk++) {
            const int kw = kk * 8;
            uint32_t bh[4][2];
            #pragma unroll
            for (int nt = 0; nt < 4; nt++) {
                int w0 = (wn * 32 + nt * 8 + g) * LDW + kw + t;
                bh[nt][0] = Bhw[w0]; bh[nt][1] = Bhw[w0 + 4];
            }
            #pragma unroll
            for (int mt = 0; mt < 2; mt++) {
                int w0 = (wm * 32 + mt * 16 + g) * LDW + kw + t;
                uint32_t ah[4];
                ah[0] = Ahw[w0]; ah[1] = Ahw[w0 + 8 * LDW];
                ah[2] = Ahw[w0 + 4]; ah[3] = Ahw[w0 + 8 * LDW + 4];
                #pragma unroll
                for (int nt = 0; nt < 4; nt++)
                    mma_bf16(acc[mt][nt], ah, bh[nt]);
            }
        }
    };

    loadA(0); cpB(0, 0); CP_COMMIT(); storeA(0);
    CP_WAIT0(); __syncthreads();
    #pragma unroll
    for (int c = 0; c < 4; c++) {
        int buf = c & 1;
        if (c < 3) { loadA(c + 1); cpB(c + 1, buf ^ 1); CP_COMMIT(); }
        compute(buf);
        if (c < 3) { storeA(buf ^ 1); CP_WAIT0(); __syncthreads(); }
    }

    #pragma unroll
    for (int mt = 0; mt < 2; mt++) {
        int row0 = bm + wm * 32 + mt * 16 + g;
        int row1 = row0 + 8;
        float s0 = 0.f, s1 = 0.f, d0 = 0.f, d1 = 0.f;
        #pragma unroll
        for (int nt = 0; nt < 4; nt++) {
            int lcol = wn * 32 + nt * 8 + 2 * t;
            int col = bn + lcol;
            float as0 = sAs[lcol], as1 = sAs[lcol + 1];
            float ad0 = sAd[lcol], ad1 = sAd[lcol + 1];
            s0 += acc[mt][nt][0] * as0 + acc[mt][nt][1] * as1;
            s1 += acc[mt][nt][2] * as0 + acc[mt][nt][3] * as1;
            d0 += acc[mt][nt][0] * ad0 + acc[mt][nt][1] * ad1;
            d1 += acc[mt][nt][2] * ad0 + acc[mt][nt][3] * ad1;
            if (row0 < Nn)
                *(uint32_t*)(g_h1b + (size_t)row0 * HC + col) =
                    pack2(__float2bfloat16(acc[mt][nt][0]), __float2bfloat16(acc[mt][nt][1]));
            if (row1 < Nn)
                *(uint32_t*)(g_h1b + (size_t)row1 * HC + col) =
                    pack2(__float2bfloat16(acc[mt][nt][2]), __float2bfloat16(acc[mt][nt][3]));
        }
        s0 += __shfl_down_sync(0xffffffffu, s0, 2); s0 += __shfl_down_sync(0xffffffffu, s0, 1);
        s1 += __shfl_down_sync(0xffffffffu, s1, 2); s1 += __shfl_down_sync(0xffffffffu, s1, 1);
        d0 += __shfl_down_sync(0xffffffffu, d0, 2); d0 += __shfl_down_sync(0xffffffffu, d0, 1);
        d1 += __shfl_down_sync(0xffffffffu, d1, 2); d1 += __shfl_down_sync(0xffffffffu, d1, 1);
        if (t == 0) {
            int r0 = mt * 16 + g, r1 = r0 + 8;
            atomicAdd(&red[wm][hl][0][r0], s0);
            atomicAdd(&red[wm][hl][0][r1], s1);
            atomicAdd(&red[wm][hl][1][r0], d0);
            atomicAdd(&red[wm][hl][1][r1], d1);
        }
    }
    __syncthreads();
    if (tid < 128) {
        int n = bm + tid;
        if (n < Nn) {
            int w = tid >> 5, r = tid & 31;
            #pragma unroll
            for (int h = 0; h < 2; h++) {
                int head = (bn >> 6) + h;
                g_als1[n * NH + head] = red[w][h][0][r];
                g_ald1[n * NH + head] = red[w][h][1][r];
            }
        }
    }
}

// ---------------- GEMM2: h2 = agg1 @ W2, pure bf16 ------------------------------
#define BTILE2 (64 * LDB)
#define G2_BUF (ATILE + BTILE2)
#define G2_SMEM (2 * G2_BUF)

__global__ void __launch_bounds__(512, 1)
gemm2_mma(const float* __restrict__ a_src, const float* __restrict__ a_dst) {
    extern __shared__ char smem[];
    __shared__ float sAs[64], sAd[64];
    __shared__ float red2[2][128];

    const int tid = threadIdx.x;
    const int wid = tid >> 5;
    const int lane = tid & 31;
    const int wm = wid >> 1;
    const int wn = wid & 1;
    const int g = lane >> 2;
    const int t = lane & 3;

    const int bm = blockIdx.x * MT;
    const uint32_t sb = smem_u32(smem);

    if (tid < 64) { sAs[tid] = (tid < OC) ? a_src[tid] : 0.f;
                    sAd[tid] = (tid < OC) ? a_dst[tid] : 0.f; }
    if (tid < 256) ((float*)red2)[tid] = 0.f;

    float acc[4][4] = {};

    auto stage = [&](int c, int buf) {
        uint32_t dAh = sb + buf * G2_BUF;
        uint32_t dBh = dAh + ATILE;
        #pragma unroll
        for (int i = 0; i < 2; i++) {
            int idx = i * 512 + tid;
            int row = idx >> 3;
            int col8 = (idx & 7) * 8;
            size_t ga = (size_t)(bm + row) * HC + c * 64 + col8;
            uint32_t so = row * LDB + col8 * 2;
            cp16(dAh + so, g_a1h + ga);
        }
        {
            int idx = tid;
            int row = idx >> 3;
            int col8 = (idx & 7) * 8;
            size_t gb = (size_t)row * INC + c * 64 + col8;
            uint32_t so = row * LDB + col8 * 2;
            cp16(dBh + so, g_w2h + gb);
        }
    };
    auto compute = [&](int buf) {
        const uint32_t* Ahw = (const uint32_t*)(smem + buf * G2_BUF);
        const uint32_t* Bhw = (const uint32_t*)(smem + buf * G2_BUF + ATILE);
        #pragma unroll
        for (int kk = 0; kk < 4; kk++) {
            const int kw = kk * 8;
            uint32_t bh[4][2];
            #pragma unroll
            for (int nt = 0; nt < 4; nt++) {
                int w0 = (wn * 32 + nt * 8 + g) * LDW + kw + t;
                bh[nt][0] = Bhw[w0]; bh[nt][1] = Bhw[w0 + 4];
            }
            {
                int w0 = (wm * 16 + g) * LDW + kw + t;
                uint32_t ah[4];
                ah[0] = Ahw[w0]; ah[1] = Ahw[w0 + 8 * LDW];
                ah[2] = Ahw[w0 + 4]; ah[3] = Ahw[w0 + 8 * LDW + 4];
                #pragma unroll
                for (int nt = 0; nt < 4; nt++)
                    mma_bf16(acc[nt], ah, bh[nt]);
            }
        }
    };

    stage(0, 0); CP_COMMIT();
    CP_WAIT0(); __syncthreads();
    #pragma unroll
    for (int c = 0; c < 4; c++) {
        int buf = c & 1;
        if (c < 3) { stage(c + 1, buf ^ 1); CP_COMMIT(); }
        compute(buf);
        if (c < 3) { CP_WAIT0(); __syncthreads(); }
    }

    {
        int row0 = bm + wm * 16 + g;
        int row1 = row0 + 8;
        float s0 = 0.f, s1 = 0.f, d0 = 0.f, d1 = 0.f;
        #pragma unroll
        for (int nt = 0; nt < 4; nt++) {
            int lcol = wn * 32 + nt * 8 + 2 * t;
            float as0 = sAs[lcol], as1 = sAs[lcol + 1];
            float ad0 = sAd[lcol], ad1 = sAd[lcol + 1];
            s0 += acc[nt][0] * as0 + acc[nt][1] * as1;
            s1 += acc[nt][2] * as0 + acc[nt][3] * as1;
            d0 += acc[nt][0] * ad0 + acc[nt][1] * ad1;
            d1 += acc[nt][2] * ad0 + acc[nt][3] * ad1;
            if (lcol < OC) {
                if (row0 < Nn)
                    *(float2*)(g_h2 + (size_t)row0 * OC + lcol) = make_float2(acc[nt][0], acc[nt][1]);
                if (row1 < Nn)
                    *(float2*)(g_h2 + (size_t)row1 * OC + lcol) = make_float2(acc[nt][2], acc[nt][3]);
            }
        }
        s0 += __shfl_down_sync(0xffffffffu, s0, 2); s0 += __shfl_down_sync(0xffffffffu, s0, 1);
        s1 += __shfl_down_sync(0xffffffffu, s1, 2); s1 += __shfl_down_sync(0xffffffffu, s1, 1);
        d0 += __shfl_down_sync(0xffffffffu, d0, 2); d0 += __shfl_down_sync(0xffffffffu, d0, 1);
        d1 += __shfl_down_sync(0xffffffffu, d1, 2); d1 += __shfl_down_sync(0xffffffffu, d1, 1);
        if (t == 0) {
            int r0 = wm * 16 + g, r1 = r0 + 8;
            atomicAdd(&red2[0][r0], s0);
            atomicAdd(&red2[0][r1], s1);
            atomicAdd(&red2[1][r0], d0);
            atomicAdd(&red2[1][r1], d1);
        }
    }
    __syncthreads();
    if (tid < 128) {
        int n = bm + tid;
        if (n < Nn) {
            g_als2[n] = red2[0][tid];
            g_ald2[n] = red2[1][tid];
        }
    }
}

// ---------------- layer 1: 128-thread blocks, 2 slots, MLP-4 gathers -----------
__global__ __launch_bounds__(128) void agg1_kernel(const float* __restrict__ b1) {
    int d = blockIdx.x;
    int start = g_rowptr[d], end = g_rowptr[d + 1];
    int tid = threadIdx.x;
    __shared__ float sden[NH];
    __shared__ int ssrc[128];
    __shared__ float salpha[128 * NH];
    __shared__ float4 sacc[2 * 64];

    if (tid < NH) sden[tid] = 1e-16f;
    float4 aldv = *(const float4*)&g_ald1[d * NH];

    const int ch4 = tid & 63;       // channels [ch4*4, ch4*4+4)
    const int slot = tid >> 6;      // 0..1 edge slot
    const int head = ch4 >> 4;
    float4 acc = make_float4(0.f, 0.f, 0.f, 0.f);
    float p0 = 0.f, p1 = 0.f, p2 = 0.f, p3 = 0.f;

    for (int base = start; base < end; base += 128) {
        int cnt = min(128, end - base);
        __syncthreads();
        if (tid < cnt) {
            int s = g_srcl[base + tid];
            ssrc[tid] = s;
            float4 als = *(const float4*)&g_als1[s * NH];
            float e0 = __expf(lrelu(als.x + aldv.x));
            float e1 = __expf(lrelu(als.y + aldv.y));
            float e2 = __expf(lrelu(als.z + aldv.z));
            float e3 = __expf(lrelu(als.w + aldv.w));
            salpha[tid * 4 + 0] = e0; salpha[tid * 4 + 1] = e1;
            salpha[tid * 4 + 2] = e2; salpha[tid * 4 + 3] = e3;
            p0 += e0; p1 += e1; p2 += e2; p3 += e3;
        }
        __syncthreads();
        int j = slot;
        // MLP-4: edges j, j+2, j+4, j+6 in flight per iteration
        for (; j + 6 < cnt; j += 8) {
            float a0 = salpha[j * 4 + head];
            float a1 = salpha[(j + 2) * 4 + head];
            float a2 = salpha[(j + 4) * 4 + head];
            float a3 = salpha[(j + 6) * 4 + head];
            int s0 = ssrc[j], s1 = ssrc[j + 2], s2 = ssrc[j + 4], s3 = ssrc[j + 6];
            uint2 h0 = *(const uint2*)(g_h1b + (size_t)s0 * HC + ch4 * 4);
            uint2 h1 = *(const uint2*)(g_h1b + (size_t)s1 * HC + ch4 * 4);
            uint2 h2 = *(const uint2*)(g_h1b + (size_t)s2 * HC + ch4 * 4);
            uint2 h3 = *(const uint2*)(g_h1b + (size_t)s3 * HC + ch4 * 4);
            float2 f;
            f = __bfloat1622float2(*(const __nv_bfloat162*)&h0.x);
            acc.x = fmaf(a0, f.x, acc.x); acc.y = fmaf(a0, f.y, acc.y);
            f = __bfloat1622float2(*(const __nv_bfloat162*)&h0.y);
            acc.z = fmaf(a0, f.x, acc.z); acc.w = fmaf(a0, f.y, acc.w);
            f = __bfloat1622float2(*(const __nv_bfloat162*)&h1.x);
            acc.x = fmaf(a1, f.x, acc.x); acc.y = fmaf(a1, f.y, acc.y);
            f = __bfloat1622float2(*(const __nv_bfloat162*)&h1.y);
            acc.z = fmaf(a1, f.x, acc.z); acc.w = fmaf(a1, f.y, acc.w);
            f = __bfloat1622float2(*(const __nv_bfloat162*)&h2.x);
            acc.x = fmaf(a2, f.x, acc.x); acc.y = fmaf(a2, f.y, acc.y);
            f = __bfloat1622float2(*(const __nv_bfloat162*)&h2.y);
            acc.z = fmaf(a2, f.x, acc.z); acc.w = fmaf(a2, f.y, acc.w);
            f = __bfloat1622float2(*(const __nv_bfloat162*)&h3.x);
            acc.x = fmaf(a3, f.x, acc.x); acc.y = fmaf(a3, f.y, acc.y);
            f = __bfloat1622float2(*(const __nv_bfloat162*)&h3.y);
            acc.z = fmaf(a3, f.x, acc.z); acc.w = fmaf(a3, f.y, acc.w);
        }
        for (; j < cnt; j += 2) {
            float a = salpha[j * 4 + head];
            int s = ssrc[j];
            uint2 hv = *(const uint2*)(g_h1b + (size_t)s * HC + ch4 * 4);
            float2 f0 = __bfloat1622float2(*(const __nv_bfloat162*)&hv.x);
            float2 f1 = __bfloat1622float2(*(const __nv_bfloat162*)&hv.y);
            acc.x = fmaf(a, f0.x, acc.x);
            acc.y = fmaf(a, f0.y, acc.y);
            acc.z = fmaf(a, f1.x, acc.z);
            acc.w = fmaf(a, f1.y, acc.w);
        }
    }
    #pragma unroll
    for (int off = 16; off; off >>= 1) {
        p0 += __shfl_down_sync(0xffffffffu, p0, off);
        p1 += __shfl_down_sync(0xffffffffu, p1, off);
        p2 += __shfl_down_sync(0xffffffffu, p2, off);
        p3 += __shfl_down_sync(0xffffffffu, p3, off);
    }
    if ((tid & 31) == 0) {
        atomicAdd(&sden[0], p0);
        atomicAdd(&sden[1], p1);
        atomicAdd(&sden[2], p2);
        atomicAdd(&sden[3], p3);
    }
    sacc[slot * 64 + ch4] = acc;
    __syncthreads();
    if (tid < 64) {
        float4 a0 = sacc[tid], a1 = sacc[64 + tid];
        float rd = 1.f / sden[tid >> 4];
        int ch = tid * 4;
        float4 bb = *(const float4*)(b1 + ch);
        float4 r;
        r.x = fmaxf((a0.x + a1.x) * rd + bb.x, 0.f);
        r.y = fmaxf((a0.y + a1.y) * rd + bb.y, 0.f);
        r.z = fmaxf((a0.z + a1.z) * rd + bb.z, 0.f);
        r.w = fmaxf((a0.w + a1.w) * rd + bb.w, 0.f);
        *(uint2*)(g_a1h + (size_t)d * HC + ch) = tobf4(r);
    }
}

// ---------------- layer 2 single-pass agg + log_softmax ----------------------
__global__ void agg2_final(const float* __restrict__ b2, float* __restrict__ out) {
    int n = blockIdx.x * 8 + (threadIdx.x >> 5);
    if (n >= Nn) return;
    int lane = threadIdx.x & 31;
    int start = g_rowptr[n], end = g_rowptr[n + 1];
    float ald = g_ald2[n];

    float den = 0.f, acc0 = 0.f, acc1 = 0.f;
    for (int base = start; base < end; base += 32) {
        int i = base + lane;
        int s = 0; float e = 0.f;
        if (i < end) {
            s = g_srcl[i];
            e = __expf(lrelu(g_als2[s] + ald));
        }
        den += e;
        int cnt = min(32, end - base);
        for (int j = 0; j < cnt; j++) {
            int   sj = __shfl_sync(0xffffffffu, s, j);
            float ej = __shfl_sync(0xffffffffu, e, j);
            acc0 = fmaf(ej, g_h2[sj * OC + lane], acc0);
            if (lane < 8) acc1 = fmaf(ej, g_h2[sj * OC + 32 + lane], acc1);
        }
    }
    #pragma unroll
    for (int off = 16; off; off >>= 1)
        den += __shfl_xor_sync(0xffffffffu, den, off);
    float rden = 1.f / (den + 1e-16f);

    float v0 = acc0 * rden + b2[lane];
    float v1 = (lane < 8) ? (acc1 * rden + b2[32 + lane]) : -3.402823466e38f;
    float mx = fmaxf(v0, v1);
    #pragma unroll
    for (int off = 16; off; off >>= 1)
        mx = fmaxf(mx, __shfl_xor_sync(0xffffffffu, mx, off));
    float se = expf(v0 - mx) + ((lane < 8) ? expf(v1 - mx) : 0.f);
    #pragma unroll
    for (int off = 16; off; off >>= 1)
        se += __shfl_xor_sync(0xffffffffu, se, off);
    float lse = mx + logf(se);
    out[n * OC + lane] = v0 - lse;
    if (lane < 8) out[n * OC + 32 + lane] = v1 - lse;
}

// ---------------- launch -----------------------------------------------------
extern "C" void kernel_launch(void* const* d_in, const int* in_sizes, int n_in,
                              void* d_out, int out_size) {
    const float* x      = (const float*)d_in[0];
    const int*   ei     = (const int*)d_in[1];
    const float* W1     = (const float*)d_in[2];
    const float* a_src1 = (const float*)d_in[3];
    const float* a_dst1 = (const float*)d_in[4];
    const float* b1     = (const float*)d_in[5];
    const float* W2     = (const float*)d_in[6];
    const float* a_src2 = (const float*)d_in[7];
    const float* a_dst2 = (const float*)d_in[8];
    const float* b2     = (const float*)d_in[9];
    float* out = (float*)d_out;

    cudaFuncSetAttribute(gemm1_mma, cudaFuncAttributeMaxDynamicSharedMemorySize, G1_SMEM);
    cudaFuncSetAttribute(gemm2_mma, cudaFuncAttributeMaxDynamicSharedMemorySize, G2_SMEM);

    convert_w<<<(INC * HC + 64 * INC + 255) / 256, 256>>>(W1, W2);      // 1
    gemm1_mma<<<MTILES * 2 + HBLK, 512, G1_SMEM>>>(x, ei, a_src1, a_dst1); // 2
    scan_fused<<<NB, 256>>>();                                           // 3
    fill_kernel<<<(Ee / 4 + Nn + 255) / 256, 256>>>(ei);                 // 4 <- profiled
    agg1_kernel<<<Nn, 128>>>(b1);                                        // 5
    gemm2_mma<<<MTILES, 512, G2_SMEM>>>(a_src2, a_dst2);                 // 6
    agg2_final<<<(Nn + 7) / 8, 256>>>(b2, out);                          // 7
}

// round 15
// speedup vs baseline: 2.3516x; 1.0220x over previous
#include <cuda_runtime.h>
#include <cuda_bf16.h>
#include <cstdint>

#define Nn 50000
#define Ee 800000
#define ET (Ee + Nn)
#define INC 256
#define HC 256
#define NH 4
#define OC 40
#define NB ((Nn + 255) / 256)

#define MT 128
#define MTILES ((Nn + MT - 1) / MT)
#define PADN (MTILES * MT)
#define HBLK 391

// ---------------- scratch ----------------------------------------------------
__device__ __align__(16) __nv_bfloat16 g_h1b[(size_t)Nn * HC];
__device__ float g_als1[Nn * NH];
__device__ float g_ald1[Nn * NH];
__device__ float g_h2[Nn * OC];
__device__ float g_als2[Nn];
__device__ float g_ald2[Nn];
__device__ int g_counts[Nn];
__device__ int g_fill[Nn];
__device__ int g_rowptr[Nn + 1];
__device__ int g_srcl[ET];
__device__ __align__(16) __nv_bfloat16 g_w1h[INC * HC];
__device__ __align__(16) __nv_bfloat16 g_w2h[64 * INC];
__device__ __align__(16) __nv_bfloat16 g_a1h[(size_t)PADN * HC];

// ---------------- helpers ----------------------------------------------------
__device__ __forceinline__ float lrelu(float v) { return (v > 0.f) ? v : 0.2f * v; }
__device__ __forceinline__ uint32_t pack2(__nv_bfloat16 a, __nv_bfloat16 b) {
    __nv_bfloat162 t; t.x = a; t.y = b;
    return *reinterpret_cast<uint32_t*>(&t);
}
__device__ __forceinline__ uint2 tobf4(float4 v) {
    uint2 r;
    r.x = pack2(__float2bfloat16(v.x), __float2bfloat16(v.y));
    r.y = pack2(__float2bfloat16(v.z), __float2bfloat16(v.w));
    return r;
}
__device__ __forceinline__ uint32_t smem_u32(const void* p) {
    uint32_t a;
    asm("{ .reg .u64 t; cvta.to.shared.u64 t, %1; cvt.u32.u64 %0, t; }" : "=r"(a) : "l"(p));
    return a;
}
__device__ __forceinline__ void cp16(uint32_t dst, const void* src) {
    asm volatile("cp.async.ca.shared.global [%0], [%1], 16;" :: "r"(dst), "l"(src));
}
#define CP_COMMIT() asm volatile("cp.async.commit_group;" ::: "memory")
#define CP_WAIT0()  asm volatile("cp.async.wait_group 0;" ::: "memory")

// ---------------- convert_w + init (fused) -------------------------------------
__global__ void convert_w(const float* __restrict__ W1, const float* __restrict__ W2) {
    int t = blockIdx.x * blockDim.x + threadIdx.x;
    if (t < INC * HC) {
        int k = t >> 8, n = t & 255;
        g_w1h[n * INC + k] = __float2bfloat16(W1[t]);
    } else if (t < INC * HC + 64 * INC) {
        int u = t - INC * HC;
        int n = u >> 8, k = u & 255;
        float v = (n < OC) ? W2[k * OC + n] : 0.f;
        g_w2h[n * INC + k] = __float2bfloat16(v);
    }
    if (t < Nn) { g_counts[t] = 1; g_fill[t] = 0; }
}

// ---------------- fused single-pass scan ----------------------------------------
__global__ void scan_fused() {
    __shared__ int ws[8];
    int j = blockIdx.x;
    int tid = threadIdx.x;
    int lane = tid & 31, warp = tid >> 5;

    int off = 0;
    for (int i = tid; i < j * 256; i += 256) off += g_counts[i];
    #pragma unroll
    for (int o = 16; o; o >>= 1) off += __shfl_down_sync(0xffffffffu, off, o);
    if (lane == 0) ws[warp] = off;
    __syncthreads();
    if (warp == 0) {
        int w = (lane < 8) ? ws[lane] : 0;
        #pragma unroll
        for (int o = 4; o; o >>= 1) w += __shfl_down_sync(0xffffffffu, w, o);
        if (lane == 0) ws[0] = w;
    }
    __syncthreads();
    int total_off = ws[0];
    __syncthreads();

    int idx = j * 256 + tid;
    int v = (idx < Nn) ? g_counts[idx] : 0;
    #pragma unroll
    for (int o = 1; o < 32; o <<= 1) {
        int u = __shfl_up_sync(0xffffffffu, v, o);
        if (lane >= o) v += u;
    }
    if (lane == 31) ws[warp] = v;
    __syncthreads();
    if (warp == 0 && lane < 8) {
        int w = ws[lane];
        #pragma unroll
        for (int o = 1; o < 8; o <<= 1) {
            int u = __shfl_up_sync(0xffu, w, o);
            if (lane >= o) w += u;
        }
        ws[lane] = w;
    }
    __syncthreads();
    if (warp > 0) v += ws[warp - 1];
    if (idx < Nn) g_rowptr[idx + 1] = v + total_off;
    if (j == 0 && tid == 0) g_rowptr[0] = 0;
}

// ---------------- fill: 8 edges per thread -------------------------------------
__global__ void fill_kernel(const int* __restrict__ ei) {
    const int Q8 = Ee / 8;               // 100000 threads handle edges (2 int4 each)
    int i = blockIdx.x * blockDim.x + threadIdx.x;
    if (i < Q8) {
        int4 s0 = ((const int4*)ei)[i * 2];
        int4 s1 = ((const int4*)ei)[i * 2 + 1];
        int4 d0 = ((const int4*)(ei + Ee))[i * 2];
        int4 d1 = ((const int4*)(ei + Ee))[i * 2 + 1];
        int p;
        p = g_rowptr[d0.x] + atomicAdd(&g_fill[d0.x], 1); g_srcl[p] = s0.x;
        p = g_rowptr[d0.y] + atomicAdd(&g_fill[d0.y], 1); g_srcl[p] = s0.y;
        p = g_rowptr[d0.z] + atomicAdd(&g_fill[d0.z], 1); g_srcl[p] = s0.z;
        p = g_rowptr[d0.w] + atomicAdd(&g_fill[d0.w], 1); g_srcl[p] = s0.w;
        p = g_rowptr[d1.x] + atomicAdd(&g_fill[d1.x], 1); g_srcl[p] = s1.x;
        p = g_rowptr[d1.y] + atomicAdd(&g_fill[d1.y], 1); g_srcl[p] = s1.y;
        p = g_rowptr[d1.z] + atomicAdd(&g_fill[d1.z], 1); g_srcl[p] = s1.z;
        p = g_rowptr[d1.w] + atomicAdd(&g_fill[d1.w], 1); g_srcl[p] = s1.w;
    } else {
        int n = i - Q8;
        if (n < Nn) {
            int p = g_rowptr[n] + atomicAdd(&g_fill[n], 1);
            g_srcl[p] = n;
        }
    }
}

// ---------------- GEMM common ---------------------------------------------------
#define LDW 36
#define LDB 144
#define ATILE (128 * LDB)

__device__ __forceinline__ void mma_bf16(float* c, const uint32_t* a, const uint32_t* b) {
    asm volatile(
        "mma.sync.aligned.m16n8k16.row.col.f32.bf16.bf16.f32 "
        "{%0,%1,%2,%3}, {%4,%5,%6,%7}, {%8,%9}, {%0,%1,%2,%3};"
        : "+f"(c[0]), "+f"(c[1]), "+f"(c[2]), "+f"(c[3])
        : "r"(a[0]), "r"(a[1]), "r"(a[2]), "r"(a[3]), "r"(b[0]), "r"(b[1]));
}

// ---------------- GEMM1 (+ hist): h1b = bf16(x @ W1), pure bf16 ----------------
#define G1_BUF (2 * ATILE)
#define G1_SMEM (2 * G1_BUF)

__global__ void __launch_bounds__(512, 1)
gemm1_mma(const float* __restrict__ X, const int* __restrict__ ei,
          const float* __restrict__ a_src, const float* __restrict__ a_dst) {
    if (blockIdx.x >= MTILES * 2) {
        int i = (blockIdx.x - MTILES * 2) * 512 + threadIdx.x;
        if (i < Ee / 4) {
            int4 d = ((const int4*)(ei + Ee))[i];
            atomicAdd(&g_counts[d.x], 1);
            atomicAdd(&g_counts[d.y], 1);
            atomicAdd(&g_counts[d.z], 1);
            atomicAdd(&g_counts[d.w], 1);
        }
        return;
    }

    extern __shared__ char smem[];
    __shared__ float sAs[128], sAd[128];
    __shared__ float red[4][2][2][32];

    const int tid = threadIdx.x;
    const int wid = tid >> 5;
    const int lane = tid & 31;
    const int wm = wid >> 2;
    const int wn = wid & 3;
    const int g = lane >> 2;
    const int t = lane & 3;
    const int hl = wn >> 1;

    const int bm = (blockIdx.x >> 1) * MT;
    const int bn = (blockIdx.x & 1) * 128;

    const uint32_t sb = smem_u32(smem);

    if (tid < 128) { sAs[tid] = a_src[bn + tid]; sAd[tid] = a_dst[bn + tid]; }
    ((float*)red)[tid] = 0.f;

    float acc[2][4][4] = {};
    float4 aregs[4];

    auto loadA = [&](int c) {
        #pragma unroll
        for (int i = 0; i < 4; i++) {
            int idx = i * 512 + tid;
            int row = idx >> 4;
            int col4 = (idx & 15) * 4;
            int grow = bm + row;
            aregs[i] = (grow < Nn)
                ? *(const float4*)(X + (size_t)grow * INC + c * 64 + col4)
                : make_float4(0.f, 0.f, 0.f, 0.f);
        }
    };
    auto storeA = [&](int buf) {
        char* sAh = smem + buf * G1_BUF;
        #pragma unroll
        for (int i = 0; i < 4; i++) {
            int idx = i * 512 + tid;
            int row = idx >> 4;
            int col4 = (idx & 15) * 4;
            int so = row * LDB + col4 * 2;
            *(uint2*)(sAh + so) = tobf4(aregs[i]);
        }
    };
    auto cpB = [&](int c, int buf) {
        uint32_t dBh = sb + buf * G1_BUF + ATILE;
        #pragma unroll
        for (int i = 0; i < 2; i++) {
            int idx = i * 512 + tid;
            int row = idx >> 3;
            int col8 = (idx & 7) * 8;
            size_t gb = (size_t)(bn + row) * INC + c * 64 + col8;
            uint32_t so = row * LDB + col8 * 2;
            cp16(dBh + so, g_w1h + gb);
        }
    };
    auto compute = [&](int buf) {
        const uint32_t* Ahw = (const uint32_t*)(smem + buf * G1_BUF);
        const uint32_t* Bhw = (const uint32_t*)(smem + buf * G1_BUF + ATILE);
        #pragma unroll
        for (int kk = 0; kk < 4; kk++) {
            const int kw = kk * 8;
            uint32_t bh[4][2];
            #pragma unroll
            for (int nt = 0; nt < 4; nt++) {
                int w0 = (wn * 32 + nt * 8 + g) * LDW + kw + t;
                bh[nt][0] = Bhw[w0]; bh[nt][1] = Bhw[w0 + 4];
            }
            #pragma unroll
            for (int mt = 0; mt < 2; mt++) {
                int w0 = (wm * 32 + mt * 16 + g) * LDW + kw + t;
                uint32_t ah[4];
                ah[0] = Ahw[w0]; ah[1] = Ahw[w0 + 8 * LDW];
                ah[2] = Ahw[w0 + 4]; ah[3] = Ahw[w0 + 8 * LDW + 4];
                #pragma unroll
                for (int nt = 0; nt < 4; nt++)
                    mma_bf16(acc[mt][nt], ah, bh[nt]);
            }
        }
    };

    loadA(0); cpB(0, 0); CP_COMMIT(); storeA(0);
    CP_WAIT0(); __syncthreads();
    #pragma unroll
    for (int c = 0; c < 4; c++) {
        int buf = c & 1;
        if (c < 3) { loadA(c + 1); cpB(c + 1, buf ^ 1); CP_COMMIT(); }
        compute(buf);
        if (c < 3) { storeA(buf ^ 1); CP_WAIT0(); __syncthreads(); }
    }

    #pragma unroll
    for (int mt = 0; mt < 2; mt++) {
        int row0 = bm + wm * 32 + mt * 16 + g;
        int row1 = row0 + 8;
        float s0 = 0.f, s1 = 0.f, d0 = 0.f, d1 = 0.f;
        #pragma unroll
        for (int nt = 0; nt < 4; nt++) {
            int lcol = wn * 32 + nt * 8 + 2 * t;
            int col = bn + lcol;
            float as0 = sAs[lcol], as1 = sAs[lcol + 1];
            float ad0 = sAd[lcol], ad1 = sAd[lcol + 1];
            s0 += acc[mt][nt][0] * as0 + acc[mt][nt][1] * as1;
            s1 += acc[mt][nt][2] * as0 + acc[mt][nt][3] * as1;
            d0 += acc[mt][nt][0] * ad0 + acc[mt][nt][1] * ad1;
            d1 += acc[mt][nt][2] * ad0 + acc[mt][nt][3] * ad1;
            if (row0 < Nn)
                *(uint32_t*)(g_h1b + (size_t)row0 * HC + col) =
                    pack2(__float2bfloat16(acc[mt][nt][0]), __float2bfloat16(acc[mt][nt][1]));
            if (row1 < Nn)
                *(uint32_t*)(g_h1b + (size_t)row1 * HC + col) =
                    pack2(__float2bfloat16(acc[mt][nt][2]), __float2bfloat16(acc[mt][nt][3]));
        }
        s0 += __shfl_down_sync(0xffffffffu, s0, 2); s0 += __shfl_down_sync(0xffffffffu, s0, 1);
        s1 += __shfl_down_sync(0xffffffffu, s1, 2); s1 += __shfl_down_sync(0xffffffffu, s1, 1);
        d0 += __shfl_down_sync(0xffffffffu, d0, 2); d0 += __shfl_down_sync(0xffffffffu, d0, 1);
        d1 += __shfl_down_sync(0xffffffffu, d1, 2); d1 += __shfl_down_sync(0xffffffffu, d1, 1);
        if (t == 0) {
            int r0 = mt * 16 + g, r1 = r0 + 8;
            atomicAdd(&red[wm][hl][0][r0], s0);
            atomicAdd(&red[wm][hl][0][r1], s1);
            atomicAdd(&red[wm][hl][1][r0], d0);
            atomicAdd(&red[wm][hl][1][r1], d1);
        }
    }
    __syncthreads();
    if (tid < 128) {
        int n = bm + tid;
        if (n < Nn) {
            int w = tid >> 5, r = tid & 31;
            #pragma unroll
            for (int h = 0; h < 2; h++) {
                int head = (bn >> 6) + h;
                g_als1[n * NH + head] = red[w][h][0][r];
                g_ald1[n * NH + head] = red[w][h][1][r];
            }
        }
    }
}

// ---------------- GEMM2: h2 = agg1 @ W2, pure bf16 ------------------------------
#define BTILE2 (64 * LDB)
#define G2_BUF (ATILE + BTILE2)
#define G2_SMEM (2 * G2_BUF)

__global__ void __launch_bounds__(512, 1)
gemm2_mma(const float* __restrict__ a_src, const float* __restrict__ a_dst) {
    extern __shared__ char smem[];
    __shared__ float sAs[64], sAd[64];
    __shared__ float red2[2][128];

    const int tid = threadIdx.x;
    const int wid = tid >> 5;
    const int lane = tid & 31;
    const int wm = wid >> 1;
    const int wn = wid & 1;
    const int g = lane >> 2;
    const int t = lane & 3;

    const int bm = blockIdx.x * MT;
    const uint32_t sb = smem_u32(smem);

    if (tid < 64) { sAs[tid] = (tid < OC) ? a_src[tid] : 0.f;
                    sAd[tid] = (tid < OC) ? a_dst[tid] : 0.f; }
    if (tid < 256) ((float*)red2)[tid] = 0.f;

    float acc[4][4] = {};

    auto stage = [&](int c, int buf) {
        uint32_t dAh = sb + buf * G2_BUF;
        uint32_t dBh = dAh + ATILE;
        #pragma unroll
        for (int i = 0; i < 2; i++) {
            int idx = i * 512 + tid;
            int row = idx >> 3;
            int col8 = (idx & 7) * 8;
            size_t ga = (size_t)(bm + row) * HC + c * 64 + col8;
            uint32_t so = row * LDB + col8 * 2;
            cp16(dAh + so, g_a1h + ga);
        }
        {
            int idx = tid;
            int row = idx >> 3;
            int col8 = (idx & 7) * 8;
            size_t gb = (size_t)row * INC + c * 64 + col8;
            uint32_t so = row * LDB + col8 * 2;
            cp16(dBh + so, g_w2h + gb);
        }
    };
    auto compute = [&](int buf) {
        const uint32_t* Ahw = (const uint32_t*)(smem + buf * G2_BUF);
        const uint32_t* Bhw = (const uint32_t*)(smem + buf * G2_BUF + ATILE);
        #pragma unroll
        for (int kk = 0; kk < 4; kk++) {
            const int kw = kk * 8;
            uint32_t bh[4][2];
            #pragma unroll
            for (int nt = 0; nt < 4; nt++) {
                int w0 = (wn * 32 + nt * 8 + g) * LDW + kw + t;
                bh[nt][0] = Bhw[w0]; bh[nt][1] = Bhw[w0 + 4];
            }
            {
                int w0 = (wm * 16 + g) * LDW + kw + t;
                uint32_t ah[4];
                ah[0] = Ahw[w0]; ah[1] = Ahw[w0 + 8 * LDW];
                ah[2] = Ahw[w0 + 4]; ah[3] = Ahw[w0 + 8 * LDW + 4];
                #pragma unroll
                for (int nt = 0; nt < 4; nt++)
                    mma_bf16(acc[nt], ah, bh[nt]);
            }
        }
    };

    stage(0, 0); CP_COMMIT();
    CP_WAIT0(); __syncthreads();
    #pragma unroll
    for (int c = 0; c < 4; c++) {
        int buf = c & 1;
        if (c < 3) { stage(c + 1, buf ^ 1); CP_COMMIT(); }
        compute(buf);
        if (c < 3) { CP_WAIT0(); __syncthreads(); }
    }

    {
        int row0 = bm + wm * 16 + g;
        int row1 = row0 + 8;
        float s0 = 0.f, s1 = 0.f, d0 = 0.f, d1 = 0.f;
        #pragma unroll
        for (int nt = 0; nt < 4; nt++) {
            int lcol = wn * 32 + nt * 8 + 2 * t;
            float as0 = sAs[lcol], as1 = sAs[lcol + 1];
            float ad0 = sAd[lcol], ad1 = sAd[lcol + 1];
            s0 += acc[nt][0] * as0 + acc[nt][1] * as1;
            s1 += acc[nt][2] * as0 + acc[nt][3] * as1;
            d0 += acc[nt][0] * ad0 + acc[nt][1] * ad1;
            d1 += acc[nt][2] * ad0 + acc[nt][3] * ad1;
            if (lcol < OC) {
                if (row0 < Nn)
                    *(float2*)(g_h2 + (size_t)row0 * OC + lcol) = make_float2(acc[nt][0], acc[nt][1]);
                if (row1 < Nn)
                    *(float2*)(g_h2 + (size_t)row1 * OC + lcol) = make_float2(acc[nt][2], acc[nt][3]);
            }
        }
        s0 += __shfl_down_sync(0xffffffffu, s0, 2); s0 += __shfl_down_sync(0xffffffffu, s0, 1);
        s1 += __shfl_down_sync(0xffffffffu, s1, 2); s1 += __shfl_down_sync(0xffffffffu, s1, 1);
        d0 += __shfl_down_sync(0xffffffffu, d0, 2); d0 += __shfl_down_sync(0xffffffffu, d0, 1);
        d1 += __shfl_down_sync(0xffffffffu, d1, 2); d1 += __shfl_down_sync(0xffffffffu, d1, 1);
        if (t == 0) {
            int r0 = wm * 16 + g, r1 = r0 + 8;
            atomicAdd(&red2[0][r0], s0);
            atomicAdd(&red2[0][r1], s1);
            atomicAdd(&red2[1][r0], d0);
            atomicAdd(&red2[1][r1], d1);
        }
    }
    __syncthreads();
    if (tid < 128) {
        int n = bm + tid;
        if (n < Nn) {
            g_als2[n] = red2[0][tid];
            g_ald2[n] = red2[1][tid];
        }
    }
}

// ---------------- layer 1: 128-thread blocks, 2 slots, MLP-8 gathers -----------
__global__ __launch_bounds__(128) void agg1_kernel(const float* __restrict__ b1) {
    int d = blockIdx.x;
    int start = g_rowptr[d], end = g_rowptr[d + 1];
    int tid = threadIdx.x;
    __shared__ float sden[NH];
    __shared__ int ssrc[128];
    __shared__ float salpha[128 * NH];
    __shared__ float4 sacc[2 * 64];

    if (tid < NH) sden[tid] = 1e-16f;
    float4 aldv = *(const float4*)&g_ald1[d * NH];

    const int ch4 = tid & 63;
    const int slot = tid >> 6;
    const int head = ch4 >> 4;
    float4 acc = make_float4(0.f, 0.f, 0.f, 0.f);
    float p0 = 0.f, p1 = 0.f, p2 = 0.f, p3 = 0.f;

    for (int base = start; base < end; base += 128) {
        int cnt = min(128, end - base);
        __syncthreads();
        if (tid < cnt) {
            int s = g_srcl[base + tid];
            ssrc[tid] = s;
            float4 als = *(const float4*)&g_als1[s * NH];
            float e0 = __expf(lrelu(als.x + aldv.x));
            float e1 = __expf(lrelu(als.y + aldv.y));
            float e2 = __expf(lrelu(als.z + aldv.z));
            float e3 = __expf(lrelu(als.w + aldv.w));
            salpha[tid * 4 + 0] = e0; salpha[tid * 4 + 1] = e1;
            salpha[tid * 4 + 2] = e2; salpha[tid * 4 + 3] = e3;
            p0 += e0; p1 += e1; p2 += e2; p3 += e3;
        }
        __syncthreads();
        int j = slot;
        // MLP-8: edges j, j+2, ..., j+14 all in flight
        for (; j + 14 < cnt; j += 16) {
            float av[8];
            uint2 hv[8];
            #pragma unroll
            for (int q = 0; q < 8; q++) {
                int e = j + q * 2;
                av[q] = salpha[e * 4 + head];
                hv[q] = *(const uint2*)(g_h1b + (size_t)ssrc[e] * HC + ch4 * 4);
            }
            #pragma unroll
            for (int q = 0; q < 8; q++) {
                float2 f0 = __bfloat1622float2(*(const __nv_bfloat162*)&hv[q].x);
                float2 f1 = __bfloat1622float2(*(const __nv_bfloat162*)&hv[q].y);
                acc.x = fmaf(av[q], f0.x, acc.x);
                acc.y = fmaf(av[q], f0.y, acc.y);
                acc.z = fmaf(av[q], f1.x, acc.z);
                acc.w = fmaf(av[q], f1.y, acc.w);
            }
        }
        // MLP-4 strip
        for (; j + 6 < cnt; j += 8) {
            float av[4];
            uint2 hv[4];
            #pragma unroll
            for (int q = 0; q < 4; q++) {
                int e = j + q * 2;
                av[q] = salpha[e * 4 + head];
                hv[q] = *(const uint2*)(g_h1b + (size_t)ssrc[e] * HC + ch4 * 4);
            }
            #pragma unroll
            for (int q = 0; q < 4; q++) {
                float2 f0 = __bfloat1622float2(*(const __nv_bfloat162*)&hv[q].x);
                float2 f1 = __bfloat1622float2(*(const __nv_bfloat162*)&hv[q].y);
                acc.x = fmaf(av[q], f0.x, acc.x);
                acc.y = fmaf(av[q], f0.y, acc.y);
                acc.z = fmaf(av[q], f1.x, acc.z);
                acc.w = fmaf(av[q], f1.y, acc.w);
            }
        }
        for (; j < cnt; j += 2) {
            float a = salpha[j * 4 + head];
            int s = ssrc[j];
            uint2 hv = *(const uint2*)(g_h1b + (size_t)s * HC + ch4 * 4);
            float2 f0 = __bfloat1622float2(*(const __nv_bfloat162*)&hv.x);
            float2 f1 = __bfloat1622float2(*(const __nv_bfloat162*)&hv.y);
            acc.x = fmaf(a, f0.x, acc.x);
            acc.y = fmaf(a, f0.y, acc.y);
            acc.z = fmaf(a, f1.x, acc.z);
            acc.w = fmaf(a, f1.y, acc.w);
        }
    }
    #pragma unroll
    for (int off = 16; off; off >>= 1) {
        p0 += __shfl_down_sync(0xffffffffu, p0, off);
        p1 += __shfl_down_sync(0xffffffffu, p1, off);
        p2 += __shfl_down_sync(0xffffffffu, p2, off);
        p3 += __shfl_down_sync(0xffffffffu, p3, off);
    }
    if ((tid & 31) == 0) {
        atomicAdd(&sden[0], p0);
        atomicAdd(&sden[1], p1);
        atomicAdd(&sden[2], p2);
        atomicAdd(&sden[3], p3);
    }
    sacc[slot * 64 + ch4] = acc;
    __syncthreads();
    if (tid < 64) {
        float4 a0 = sacc[tid], a1 = sacc[64 + tid];
        float rd = 1.f / sden[tid >> 4];
        int ch = tid * 4;
        float4 bb = *(const float4*)(b1 + ch);
        float4 r;
        r.x = fmaxf((a0.x + a1.x) * rd + bb.x, 0.f);
        r.y = fmaxf((a0.y + a1.y) * rd + bb.y, 0.f);
        r.z = fmaxf((a0.z + a1.z) * rd + bb.z, 0.f);
        r.w = fmaxf((a0.w + a1.w) * rd + bb.w, 0.f);
        *(uint2*)(g_a1h + (size_t)d * HC + ch) = tobf4(r);
    }
}

// ---------------- layer 2: single-pass agg + log_softmax, MLP-4 ---------------
__global__ void agg2_final(const float* __restrict__ b2, float* __restrict__ out) {
    int n = blockIdx.x * 8 + (threadIdx.x >> 5);
    if (n >= Nn) return;
    int lane = threadIdx.x & 31;
    int start = g_rowptr[n], end = g_rowptr[n + 1];
    float ald = g_ald2[n];

    float den = 0.f, acc0 = 0.f, acc1 = 0.f;
    for (int base = start; base < end; base += 32) {
        int i = base + lane;
        int s = 0; float e = 0.f;
        if (i < end) {
            s = g_srcl[i];
            e = __expf(lrelu(g_als2[s] + ald));
        }
        den += e;
        int cnt = min(32, end - base);
        int j = 0;
        for (; j + 3 < cnt; j += 4) {
            int   sj0 = __shfl_sync(0xffffffffu, s, j);
            int   sj1 = __shfl_sync(0xffffffffu, s, j + 1);
            int   sj2 = __shfl_sync(0xffffffffu, s, j + 2);
            int   sj3 = __shfl_sync(0xffffffffu, s, j + 3);
            float ej0 = __shfl_sync(0xffffffffu, e, j);
            float ej1 = __shfl_sync(0xffffffffu, e, j + 1);
            float ej2 = __shfl_sync(0xffffffffu, e, j + 2);
            float ej3 = __shfl_sync(0xffffffffu, e, j + 3);
            float v0 = g_h2[sj0 * OC + lane];
            float v1 = g_h2[sj1 * OC + lane];
            float v2 = g_h2[sj2 * OC + lane];
            float v3 = g_h2[sj3 * OC + lane];
            float w0 = 0.f, w1 = 0.f, w2 = 0.f, w3 = 0.f;
            if (lane < 8) {
                w0 = g_h2[sj0 * OC + 32 + lane];
                w1 = g_h2[sj1 * OC + 32 + lane];
                w2 = g_h2[sj2 * OC + 32 + lane];
                w3 = g_h2[sj3 * OC + 32 + lane];
            }
            acc0 = fmaf(ej0, v0, acc0); acc0 = fmaf(ej1, v1, acc0);
            acc0 = fmaf(ej2, v2, acc0); acc0 = fmaf(ej3, v3, acc0);
            acc1 = fmaf(ej0, w0, acc1); acc1 = fmaf(ej1, w1, acc1);
            acc1 = fmaf(ej2, w2, acc1); acc1 = fmaf(ej3, w3, acc1);
        }
        for (; j < cnt; j++) {
            int   sj = __shfl_sync(0xffffffffu, s, j);
            float ej = __shfl_sync(0xffffffffu, e, j);
            acc0 = fmaf(ej, g_h2[sj * OC + lane], acc0);
            if (lane < 8) acc1 = fmaf(ej, g_h2[sj * OC + 32 + lane], acc1);
        }
    }
    #pragma unroll
    for (int off = 16; off; off >>= 1)
        den += __shfl_xor_sync(0xffffffffu, den, off);
    float rden = 1.f / (den + 1e-16f);

    float v0 = acc0 * rden + b2[lane];
    float v1 = (lane < 8) ? (acc1 * rden + b2[32 + lane]) : -3.402823466e38f;
    float mx = fmaxf(v0, v1);
    #pragma unroll
    for (int off = 16; off; off >>= 1)
        mx = fmaxf(mx, __shfl_xor_sync(0xffffffffu, mx, off));
    float se = expf(v0 - mx) + ((lane < 8) ? expf(v1 - mx) : 0.f);
    #pragma unroll
    for (int off = 16; off; off >>= 1)
        se += __shfl_xor_sync(0xffffffffu, se, off);
    float lse = mx + logf(se);
    out[n * OC + lane] = v0 - lse;
    if (lane < 8) out[n * OC + 32 + lane] = v1 - lse;
}

// ---------------- launch -----------------------------------------------------
extern "C" void kernel_launch(void* const* d_in, const int* in_sizes, int n_in,
                              void* d_out, int out_size) {
    const float* x      = (const float*)d_in[0];
    const int*   ei     = (const int*)d_in[1];
    const float* W1     = (const float*)d_in[2];
    const float* a_src1 = (const float*)d_in[3];
    const float* a_dst1 = (const float*)d_in[4];
    const float* b1     = (const float*)d_in[5];
    const float* W2     = (const float*)d_in[6];
    const float* a_src2 = (const float*)d_in[7];
    const float* a_dst2 = (const float*)d_in[8];
    const float* b2     = (const float*)d_in[9];
    float* out = (float*)d_out;

    cudaFuncSetAttribute(gemm1_mma, cudaFuncAttributeMaxDynamicSharedMemorySize, G1_SMEM);
    cudaFuncSetAttribute(gemm2_mma, cudaFuncAttributeMaxDynamicSharedMemorySize, G2_SMEM);

    convert_w<<<(INC * HC + 64 * INC + 255) / 256, 256>>>(W1, W2);
    gemm1_mma<<<MTILES * 2 + HBLK, 512, G1_SMEM>>>(x, ei, a_src1, a_dst1);
    scan_fused<<<NB, 256>>>();
    fill_kernel<<<(Ee / 8 + Nn + 255) / 256, 256>>>(ei);
    agg1_kernel<<<Nn, 128>>>(b1);
    gemm2_mma<<<MTILES, 512, G2_SMEM>>>(a_src2, a_dst2);
    agg2_final<<<(Nn + 7) / 8, 256>>>(b2, out);
}

// round 16
// speedup vs baseline: 2.7626x; 1.1748x over previous
#include <cuda_runtime.h>
#include <cuda_bf16.h>
#include <cstdint>

#define Nn 50000
#define Ee 800000
#define ET (Ee + Nn)
#define INC 256
#define HC 256
#define NH 4
#define OC 40
#define NB ((Nn + 255) / 256)

#define MT 128
#define MTILES ((Nn + MT - 1) / MT)
#define PADN (MTILES * MT)
#define HBLK 391

// ---------------- scratch ----------------------------------------------------
__device__ __align__(16) __nv_bfloat16 g_h1b[(size_t)Nn * HC];
__device__ float g_als1[Nn * NH];
__device__ float g_ald1[Nn * NH];
__device__ float g_h2[Nn * OC];
__device__ float g_als2[Nn];
__device__ float g_ald2[Nn];
__device__ int g_counts[Nn];
__device__ int g_fill[Nn];
__device__ int g_rowptr[Nn + 1];
__device__ int g_srcl[ET];
__device__ __align__(16) __nv_bfloat16 g_w1h[INC * HC];
__device__ __align__(16) __nv_bfloat16 g_w2h[64 * INC];
__device__ __align__(16) __nv_bfloat16 g_a1h[(size_t)PADN * HC];

// ---------------- helpers ----------------------------------------------------
__device__ __forceinline__ float lrelu(float v) { return (v > 0.f) ? v : 0.2f * v; }
__device__ __forceinline__ uint32_t pack2(__nv_bfloat16 a, __nv_bfloat16 b) {
    __nv_bfloat162 t; t.x = a; t.y = b;
    return *reinterpret_cast<uint32_t*>(&t);
}
__device__ __forceinline__ uint2 tobf4(float4 v) {
    uint2 r;
    r.x = pack2(__float2bfloat16(v.x), __float2bfloat16(v.y));
    r.y = pack2(__float2bfloat16(v.z), __float2bfloat16(v.w));
    return r;
}
__device__ __forceinline__ uint32_t smem_u32(const void* p) {
    uint32_t a;
    asm("{ .reg .u64 t; cvta.to.shared.u64 t, %1; cvt.u32.u64 %0, t; }" : "=r"(a) : "l"(p));
    return a;
}
__device__ __forceinline__ void cp16(uint32_t dst, const void* src) {
    asm volatile("cp.async.ca.shared.global [%0], [%1], 16;" :: "r"(dst), "l"(src));
}
#define CP_COMMIT() asm volatile("cp.async.commit_group;" ::: "memory")
#define CP_WAIT0()  asm volatile("cp.async.wait_group 0;" ::: "memory")

// ---------------- convert_w + init (fused) -------------------------------------
__global__ void convert_w(const float* __restrict__ W1, const float* __restrict__ W2) {
    int t = blockIdx.x * blockDim.x + threadIdx.x;
    if (t < INC * HC) {
        int k = t >> 8, n = t & 255;
        g_w1h[n * INC + k] = __float2bfloat16(W1[t]);
    } else if (t < INC * HC + 64 * INC) {
        int u = t - INC * HC;
        int n = u >> 8, k = u & 255;
        float v = (n < OC) ? W2[k * OC + n] : 0.f;
        g_w2h[n * INC + k] = __float2bfloat16(v);
    }
    if (t < Nn) { g_counts[t] = 1; g_fill[t] = 0; }
}

// ---------------- fused single-pass scan ----------------------------------------
__global__ void scan_fused() {
    __shared__ int ws[8];
    int j = blockIdx.x;
    int tid = threadIdx.x;
    int lane = tid & 31, warp = tid >> 5;

    int off = 0;
    for (int i = tid; i < j * 256; i += 256) off += g_counts[i];
    #pragma unroll
    for (int o = 16; o; o >>= 1) off += __shfl_down_sync(0xffffffffu, off, o);
    if (lane == 0) ws[warp] = off;
    __syncthreads();
    if (warp == 0) {
        int w = (lane < 8) ? ws[lane] : 0;
        #pragma unroll
        for (int o = 4; o; o >>= 1) w += __shfl_down_sync(0xffffffffu, w, o);
        if (lane == 0) ws[0] = w;
    }
    __syncthreads();
    int total_off = ws[0];
    __syncthreads();

    int idx = j * 256 + tid;
    int v = (idx < Nn) ? g_counts[idx] : 0;
    #pragma unroll
    for (int o = 1; o < 32; o <<= 1) {
        int u = __shfl_up_sync(0xffffffffu, v, o);
        if (lane >= o) v += u;
    }
    if (lane == 31) ws[warp] = v;
    __syncthreads();
    if (warp == 0 && lane < 8) {
        int w = ws[lane];
        #pragma unroll
        for (int o = 1; o < 8; o <<= 1) {
            int u = __shfl_up_sync(0xffu, w, o);
            if (lane >= o) w += u;
        }
        ws[lane] = w;
    }
    __syncthreads();
    if (warp > 0) v += ws[warp - 1];
    if (idx < Nn) g_rowptr[idx + 1] = v + total_off;
    if (j == 0 && tid == 0) g_rowptr[0] = 0;
}

// ---------------- fill: 4 edges per thread (round-14 proven shape) --------------
__global__ void fill_kernel(const int* __restrict__ ei) {
    const int Q = Ee / 4;
    int i = blockIdx.x * blockDim.x + threadIdx.x;
    if (i < Q) {
        int4 s = ((const int4*)ei)[i];
        int4 d = ((const int4*)(ei + Ee))[i];
        int p;
        p = g_rowptr[d.x] + atomicAdd(&g_fill[d.x], 1); g_srcl[p] = s.x;
        p = g_rowptr[d.y] + atomicAdd(&g_fill[d.y], 1); g_srcl[p] = s.y;
        p = g_rowptr[d.z] + atomicAdd(&g_fill[d.z], 1); g_srcl[p] = s.z;
        p = g_rowptr[d.w] + atomicAdd(&g_fill[d.w], 1); g_srcl[p] = s.w;
    } else {
        int n = i - Q;
        if (n < Nn) {
            int p = g_rowptr[n] + atomicAdd(&g_fill[n], 1);
            g_srcl[p] = n;
        }
    }
}

// ---------------- GEMM common ---------------------------------------------------
#define LDW 36
#define LDB 144
#define ATILE (128 * LDB)

__device__ __forceinline__ void mma_bf16(float* c, const uint32_t* a, const uint32_t* b) {
    asm volatile(
        "mma.sync.aligned.m16n8k16.row.col.f32.bf16.bf16.f32 "
        "{%0,%1,%2,%3}, {%4,%5,%6,%7}, {%8,%9}, {%0,%1,%2,%3};"
        : "+f"(c[0]), "+f"(c[1]), "+f"(c[2]), "+f"(c[3])
        : "r"(a[0]), "r"(a[1]), "r"(a[2]), "r"(a[3]), "r"(b[0]), "r"(b[1]));
}

// ---------------- GEMM1 (+ hist): h1b = bf16(x @ W1), pure bf16 ----------------
#define G1_BUF (2 * ATILE)
#define G1_SMEM (2 * G1_BUF)

__global__ void __launch_bounds__(512, 1)
gemm1_mma(const float* __restrict__ X, const int* __restrict__ ei,
          const float* __restrict__ a_src, const float* __restrict__ a_dst) {
    if (blockIdx.x >= MTILES * 2) {
        int i = (blockIdx.x - MTILES * 2) * 512 + threadIdx.x;
        if (i < Ee / 4) {
            int4 d = ((const int4*)(ei + Ee))[i];
            atomicAdd(&g_counts[d.x], 1);
            atomicAdd(&g_counts[d.y], 1);
            atomicAdd(&g_counts[d.z], 1);
            atomicAdd(&g_counts[d.w], 1);
        }
        return;
    }

    extern __shared__ char smem[];
    __shared__ float sAs[128], sAd[128];
    __shared__ float red[4][2][2][32];

    const int tid = threadIdx.x;
    const int wid = tid >> 5;
    const int lane = tid & 31;
    const int wm = wid >> 2;
    const int wn = wid & 3;
    const int g = lane >> 2;
    const int t = lane & 3;
    const int hl = wn >> 1;

    const int bm = (blockIdx.x >> 1) * MT;
    const int bn = (blockIdx.x & 1) * 128;

    const uint32_t sb = smem_u32(smem);

    if (tid < 128) { sAs[tid] = a_src[bn + tid]; sAd[tid] = a_dst[bn + tid]; }
    ((float*)red)[tid] = 0.f;

    float acc[2][4][4] = {};
    float4 aregs[4];

    auto loadA = [&](int c) {
        #pragma unroll
        for (int i = 0; i < 4; i++) {
            int idx = i * 512 + tid;
            int row = idx >> 4;
            int col4 = (idx & 15) * 4;
            int grow = bm + row;
            aregs[i] = (grow < Nn)
                ? *(const float4*)(X + (size_t)grow * INC + c * 64 + col4)
                : make_float4(0.f, 0.f, 0.f, 0.f);
        }
    };
    auto storeA = [&](int buf) {
        char* sAh = smem + buf * G1_BUF;
        #pragma unroll
        for (int i = 0; i < 4; i++) {
            int idx = i * 512 + tid;
            int row = idx >> 4;
            int col4 = (idx & 15) * 4;
            int so = row * LDB + col4 * 2;
            *(uint2*)(sAh + so) = tobf4(aregs[i]);
        }
    };
    auto cpB = [&](int c, int buf) {
        uint32_t dBh = sb + buf * G1_BUF + ATILE;
        #pragma unroll
        for (int i = 0; i < 2; i++) {
            int idx = i * 512 + tid;
            int row = idx >> 3;
            int col8 = (idx & 7) * 8;
            size_t gb = (size_t)(bn + row) * INC + c * 64 + col8;
            uint32_t so = row * LDB + col8 * 2;
            cp16(dBh + so, g_w1h + gb);
        }
    };
    auto compute = [&](int buf) {
        const uint32_t* Ahw = (const uint32_t*)(smem + buf * G1_BUF);
        const uint32_t* Bhw = (const uint32_t*)(smem + buf * G1_BUF + ATILE);
        #pragma unroll
        for (int kk = 0; kk < 4; kk++) {
            const int kw = kk * 8;
            uint32_t bh[4][2];
            #pragma unroll
            for (int nt = 0; nt < 4; nt++) {
                int w0 = (wn * 32 + nt * 8 + g) * LDW + kw + t;
                bh[nt][0] = Bhw[w0]; bh[nt][1] = Bhw[w0 + 4];
            }
            #pragma unroll
            for (int mt = 0; mt < 2; mt++) {
                int w0 = (wm * 32 + mt * 16 + g) * LDW + kw + t;
                uint32_t ah[4];
                ah[0] = Ahw[w0]; ah[1] = Ahw[w0 + 8 * LDW];
                ah[2] = Ahw[w0 + 4]; ah[3] = Ahw[w0 + 8 * LDW + 4];
                #pragma unroll
                for (int nt = 0; nt < 4; nt++)
                    mma_bf16(acc[mt][nt], ah, bh[nt]);
            }
        }
    };

    loadA(0); cpB(0, 0); CP_COMMIT(); storeA(0);
    CP_WAIT0(); __syncthreads();
    #pragma unroll
    for (int c = 0; c < 4; c++) {
        int buf = c & 1;
        if (c < 3) { loadA(c + 1); cpB(c + 1, buf ^ 1); CP_COMMIT(); }
        compute(buf);
        if (c < 3) { storeA(buf ^ 1); CP_WAIT0(); __syncthreads(); }
    }

    #pragma unroll
    for (int mt = 0; mt < 2; mt++) {
        int row0 = bm + wm * 32 + mt * 16 + g;
        int row1 = row0 + 8;
        float s0 = 0.f, s1 = 0.f, d0 = 0.f, d1 = 0.f;
        #pragma unroll
        for (int nt = 0; nt < 4; nt++) {
            int lcol = wn * 32 + nt * 8 + 2 * t;
            int col = bn + lcol;
            float as0 = sAs[lcol], as1 = sAs[lcol + 1];
            float ad0 = sAd[lcol], ad1 = sAd[lcol + 1];
            s0 += acc[mt][nt][0] * as0 + acc[mt][nt][1] * as1;
            s1 += acc[mt][nt][2] * as0 + acc[mt][nt][3] * as1;
            d0 += acc[mt][nt][0] * ad0 + acc[mt][nt][1] * ad1;
            d1 += acc[mt][nt][2] * ad0 + acc[mt][nt][3] * ad1;
            if (row0 < Nn)
                *(uint32_t*)(g_h1b + (size_t)row0 * HC + col) =
                    pack2(__float2bfloat16(acc[mt][nt][0]), __float2bfloat16(acc[mt][nt][1]));
            if (row1 < Nn)
                *(uint32_t*)(g_h1b + (size_t)row1 * HC + col) =
                    pack2(__float2bfloat16(acc[mt][nt][2]), __float2bfloat16(acc[mt][nt][3]));
        }
        s0 += __shfl_down_sync(0xffffffffu, s0, 2); s0 += __shfl_down_sync(0xffffffffu, s0, 1);
        s1 += __shfl_down_sync(0xffffffffu, s1, 2); s1 += __shfl_down_sync(0xffffffffu, s1, 1);
        d0 += __shfl_down_sync(0xffffffffu, d0, 2); d0 += __shfl_down_sync(0xffffffffu, d0, 1);
        d1 += __shfl_down_sync(0xffffffffu, d1, 2); d1 += __shfl_down_sync(0xffffffffu, d1, 1);
        if (t == 0) {
            int r0 = mt * 16 + g, r1 = r0 + 8;
            atomicAdd(&red[wm][hl][0][r0], s0);
            atomicAdd(&red[wm][hl][0][r1], s1);
            atomicAdd(&red[wm][hl][1][r0], d0);
            atomicAdd(&red[wm][hl][1][r1], d1);
        }
    }
    __syncthreads();
    if (tid < 128) {
        int n = bm + tid;
        if (n < Nn) {
            int w = tid >> 5, r = tid & 31;
            #pragma unroll
            for (int h = 0; h < 2; h++) {
                int head = (bn >> 6) + h;
                g_als1[n * NH + head] = red[w][h][0][r];
                g_ald1[n * NH + head] = red[w][h][1][r];
            }
        }
    }
}

// ---------------- GEMM2: h2 = agg1 @ W2, pure bf16 ------------------------------
#define BTILE2 (64 * LDB)
#define G2_BUF (ATILE + BTILE2)
#define G2_SMEM (2 * G2_BUF)

__global__ void __launch_bounds__(512, 1)
gemm2_mma(const float* __restrict__ a_src, const float* __restrict__ a_dst) {
    extern __shared__ char smem[];
    __shared__ float sAs[64], sAd[64];
    __shared__ float red2[2][128];

    const int tid = threadIdx.x;
    const int wid = tid >> 5;
    const int lane = tid & 31;
    const int wm = wid >> 1;
    const int wn = wid & 1;
    const int g = lane >> 2;
    const int t = lane & 3;

    const int bm = blockIdx.x * MT;
    const uint32_t sb = smem_u32(smem);

    if (tid < 64) { sAs[tid] = (tid < OC) ? a_src[tid] : 0.f;
                    sAd[tid] = (tid < OC) ? a_dst[tid] : 0.f; }
    if (tid < 256) ((float*)red2)[tid] = 0.f;

    float acc[4][4] = {};

    auto stage = [&](int c, int buf) {
        uint32_t dAh = sb + buf * G2_BUF;
        uint32_t dBh = dAh + ATILE;
        #pragma unroll
        for (int i = 0; i < 2; i++) {
            int idx = i * 512 + tid;
            int row = idx >> 3;
            int col8 = (idx & 7) * 8;
            size_t ga = (size_t)(bm + row) * HC + c * 64 + col8;
            uint32_t so = row * LDB + col8 * 2;
            cp16(dAh + so, g_a1h + ga);
        }
        {
            int idx = tid;
            int row = idx >> 3;
            int col8 = (idx & 7) * 8;
            size_t gb = (size_t)row * INC + c * 64 + col8;
            uint32_t so = row * LDB + col8 * 2;
            cp16(dBh + so, g_w2h + gb);
        }
    };
    auto compute = [&](int buf) {
        const uint32_t* Ahw = (const uint32_t*)(smem + buf * G2_BUF);
        const uint32_t* Bhw = (const uint32_t*)(smem + buf * G2_BUF + ATILE);
        #pragma unroll
        for (int kk = 0; kk < 4; kk++) {
            const int kw = kk * 8;
            uint32_t bh[4][2];
            #pragma unroll
            for (int nt = 0; nt < 4; nt++) {
                int w0 = (wn * 32 + nt * 8 + g) * LDW + kw + t;
                bh[nt][0] = Bhw[w0]; bh[nt][1] = Bhw[w0 + 4];
            }
            {
                int w0 = (wm * 16 + g) * LDW + kw + t;
                uint32_t ah[4];
                ah[0] = Ahw[w0]; ah[1] = Ahw[w0 + 8 * LDW];
                ah[2] = Ahw[w0 + 4]; ah[3] = Ahw[w0 + 8 * LDW + 4];
                #pragma unroll
                for (int nt = 0; nt < 4; nt++)
                    mma_bf16(acc[nt], ah, bh[nt]);
            }
        }
    };

    stage(0, 0); CP_COMMIT();
    CP_WAIT0(); __syncthreads();
    #pragma unroll
    for (int c = 0; c < 4; c++) {
        int buf = c & 1;
        if (c < 3) { stage(c + 1, buf ^ 1); CP_COMMIT(); }
        compute(buf);
        if (c < 3) { CP_WAIT0(); __syncthreads(); }
    }

    {
        int row0 = bm + wm * 16 + g;
        int row1 = row0 + 8;
        float s0 = 0.f, s1 = 0.f, d0 = 0.f, d1 = 0.f;
        #pragma unroll
        for (int nt = 0; nt < 4; nt++) {
            int lcol = wn * 32 + nt * 8 + 2 * t;
            float as0 = sAs[lcol], as1 = sAs[lcol + 1];
            float ad0 = sAd[lcol], ad1 = sAd[lcol + 1];
            s0 += acc[nt][0] * as0 + acc[nt][1] * as1;
            s1 += acc[nt][2] * as0 + acc[nt][3] * as1;
            d0 += acc[nt][0] * ad0 + acc[nt][1] * ad1;
            d1 += acc[nt][2] * ad0 + acc[nt][3] * ad1;
            if (lcol < OC) {
                if (row0 < Nn)
                    *(float2*)(g_h2 + (size_t)row0 * OC + lcol) = make_float2(acc[nt][0], acc[nt][1]);
                if (row1 < Nn)
                    *(float2*)(g_h2 + (size_t)row1 * OC + lcol) = make_float2(acc[nt][2], acc[nt][3]);
            }
        }
        s0 += __shfl_down_sync(0xffffffffu, s0, 2); s0 += __shfl_down_sync(0xffffffffu, s0, 1);
        s1 += __shfl_down_sync(0xffffffffu, s1, 2); s1 += __shfl_down_sync(0xffffffffu, s1, 1);
        d0 += __shfl_down_sync(0xffffffffu, d0, 2); d0 += __shfl_down_sync(0xffffffffu, d0, 1);
        d1 += __shfl_down_sync(0xffffffffu, d1, 2); d1 += __shfl_down_sync(0xffffffffu, d1, 1);
        if (t == 0) {
            int r0 = wm * 16 + g, r1 = r0 + 8;
            atomicAdd(&red2[0][r0], s0);
            atomicAdd(&red2[0][r1], s1);
            atomicAdd(&red2[1][r0], d0);
            atomicAdd(&red2[1][r1], d1);
        }
    }
    __syncthreads();
    if (tid < 128) {
        int n = bm + tid;
        if (n < Nn) {
            g_als2[n] = red2[0][tid];
            g_ald2[n] = red2[1][tid];
        }
    }
}

// ---------------- layer 1: 64-thread blocks, 1 slot, MLP-8 gathers -------------
__global__ __launch_bounds__(64) void agg1_kernel(const float* __restrict__ b1) {
    int d = blockIdx.x;
    int start = g_rowptr[d], end = g_rowptr[d + 1];
    int tid = threadIdx.x;
    __shared__ float sden[NH];
    __shared__ int ssrc[64];
    __shared__ float salpha[64 * NH];

    if (tid < NH) sden[tid] = 1e-16f;
    float4 aldv = *(const float4*)&g_ald1[d * NH];

    const int ch4 = tid;            // channels [tid*4, tid*4+4)
    const int head = tid >> 4;
    float4 acc = make_float4(0.f, 0.f, 0.f, 0.f);
    float p0 = 0.f, p1 = 0.f, p2 = 0.f, p3 = 0.f;

    for (int base = start; base < end; base += 64) {
        int cnt = min(64, end - base);
        __syncthreads();
        if (tid < cnt) {
            int s = g_srcl[base + tid];
            ssrc[tid] = s;
            float4 als = *(const float4*)&g_als1[s * NH];
            float e0 = __expf(lrelu(als.x + aldv.x));
            float e1 = __expf(lrelu(als.y + aldv.y));
            float e2 = __expf(lrelu(als.z + aldv.z));
            float e3 = __expf(lrelu(als.w + aldv.w));
            salpha[tid * 4 + 0] = e0; salpha[tid * 4 + 1] = e1;
            salpha[tid * 4 + 2] = e2; salpha[tid * 4 + 3] = e3;
            p0 += e0; p1 += e1; p2 += e2; p3 += e3;
        }
        __syncthreads();
        int j = 0;
        // MLP-8
        for (; j + 7 < cnt; j += 8) {
            float av[8];
            uint2 hv[8];
            #pragma unroll
            for (int q = 0; q < 8; q++) {
                av[q] = salpha[(j + q) * 4 + head];
                hv[q] = *(const uint2*)(g_h1b + (size_t)ssrc[j + q] * HC + ch4 * 4);
            }
            #pragma unroll
            for (int q = 0; q < 8; q++) {
                float2 f0 = __bfloat1622float2(*(const __nv_bfloat162*)&hv[q].x);
                float2 f1 = __bfloat1622float2(*(const __nv_bfloat162*)&hv[q].y);
                acc.x = fmaf(av[q], f0.x, acc.x);
                acc.y = fmaf(av[q], f0.y, acc.y);
                acc.z = fmaf(av[q], f1.x, acc.z);
                acc.w = fmaf(av[q], f1.y, acc.w);
            }
        }
        // MLP-4 strip
        for (; j + 3 < cnt; j += 4) {
            float av[4];
            uint2 hv[4];
            #pragma unroll
            for (int q = 0; q < 4; q++) {
                av[q] = salpha[(j + q) * 4 + head];
                hv[q] = *(const uint2*)(g_h1b + (size_t)ssrc[j + q] * HC + ch4 * 4);
            }
            #pragma unroll
            for (int q = 0; q < 4; q++) {
                float2 f0 = __bfloat1622float2(*(const __nv_bfloat162*)&hv[q].x);
                float2 f1 = __bfloat1622float2(*(const __nv_bfloat162*)&hv[q].y);
                acc.x = fmaf(av[q], f0.x, acc.x);
                acc.y = fmaf(av[q], f0.y, acc.y);
                acc.z = fmaf(av[q], f1.x, acc.z);
                acc.w = fmaf(av[q], f1.y, acc.w);
            }
        }
        for (; j < cnt; j++) {
            float a = salpha[j * 4 + head];
            uint2 hv = *(const uint2*)(g_h1b + (size_t)ssrc[j] * HC + ch4 * 4);
            float2 f0 = __bfloat1622float2(*(const __nv_bfloat162*)&hv.x);
            float2 f1 = __bfloat1622float2(*(const __nv_bfloat162*)&hv.y);
            acc.x = fmaf(a, f0.x, acc.x);
            acc.y = fmaf(a, f0.y, acc.y);
            acc.z = fmaf(a, f1.x, acc.z);
            acc.w = fmaf(a, f1.y, acc.w);
        }
    }
    // denominator reduction: 2 warps
    #pragma unroll
    for (int off = 16; off; off >>= 1) {
        p0 += __shfl_down_sync(0xffffffffu, p0, off);
        p1 += __shfl_down_sync(0xffffffffu, p1, off);
        p2 += __shfl_down_sync(0xffffffffu, p2, off);
        p3 += __shfl_down_sync(0xffffffffu, p3, off);
    }
    if ((tid & 31) == 0) {
        atomicAdd(&sden[0], p0);
        atomicAdd(&sden[1], p1);
        atomicAdd(&sden[2], p2);
        atomicAdd(&sden[3], p3);
    }
    __syncthreads();
    {
        float rd = 1.f / sden[head];
        int ch = tid * 4;
        float4 bb = *(const float4*)(b1 + ch);
        float4 r;
        r.x = fmaxf(acc.x * rd + bb.x, 0.f);
        r.y = fmaxf(acc.y * rd + bb.y, 0.f);
        r.z = fmaxf(acc.z * rd + bb.z, 0.f);
        r.w = fmaxf(acc.w * rd + bb.w, 0.f);
        *(uint2*)(g_a1h + (size_t)d * HC + ch) = tobf4(r);
    }
}

// ---------------- layer 2: single-pass agg + log_softmax, MLP-4 ---------------
__global__ void agg2_final(const float* __restrict__ b2, float* __restrict__ out) {
    int n = blockIdx.x * 8 + (threadIdx.x >> 5);
    if (n >= Nn) return;
    int lane = threadIdx.x & 31;
    int start = g_rowptr[n], end = g_rowptr[n + 1];
    float ald = g_ald2[n];

    float den = 0.f, acc0 = 0.f, acc1 = 0.f;
    for (int base = start; base < end; base += 32) {
        int i = base + lane;
        int s = 0; float e = 0.f;
        if (i < end) {
            s = g_srcl[i];
            e = __expf(lrelu(g_als2[s] + ald));
        }
        den += e;
        int cnt = min(32, end - base);
        int j = 0;
        for (; j + 3 < cnt; j += 4) {
            int   sj0 = __shfl_sync(0xffffffffu, s, j);
            int   sj1 = __shfl_sync(0xffffffffu, s, j + 1);
            int   sj2 = __shfl_sync(0xffffffffu, s, j + 2);
            int   sj3 = __shfl_sync(0xffffffffu, s, j + 3);
            float ej0 = __shfl_sync(0xffffffffu, e, j);
            float ej1 = __shfl_sync(0xffffffffu, e, j + 1);
            float ej2 = __shfl_sync(0xffffffffu, e, j + 2);
            float ej3 = __shfl_sync(0xffffffffu, e, j + 3);
            float v0 = g_h2[sj0 * OC + lane];
            float v1 = g_h2[sj1 * OC + lane];
            float v2 = g_h2[sj2 * OC + lane];
            float v3 = g_h2[sj3 * OC + lane];
            float w0 = 0.f, w1 = 0.f, w2 = 0.f, w3 = 0.f;
            if (lane < 8) {
                w0 = g_h2[sj0 * OC + 32 + lane];
                w1 = g_h2[sj1 * OC + 32 + lane];
                w2 = g_h2[sj2 * OC + 32 + lane];
                w3 = g_h2[sj3 * OC + 32 + lane];
            }
            acc0 = fmaf(ej0, v0, acc0); acc0 = fmaf(ej1, v1, acc0);
            acc0 = fmaf(ej2, v2, acc0); acc0 = fmaf(ej3, v3, acc0);
            acc1 = fmaf(ej0, w0, acc1); acc1 = fmaf(ej1, w1, acc1);
            acc1 = fmaf(ej2, w2, acc1); acc1 = fmaf(ej3, w3, acc1);
        }
        for (; j < cnt; j++) {
            int   sj = __shfl_sync(0xffffffffu, s, j);
            float ej = __shfl_sync(0xffffffffu, e, j);
            acc0 = fmaf(ej, g_h2[sj * OC + lane], acc0);
            if (lane < 8) acc1 = fmaf(ej, g_h2[sj * OC + 32 + lane], acc1);
        }
    }
    #pragma unroll
    for (int off = 16; off; off >>= 1)
        den += __shfl_xor_sync(0xffffffffu, den, off);
    float rden = 1.f / (den + 1e-16f);

    float v0 = acc0 * rden + b2[lane];
    float v1 = (lane < 8) ? (acc1 * rden + b2[32 + lane]) : -3.402823466e38f;
    float mx = fmaxf(v0, v1);
    #pragma unroll
    for (int off = 16; off; off >>= 1)
        mx = fmaxf(mx, __shfl_xor_sync(0xffffffffu, mx, off));
    float se = expf(v0 - mx) + ((lane < 8) ? expf(v1 - mx) : 0.f);
    #pragma unroll
    for (int off = 16; off; off >>= 1)
        se += __shfl_xor_sync(0xffffffffu, se, off);
    float lse = mx + logf(se);
    out[n * OC + lane] = v0 - lse;
    if (lane < 8) out[n * OC + 32 + lane] = v1 - lse;
}

// ---------------- launch -----------------------------------------------------
extern "C" void kernel_launch(void* const* d_in, const int* in_sizes, int n_in,
                              void* d_out, int out_size) {
    const float* x      = (const float*)d_in[0];
    const int*   ei     = (const int*)d_in[1];
    const float* W1     = (const float*)d_in[2];
    const float* a_src1 = (const float*)d_in[3];
    const float* a_dst1 = (const float*)d_in[4];
    const float* b1     = (const float*)d_in[5];
    const float* W2     = (const float*)d_in[6];
    const float* a_src2 = (const float*)d_in[7];
    const float* a_dst2 = (const float*)d_in[8];
    const float* b2     = (const float*)d_in[9];
    float* out = (float*)d_out;

    cudaFuncSetAttribute(gemm1_mma, cudaFuncAttributeMaxDynamicSharedMemorySize, G1_SMEM);
    cudaFuncSetAttribute(gemm2_mma, cudaFuncAttributeMaxDynamicSharedMemorySize, G2_SMEM);

    convert_w<<<(INC * HC + 64 * INC + 255) / 256, 256>>>(W1, W2);
    gemm1_mma<<<MTILES * 2 + HBLK, 512, G1_SMEM>>>(x, ei, a_src1, a_dst1);
    scan_fused<<<NB, 256>>>();
    fill_kernel<<<(Ee / 4 + Nn + 255) / 256, 256>>>(ei);
    agg1_kernel<<<Nn, 64>>>(b1);
    gemm2_mma<<<MTILES, 512, G2_SMEM>>>(a_src2, a_dst2);
    agg2_final<<<(Nn + 7) / 8, 256>>>(b2, out);
}

// round 17
// speedup vs baseline: 2.8079x; 1.0164x over previous
#include <cuda_runtime.h>
#include <cuda_bf16.h>
#include <cstdint>

#define Nn 50000
#define Ee 800000
#define ET (Ee + Nn)
#define INC 256
#define HC 256
#define NH 4
#define OC 40
#define NB ((Nn + 255) / 256)

#define MT 128
#define MTILES ((Nn + MT - 1) / MT)
#define PADN (MTILES * MT)

// ---------------- scratch ----------------------------------------------------
__device__ __align__(16) __nv_bfloat16 g_h1b[(size_t)Nn * HC];
__device__ float g_als1[Nn * NH];
__device__ float g_ald1[Nn * NH];
__device__ float g_h2[Nn * OC];
__device__ float g_als2[Nn];
__device__ float g_ald2[Nn];
__device__ int g_counts[Nn];
__device__ int g_fill[Nn];
__device__ int g_rowptr[Nn + 1];
__device__ int g_srcl[ET];
__device__ __align__(16) __nv_bfloat16 g_w1h[INC * HC];
__device__ __align__(16) __nv_bfloat16 g_w2h[64 * INC];
__device__ __align__(16) __nv_bfloat16 g_a1h[(size_t)PADN * HC];

// ---------------- helpers ----------------------------------------------------
__device__ __forceinline__ float lrelu(float v) { return (v > 0.f) ? v : 0.2f * v; }
__device__ __forceinline__ uint32_t pack2(__nv_bfloat16 a, __nv_bfloat16 b) {
    __nv_bfloat162 t; t.x = a; t.y = b;
    return *reinterpret_cast<uint32_t*>(&t);
}
__device__ __forceinline__ uint2 tobf4(float4 v) {
    uint2 r;
    r.x = pack2(__float2bfloat16(v.x), __float2bfloat16(v.y));
    r.y = pack2(__float2bfloat16(v.z), __float2bfloat16(v.w));
    return r;
}
__device__ __forceinline__ uint32_t smem_u32(const void* p) {
    uint32_t a;
    asm("{ .reg .u64 t; cvta.to.shared.u64 t, %1; cvt.u32.u64 %0, t; }" : "=r"(a) : "l"(p));
    return a;
}
__device__ __forceinline__ void cp16(uint32_t dst, const void* src) {
    asm volatile("cp.async.ca.shared.global [%0], [%1], 16;" :: "r"(dst), "l"(src));
}
#define CP_COMMIT() asm volatile("cp.async.commit_group;" ::: "memory")
#define CP_WAIT0()  asm volatile("cp.async.wait_group 0;" ::: "memory")

// ---------------- convert_w + init counts --------------------------------------
__global__ void convert_w(const float* __restrict__ W1, const float* __restrict__ W2) {
    int t = blockIdx.x * blockDim.x + threadIdx.x;
    if (t < INC * HC) {
        int k = t >> 8, n = t & 255;
        g_w1h[n * INC + k] = __float2bfloat16(W1[t]);
    } else if (t < INC * HC + 64 * INC) {
        int u = t - INC * HC;
        int n = u >> 8, k = u & 255;
        float v = (n < OC) ? W2[k * OC + n] : 0.f;
        g_w2h[n * INC + k] = __float2bfloat16(v);
    }
    if (t < Nn) g_counts[t] = 1;   // self loop baked in
}

// ---------------- hist (standalone, on side stream) -----------------------------
__global__ void hist_kernel(const int* __restrict__ ei) {
    int i = blockIdx.x * blockDim.x + threadIdx.x;
    if (i >= Ee / 4) return;
    int4 d = ((const int4*)(ei + Ee))[i];
    atomicAdd(&g_counts[d.x], 1);
    atomicAdd(&g_counts[d.y], 1);
    atomicAdd(&g_counts[d.z], 1);
    atomicAdd(&g_counts[d.w], 1);
}

// ---------------- fused single-pass scan (+ g_fill prebias) ---------------------
__global__ void scan_fused() {
    __shared__ int ws[8];
    int j = blockIdx.x;
    int tid = threadIdx.x;
    int lane = tid & 31, warp = tid >> 5;

    int off = 0;
    for (int i = tid; i < j * 256; i += 256) off += g_counts[i];
    #pragma unroll
    for (int o = 16; o; o >>= 1) off += __shfl_down_sync(0xffffffffu, off, o);
    if (lane == 0) ws[warp] = off;
    __syncthreads();
    if (warp == 0) {
        int w = (lane < 8) ? ws[lane] : 0;
        #pragma unroll
        for (int o = 4; o; o >>= 1) w += __shfl_down_sync(0xffffffffu, w, o);
        if (lane == 0) ws[0] = w;
    }
    __syncthreads();
    int total_off = ws[0];
    __syncthreads();

    int idx = j * 256 + tid;
    int cval = (idx < Nn) ? g_counts[idx] : 0;
    int v = cval;
    #pragma unroll
    for (int o = 1; o < 32; o <<= 1) {
        int u = __shfl_up_sync(0xffffffffu, v, o);
        if (lane >= o) v += u;
    }
    if (lane == 31) ws[warp] = v;
    __syncthreads();
    if (warp == 0 && lane < 8) {
        int w = ws[lane];
        #pragma unroll
        for (int o = 1; o < 8; o <<= 1) {
            int u = __shfl_up_sync(0xffu, w, o);
            if (lane >= o) w += u;
        }
        ws[lane] = w;
    }
    __syncthreads();
    if (warp > 0) v += ws[warp - 1];
    if (idx < Nn) {
        int incl = v + total_off;
        g_rowptr[idx + 1] = incl;
        g_fill[idx] = incl - cval;     // exclusive prefix: fill cursor starts here
    }
    if (j == 0 && tid == 0) g_rowptr[0] = 0;
}

// ---------------- fill: cursor-only atomics (no rowptr load) --------------------
__global__ void fill_kernel(const int* __restrict__ ei) {
    const int Q = Ee / 4;
    int i = blockIdx.x * blockDim.x + threadIdx.x;
    if (i < Q) {
        int4 s = ((const int4*)ei)[i];
        int4 d = ((const int4*)(ei + Ee))[i];
        g_srcl[atomicAdd(&g_fill[d.x], 1)] = s.x;
        g_srcl[atomicAdd(&g_fill[d.y], 1)] = s.y;
        g_srcl[atomicAdd(&g_fill[d.z], 1)] = s.z;
        g_srcl[atomicAdd(&g_fill[d.w], 1)] = s.w;
    } else {
        int n = i - Q;
        if (n < Nn)
            g_srcl[atomicAdd(&g_fill[n], 1)] = n;
    }
}

// ---------------- GEMM common ---------------------------------------------------
#define LDW 36
#define LDB 144
#define ATILE (128 * LDB)

__device__ __forceinline__ void mma_bf16(float* c, const uint32_t* a, const uint32_t* b) {
    asm volatile(
        "mma.sync.aligned.m16n8k16.row.col.f32.bf16.bf16.f32 "
        "{%0,%1,%2,%3}, {%4,%5,%6,%7}, {%8,%9}, {%0,%1,%2,%3};"
        : "+f"(c[0]), "+f"(c[1]), "+f"(c[2]), "+f"(c[3])
        : "r"(a[0]), "r"(a[1]), "r"(a[2]), "r"(a[3]), "r"(b[0]), "r"(b[1]));
}

// ---------------- GEMM1: h1b = bf16(x @ W1), pure bf16 -------------------------
#define G1_BUF (2 * ATILE)
#define G1_SMEM (2 * G1_BUF)

__global__ void __launch_bounds__(512, 1)
gemm1_mma(const float* __restrict__ X,
          const float* __restrict__ a_src, const float* __restrict__ a_dst) {
    extern __shared__ char smem[];
    __shared__ float sAs[128], sAd[128];
    __shared__ float red[4][2][2][32];

    const int tid = threadIdx.x;
    const int wid = tid >> 5;
    const int lane = tid & 31;
    const int wm = wid >> 2;
    const int wn = wid & 3;
    const int g = lane >> 2;
    const int t = lane & 3;
    const int hl = wn >> 1;

    const int bm = (blockIdx.x >> 1) * MT;
    const int bn = (blockIdx.x & 1) * 128;

    const uint32_t sb = smem_u32(smem);

    if (tid < 128) { sAs[tid] = a_src[bn + tid]; sAd[tid] = a_dst[bn + tid]; }
    ((float*)red)[tid] = 0.f;

    float acc[2][4][4] = {};
    float4 aregs[4];

    auto loadA = [&](int c) {
        #pragma unroll
        for (int i = 0; i < 4; i++) {
            int idx = i * 512 + tid;
            int row = idx >> 4;
            int col4 = (idx & 15) * 4;
            int grow = bm + row;
            aregs[i] = (grow < Nn)
                ? *(const float4*)(X + (size_t)grow * INC + c * 64 + col4)
                : make_float4(0.f, 0.f, 0.f, 0.f);
        }
    };
    auto storeA = [&](int buf) {
        char* sAh = smem + buf * G1_BUF;
        #pragma unroll
        for (int i = 0; i < 4; i++) {
            int idx = i * 512 + tid;
            int row = idx >> 4;
            int col4 = (idx & 15) * 4;
            int so = row * LDB + col4 * 2;
            *(uint2*)(sAh + so) = tobf4(aregs[i]);
        }
    };
    auto cpB = [&](int c, int buf) {
        uint32_t dBh = sb + buf * G1_BUF + ATILE;
        #pragma unroll
        for (int i = 0; i < 2; i++) {
            int idx = i * 512 + tid;
            int row = idx >> 3;
            int col8 = (idx & 7) * 8;
            size_t gb = (size_t)(bn + row) * INC + c * 64 + col8;
            uint32_t so = row * LDB + col8 * 2;
            cp16(dBh + so, g_w1h + gb);
        }
    };
    auto compute = [&](int buf) {
        const uint32_t* Ahw = (const uint32_t*)(smem + buf * G1_BUF);
        const uint32_t* Bhw = (const uint32_t*)(smem + buf * G1_BUF + ATILE);
        #pragma unroll
        for (int kk = 0; kk < 4; kk++) {
            const int kw = kk * 8;
            uint32_t bh[4][2];
            #pragma unroll
            for (int nt = 0; nt < 4; nt++) {
                int w0 = (wn * 32 + nt * 8 + g) * LDW + kw + t;
                bh[nt][0] = Bhw[w0]; bh[nt][1] = Bhw[w0 + 4];
            }
            #pragma unroll
            for (int mt = 0; mt < 2; mt++) {
                int w0 = (wm * 32 + mt * 16 + g) * LDW + kw + t;
                uint32_t ah[4];
                ah[0] = Ahw[w0]; ah[1] = Ahw[w0 + 8 * LDW];
                ah[2] = Ahw[w0 + 4]; ah[3] = Ahw[w0 + 8 * LDW + 4];
                #pragma unroll
                for (int nt = 0; nt < 4; nt++)
                    mma_bf16(acc[mt][nt], ah, bh[nt]);
            }
        }
    };

    loadA(0); cpB(0, 0); CP_COMMIT(); storeA(0);
    CP_WAIT0(); __syncthreads();
    #pragma unroll
    for (int c = 0; c < 4; c++) {
        int buf = c & 1;
        if (c < 3) { loadA(c + 1); cpB(c + 1, buf ^ 1); CP_COMMIT(); }
        compute(buf);
        if (c < 3) { storeA(buf ^ 1); CP_WAIT0(); __syncthreads(); }
    }

    #pragma unroll
    for (int mt = 0; mt < 2; mt++) {
        int row0 = bm + wm * 32 + mt * 16 + g;
        int row1 = row0 + 8;
        float s0 = 0.f, s1 = 0.f, d0 = 0.f, d1 = 0.f;
        #pragma unroll
        for (int nt = 0; nt < 4; nt++) {
            int lcol = wn * 32 + nt * 8 + 2 * t;
            int col = bn + lcol;
            float as0 = sAs[lcol], as1 = sAs[lcol + 1];
            float ad0 = sAd[lcol], ad1 = sAd[lcol + 1];
            s0 += acc[mt][nt][0] * as0 + acc[mt][nt][1] * as1;
            s1 += acc[mt][nt][2] * as0 + acc[mt][nt][3] * as1;
            d0 += acc[mt][nt][0] * ad0 + acc[mt][nt][1] * ad1;
            d1 += acc[mt][nt][2] * ad0 + acc[mt][nt][3] * ad1;
            if (row0 < Nn)
                *(uint32_t*)(g_h1b + (size_t)row0 * HC + col) =
                    pack2(__float2bfloat16(acc[mt][nt][0]), __float2bfloat16(acc[mt][nt][1]));
            if (row1 < Nn)
                *(uint32_t*)(g_h1b + (size_t)row1 * HC + col) =
                    pack2(__float2bfloat16(acc[mt][nt][2]), __float2bfloat16(acc[mt][nt][3]));
        }
        s0 += __shfl_down_sync(0xffffffffu, s0, 2); s0 += __shfl_down_sync(0xffffffffu, s0, 1);
        s1 += __shfl_down_sync(0xffffffffu, s1, 2); s1 += __shfl_down_sync(0xffffffffu, s1, 1);
        d0 += __shfl_down_sync(0xffffffffu, d0, 2); d0 += __shfl_down_sync(0xffffffffu, d0, 1);
        d1 += __shfl_down_sync(0xffffffffu, d1, 2); d1 += __shfl_down_sync(0xffffffffu, d1, 1);
        if (t == 0) {
            int r0 = mt * 16 + g, r1 = r0 + 8;
            atomicAdd(&red[wm][hl][0][r0], s0);
            atomicAdd(&red[wm][hl][0][r1], s1);
            atomicAdd(&red[wm][hl][1][r0], d0);
            atomicAdd(&red[wm][hl][1][r1], d1);
        }
    }
    __syncthreads();
    if (tid < 128) {
        int n = bm + tid;
        if (n < Nn) {
            int w = tid >> 5, r = tid & 31;
            #pragma unroll
            for (int h = 0; h < 2; h++) {
                int head = (bn >> 6) + h;
                g_als1[n * NH + head] = red[w][h][0][r];
                g_ald1[n * NH + head] = red[w][h][1][r];
            }
        }
    }
}

// ---------------- GEMM2: h2 = agg1 @ W2, pure bf16 ------------------------------
#define BTILE2 (64 * LDB)
#define G2_BUF (ATILE + BTILE2)
#define G2_SMEM (2 * G2_BUF)

__global__ void __launch_bounds__(512, 1)
gemm2_mma(const float* __restrict__ a_src, const float* __restrict__ a_dst) {
    extern __shared__ char smem[];
    __shared__ float sAs[64], sAd[64];
    __shared__ float red2[2][128];

    const int tid = threadIdx.x;
    const int wid = tid >> 5;
    const int lane = tid & 31;
    const int wm = wid >> 1;
    const int wn = wid & 1;
    const int g = lane >> 2;
    const int t = lane & 3;

    const int bm = blockIdx.x * MT;
    const uint32_t sb = smem_u32(smem);

    if (tid < 64) { sAs[tid] = (tid < OC) ? a_src[tid] : 0.f;
                    sAd[tid] = (tid < OC) ? a_dst[tid] : 0.f; }
    if (tid < 256) ((float*)red2)[tid] = 0.f;

    float acc[4][4] = {};

    auto stage = [&](int c, int buf) {
        uint32_t dAh = sb + buf * G2_BUF;
        uint32_t dBh = dAh + ATILE;
        #pragma unroll
        for (int i = 0; i < 2; i++) {
            int idx = i * 512 + tid;
            int row = idx >> 3;
            int col8 = (idx & 7) * 8;
            size_t ga = (size_t)(bm + row) * HC + c * 64 + col8;
            uint32_t so = row * LDB + col8 * 2;
            cp16(dAh + so, g_a1h + ga);
        }
        {
            int idx = tid;
            int row = idx >> 3;
            int col8 = (idx & 7) * 8;
            size_t gb = (size_t)row * INC + c * 64 + col8;
            uint32_t so = row * LDB + col8 * 2;
            cp16(dBh + so, g_w2h + gb);
        }
    };
    auto compute = [&](int buf) {
        const uint32_t* Ahw = (const uint32_t*)(smem + buf * G2_BUF);
        const uint32_t* Bhw = (const uint32_t*)(smem + buf * G2_BUF + ATILE);
        #pragma unroll
        for (int kk = 0; kk < 4; kk++) {
            const int kw = kk * 8;
            uint32_t bh[4][2];
            #pragma unroll
            for (int nt = 0; nt < 4; nt++) {
                int w0 = (wn * 32 + nt * 8 + g) * LDW + kw + t;
                bh[nt][0] = Bhw[w0]; bh[nt][1] = Bhw[w0 + 4];
            }
            {
                int w0 = (wm * 16 + g) * LDW + kw + t;
                uint32_t ah[4];
                ah[0] = Ahw[w0]; ah[1] = Ahw[w0 + 8 * LDW];
                ah[2] = Ahw[w0 + 4]; ah[3] = Ahw[w0 + 8 * LDW + 4];
                #pragma unroll
                for (int nt = 0; nt < 4; nt++)
                    mma_bf16(acc[nt], ah, bh[nt]);
            }
        }
    };

    stage(0, 0); CP_COMMIT();
    CP_WAIT0(); __syncthreads();
    #pragma unroll
    for (int c = 0; c < 4; c++) {
        int buf = c & 1;
        if (c < 3) { stage(c + 1, buf ^ 1); CP_COMMIT(); }
        compute(buf);
        if (c < 3) { CP_WAIT0(); __syncthreads(); }
    }

    {
        int row0 = bm + wm * 16 + g;
        int row1 = row0 + 8;
        float s0 = 0.f, s1 = 0.f, d0 = 0.f, d1 = 0.f;
        #pragma unroll
        for (int nt = 0; nt < 4; nt++) {
            int lcol = wn * 32 + nt * 8 + 2 * t;
            float as0 = sAs[lcol], as1 = sAs[lcol + 1];
            float ad0 = sAd[lcol], ad1 = sAd[lcol + 1];
            s0 += acc[nt][0] * as0 + acc[nt][1] * as1;
            s1 += acc[nt][2] * as0 + acc[nt][3] * as1;
            d0 += acc[nt][0] * ad0 + acc[nt][1] * ad1;
            d1 += acc[nt][2] * ad0 + acc[nt][3] * ad1;
            if (lcol < OC) {
                if (row0 < Nn)
                    *(float2*)(g_h2 + (size_t)row0 * OC + lcol) = make_float2(acc[nt][0], acc[nt][1]);
                if (row1 < Nn)
                    *(float2*)(g_h2 + (size_t)row1 * OC + lcol) = make_float2(acc[nt][2], acc[nt][3]);
            }
        }
        s0 += __shfl_down_sync(0xffffffffu, s0, 2); s0 += __shfl_down_sync(0xffffffffu, s0, 1);
        s1 += __shfl_down_sync(0xffffffffu, s1, 2); s1 += __shfl_down_sync(0xffffffffu, s1, 1);
        d0 += __shfl_down_sync(0xffffffffu, d0, 2); d0 += __shfl_down_sync(0xffffffffu, d0, 1);
        d1 += __shfl_down_sync(0xffffffffu, d1, 2); d1 += __shfl_down_sync(0xffffffffu, d1, 1);
        if (t == 0) {
            int r0 = wm * 16 + g, r1 = r0 + 8;
            atomicAdd(&red2[0][r0], s0);
            atomicAdd(&red2[0][r1], s1);
            atomicAdd(&red2[1][r0], d0);
            atomicAdd(&red2[1][r1], d1);
        }
    }
    __syncthreads();
    if (tid < 128) {
        int n = bm + tid;
        if (n < Nn) {
            g_als2[n] = red2[0][tid];
            g_ald2[n] = red2[1][tid];
        }
    }
}

// ---------------- layer 1: 64-thread blocks, MLP-8 gathers ---------------------
__global__ __launch_bounds__(64) void agg1_kernel(const float* __restrict__ b1) {
    int d = blockIdx.x;
    int start = g_rowptr[d], end = g_rowptr[d + 1];
    int tid = threadIdx.x;
    __shared__ float sden[NH];
    __shared__ int ssrc[64];
    __shared__ float salpha[64 * NH];

    if (tid < NH) sden[tid] = 1e-16f;
    float4 aldv = *(const float4*)&g_ald1[d * NH];

    const int ch4 = tid;
    const int head = tid >> 4;
    float4 acc = make_float4(0.f, 0.f, 0.f, 0.f);
    float p0 = 0.f, p1 = 0.f, p2 = 0.f, p3 = 0.f;

    for (int base = start; base < end; base += 64) {
        int cnt = min(64, end - base);
        __syncthreads();
        if (tid < cnt) {
            int s = g_srcl[base + tid];
            ssrc[tid] = s;
            float4 als = *(const float4*)&g_als1[s * NH];
            float e0 = __expf(lrelu(als.x + aldv.x));
            float e1 = __expf(lrelu(als.y + aldv.y));
            float e2 = __expf(lrelu(als.z + aldv.z));
            float e3 = __expf(lrelu(als.w + aldv.w));
            salpha[tid * 4 + 0] = e0; salpha[tid * 4 + 1] = e1;
            salpha[tid * 4 + 2] = e2; salpha[tid * 4 + 3] = e3;
            p0 += e0; p1 += e1; p2 += e2; p3 += e3;
        }
        __syncthreads();
        int j = 0;
        for (; j + 7 < cnt; j += 8) {
            float av[8];
            uint2 hv[8];
            #pragma unroll
            for (int q = 0; q < 8; q++) {
                av[q] = salpha[(j + q) * 4 + head];
                hv[q] = *(const uint2*)(g_h1b + (size_t)ssrc[j + q] * HC + ch4 * 4);
            }
            #pragma unroll
            for (int q = 0; q < 8; q++) {
                float2 f0 = __bfloat1622float2(*(const __nv_bfloat162*)&hv[q].x);
                float2 f1 = __bfloat1622float2(*(const __nv_bfloat162*)&hv[q].y);
                acc.x = fmaf(av[q], f0.x, acc.x);
                acc.y = fmaf(av[q], f0.y, acc.y);
                acc.z = fmaf(av[q], f1.x, acc.z);
                acc.w = fmaf(av[q], f1.y, acc.w);
            }
        }
        for (; j + 3 < cnt; j += 4) {
            float av[4];
            uint2 hv[4];
            #pragma unroll
            for (int q = 0; q < 4; q++) {
                av[q] = salpha[(j + q) * 4 + head];
                hv[q] = *(const uint2*)(g_h1b + (size_t)ssrc[j + q] * HC + ch4 * 4);
            }
            #pragma unroll
            for (int q = 0; q < 4; q++) {
                float2 f0 = __bfloat1622float2(*(const __nv_bfloat162*)&hv[q].x);
                float2 f1 = __bfloat1622float2(*(const __nv_bfloat162*)&hv[q].y);
                acc.x = fmaf(av[q], f0.x, acc.x);
                acc.y = fmaf(av[q], f0.y, acc.y);
                acc.z = fmaf(av[q], f1.x, acc.z);
                acc.w = fmaf(av[q], f1.y, acc.w);
            }
        }
        for (; j < cnt; j++) {
            float a = salpha[j * 4 + head];
            uint2 hv = *(const uint2*)(g_h1b + (size_t)ssrc[j] * HC + ch4 * 4);
            float2 f0 = __bfloat1622float2(*(const __nv_bfloat162*)&hv.x);
            float2 f1 = __bfloat1622float2(*(const __nv_bfloat162*)&hv.y);
            acc.x = fmaf(a, f0.x, acc.x);
            acc.y = fmaf(a, f0.y, acc.y);
            acc.z = fmaf(a, f1.x, acc.z);
            acc.w = fmaf(a, f1.y, acc.w);
        }
    }
    #pragma unroll
    for (int off = 16; off; off >>= 1) {
        p0 += __shfl_down_sync(0xffffffffu, p0, off);
        p1 += __shfl_down_sync(0xffffffffu, p1, off);
        p2 += __shfl_down_sync(0xffffffffu, p2, off);
        p3 += __shfl_down_sync(0xffffffffu, p3, off);
    }
    if ((tid & 31) == 0) {
        atomicAdd(&sden[0], p0);
        atomicAdd(&sden[1], p1);
        atomicAdd(&sden[2], p2);
        atomicAdd(&sden[3], p3);
    }
    __syncthreads();
    {
        float rd = 1.f / sden[head];
        int ch = tid * 4;
        float4 bb = *(const float4*)(b1 + ch);
        float4 r;
        r.x = fmaxf(acc.x * rd + bb.x, 0.f);
        r.y = fmaxf(acc.y * rd + bb.y, 0.f);
        r.z = fmaxf(acc.z * rd + bb.z, 0.f);
        r.w = fmaxf(acc.w * rd + bb.w, 0.f);
        *(uint2*)(g_a1h + (size_t)d * HC + ch) = tobf4(r);
    }
}

// ---------------- layer 2: single-pass agg + log_softmax, MLP-4 ---------------
__global__ void agg2_final(const float* __restrict__ b2, float* __restrict__ out) {
    int n = blockIdx.x * 8 + (threadIdx.x >> 5);
    if (n >= Nn) return;
    int lane = threadIdx.x & 31;
    int start = g_rowptr[n], end = g_rowptr[n + 1];
    float ald = g_ald2[n];

    float den = 0.f, acc0 = 0.f, acc1 = 0.f;
    for (int base = start; base < end; base += 32) {
        int i = base + lane;
        int s = 0; float e = 0.f;
        if (i < end) {
            s = g_srcl[i];
            e = __expf(lrelu(g_als2[s] + ald));
        }
        den += e;
        int cnt = min(32, end - base);
        int j = 0;
        for (; j + 3 < cnt; j += 4) {
            int   sj0 = __shfl_sync(0xffffffffu, s, j);
            int   sj1 = __shfl_sync(0xffffffffu, s, j + 1);
            int   sj2 = __shfl_sync(0xffffffffu, s, j + 2);
            int   sj3 = __shfl_sync(0xffffffffu, s, j + 3);
            float ej0 = __shfl_sync(0xffffffffu, e, j);
            float ej1 = __shfl_sync(0xffffffffu, e, j + 1);
            float ej2 = __shfl_sync(0xffffffffu, e, j + 2);
            float ej3 = __shfl_sync(0xffffffffu, e, j + 3);
            float v0 = g_h2[sj0 * OC + lane];
            float v1 = g_h2[sj1 * OC + lane];
            float v2 = g_h2[sj2 * OC + lane];
            float v3 = g_h2[sj3 * OC + lane];
            float w0 = 0.f, w1 = 0.f, w2 = 0.f, w3 = 0.f;
            if (lane < 8) {
                w0 = g_h2[sj0 * OC + 32 + lane];
                w1 = g_h2[sj1 * OC + 32 + lane];
                w2 = g_h2[sj2 * OC + 32 + lane];
                w3 = g_h2[sj3 * OC + 32 + lane];
            }
            acc0 = fmaf(ej0, v0, acc0); acc0 = fmaf(ej1, v1, acc0);
            acc0 = fmaf(ej2, v2, acc0); acc0 = fmaf(ej3, v3, acc0);
            acc1 = fmaf(ej0, w0, acc1); acc1 = fmaf(ej1, w1, acc1);
            acc1 = fmaf(ej2, w2, acc1); acc1 = fmaf(ej3, w3, acc1);
        }
        for (; j < cnt; j++) {
            int   sj = __shfl_sync(0xffffffffu, s, j);
            float ej = __shfl_sync(0xffffffffu, e, j);
            acc0 = fmaf(ej, g_h2[sj * OC + lane], acc0);
            if (lane < 8) acc1 = fmaf(ej, g_h2[sj * OC + 32 + lane], acc1);
        }
    }
    #pragma unroll
    for (int off = 16; off; off >>= 1)
        den += __shfl_xor_sync(0xffffffffu, den, off);
    float rden = 1.f / (den + 1e-16f);

    float v0 = acc0 * rden + b2[lane];
    float v1 = (lane < 8) ? (acc1 * rden + b2[32 + lane]) : -3.402823466e38f;
    float mx = fmaxf(v0, v1);
    #pragma unroll
    for (int off = 16; off; off >>= 1)
        mx = fmaxf(mx, __shfl_xor_sync(0xffffffffu, mx, off));
    float se = expf(v0 - mx) + ((lane < 8) ? expf(v1 - mx) : 0.f);
    #pragma unroll
    for (int off = 16; off; off >>= 1)
        se += __shfl_xor_sync(0xffffffffu, se, off);
    float lse = mx + logf(se);
    out[n * OC + lane] = v0 - lse;
    if (lane < 8) out[n * OC + 32 + lane] = v1 - lse;
}

// ---------------- launch (fork-join: CSR chain overlaps gemm1) -----------------
extern "C" void kernel_launch(void* const* d_in, const int* in_sizes, int n_in,
                              void* d_out, int out_size) {
    const float* x      = (const float*)d_in[0];
    const int*   ei     = (const int*)d_in[1];
    const float* W1     = (const float*)d_in[2];
    const float* a_src1 = (const float*)d_in[3];
    const float* a_dst1 = (const float*)d_in[4];
    const float* b1     = (const float*)d_in[5];
    const float* W2     = (const float*)d_in[6];
    const float* a_src2 = (const float*)d_in[7];
    const float* a_dst2 = (const float*)d_in[8];
    const float* b2     = (const float*)d_in[9];
    float* out = (float*)d_out;

    static cudaStream_t s2 = nullptr;
    static cudaEvent_t evFork = nullptr, evJoin = nullptr;
    if (s2 == nullptr) {
        cudaStreamCreateWithFlags(&s2, cudaStreamNonBlocking);
        cudaEventCreateWithFlags(&evFork, cudaEventDisableTiming);
        cudaEventCreateWithFlags(&evJoin, cudaEventDisableTiming);
    }

    cudaFuncSetAttribute(gemm1_mma, cudaFuncAttributeMaxDynamicSharedMemorySize, G1_SMEM);
    cudaFuncSetAttribute(gemm2_mma, cudaFuncAttributeMaxDynamicSharedMemorySize, G2_SMEM);

    // common prologue (weights + counts init)
    convert_w<<<(INC * HC + 64 * INC + 255) / 256, 256>>>(W1, W2);

    // fork: CSR chain on s2, GEMM1 on main stream
    cudaEventRecord(evFork, 0);
    cudaStreamWaitEvent(s2, evFork, 0);

    hist_kernel<<<(Ee / 4 + 255) / 256, 256, 0, s2>>>(ei);
    scan_fused<<<NB, 256, 0, s2>>>();
    fill_kernel<<<(Ee / 4 + Nn + 255) / 256, 256, 0, s2>>>(ei);
    cudaEventRecord(evJoin, s2);

    gemm1_mma<<<MTILES * 2, 512, G1_SMEM>>>(x, a_src1, a_dst1);

    // join: agg1 needs both h1/als (main) and CSR (s2)
    cudaStreamWaitEvent(0, evJoin, 0);

    agg1_kernel<<<Nn, 64>>>(b1);
    gemm2_mma<<<MTILES, 512, G2_SMEM>>>(a_src2, a_dst2);
    agg2_final<<<(Nn + 7) / 8, 256>>>(b2, out);
}